// round 4
// baseline (speedup 1.0000x reference)
#include <cuda_runtime.h>
#include <math.h>

#define H 256
#define W 256
#define HW 65536
#define BATCH 4
#define NSTAT (BATCH*HW)
#define NBLKMAX 1024

#define SZ16 (BATCH*16*HW)
#define SZ18 (BATCH*18*HW)
#define SZ64 (BATCH*64*HW)

// ---------------- scratch (static device globals; no allocations) ----------
__device__ __align__(16) float g_hfpre[SZ16];
__device__ __align__(16) float g_prehf[SZ16];
__device__ __align__(16) float g_pre[SZ16];
__device__ __align__(16) float g_t[SZ16];
__device__ __align__(16) float g_off[SZ18];
__device__ __align__(16) float g_d16[SZ16];
__device__ __align__(16) float g_y[SZ16];
__device__ __align__(16) float g_z[SZ64];
__device__ __align__(16) float g_s[SZ64];
__device__ __align__(16) float g_sp[BATCH*2*HW];
__device__ __align__(16) float g_sg[BATCH*HW];
__device__ __align__(16) float g_xb[4*SZ16];
__device__ float g_bsum[NBLKMAX*64];
__device__ float g_bsq[NBLKMAX*64];
__device__ float g_bmax[NBLKMAX*64];
// stats slots: 0=hf, 1..4=branch outs, 5=pre, 6=y, 7=z, 8=xx, 9=final
__device__ float g_stats[10*128];
__device__ float g_ca[BATCH*64];

// ---------------- BN finalize ------------------------------------------------
__global__ void bn_final_k(int nblk, int slot)
{
    int c = blockIdx.x, lane = threadIdx.x;
    float s = 0.f, q = 0.f;
    for (int j = lane; j < nblk; j += 32) {
        s += g_bsum[j * 64 + c];
        q += g_bsq[j * 64 + c];
    }
    #pragma unroll
    for (int d = 16; d > 0; d >>= 1) {
        s += __shfl_down_sync(0xffffffffu, s, d);
        q += __shfl_down_sync(0xffffffffu, q, d);
    }
    if (lane == 0) {
        float m = s / (float)NSTAT;
        float v = q / (float)NSTAT - m * m;
        g_stats[slot * 128 + c] = m;
        g_stats[slot * 128 + 64 + c] = rsqrtf(v + 1e-5f);
    }
}

// =============== dil=1 fast conv: 4 pixels/thread along x ====================
// 128 threads/block; block covers 2 rows x 256 cols = 512 pixels.
template<int CIN, int COUT, bool BIAS, bool NORM, bool RELU, bool ADDEND, int STATS>
__global__ void __launch_bounds__(128) conv3x3_d1(
    const float* __restrict__ in, int inCt, int inCo,
    const float* __restrict__ stats,
    const float* __restrict__ w, int wCt, int wCo,
    const float* __restrict__ bias,
    const float* __restrict__ addend,
    float* __restrict__ out, int outCt)
{
    constexpr int CCH = (CIN < 16) ? CIN : 16;
    constexpr int COUTP = (COUT + 3) & ~3;
    __shared__ __align__(16) float ws[CCH * 9 * COUTP];
    __shared__ float reds[STATS ? COUT * 4 : 1];
    __shared__ float redq[STATS ? COUT * 4 : 1];
    __shared__ float redm[(STATS == 2) ? COUT * 4 : 1];

    const int tid = threadIdx.x;
    const int b = blockIdx.y;
    const int oc0 = blockIdx.z * COUT;
    const int row = blockIdx.x * 2 + (tid >> 6);
    const int xs = (tid & 63) * 4;

    float acc[4][COUTP];
    #pragma unroll
    for (int p = 0; p < 4; p++)
        #pragma unroll
        for (int o = 0; o < COUTP; o++)
            acc[p][o] = (BIAS && o < COUT) ? __ldg(&bias[oc0 + o]) : 0.f;

    for (int c0 = 0; c0 < CIN; c0 += CCH) {
        __syncthreads();
        for (int i = tid; i < CCH * 9 * COUTP; i += 128) {
            int o = i % COUTP;
            int rem = i / COUTP;
            int k = rem % 9;
            int cl = rem / 9;
            ws[i] = (o < COUT) ? w[((size_t)(oc0 + o) * wCt + wCo + c0 + cl) * 9 + k] : 0.f;
        }
        __syncthreads();
        #pragma unroll 1
        for (int cl = 0; cl < CCH; cl++) {
            const float* __restrict__ inp = in + (size_t)(b * inCt + inCo + c0 + cl) * HW;
            float iv = 1.f, nm = 0.f;
            if (NORM) {
                float m = stats[c0 + cl];
                iv = stats[64 + c0 + cl];
                nm = -m * iv;
            }
            #pragma unroll
            for (int ky = 0; ky < 3; ky++) {
                int yy = row + ky - 1;
                float rr[6];
                if ((unsigned)yy < (unsigned)H) {
                    const float* rp = inp + yy * W + xs;
                    float4 mid = *(const float4*)rp;
                    float e0 = (xs > 0)   ? rp[-1] : 0.f;
                    float e5 = (xs < 252) ? rp[4]  : 0.f;
                    if (NORM) {
                        mid.x = fmaf(mid.x, iv, nm); mid.y = fmaf(mid.y, iv, nm);
                        mid.z = fmaf(mid.z, iv, nm); mid.w = fmaf(mid.w, iv, nm);
                        if (xs > 0)   e0 = fmaf(e0, iv, nm);
                        if (xs < 252) e5 = fmaf(e5, iv, nm);
                    }
                    if (RELU) {
                        mid.x = fmaxf(mid.x, 0.f); mid.y = fmaxf(mid.y, 0.f);
                        mid.z = fmaxf(mid.z, 0.f); mid.w = fmaxf(mid.w, 0.f);
                        e0 = fmaxf(e0, 0.f); e5 = fmaxf(e5, 0.f);
                    }
                    rr[0] = e0; rr[1] = mid.x; rr[2] = mid.y;
                    rr[3] = mid.z; rr[4] = mid.w; rr[5] = e5;
                } else {
                    #pragma unroll
                    for (int j = 0; j < 6; j++) rr[j] = 0.f;
                }
                const float* wbase = &ws[(cl * 9 + ky * 3) * COUTP];
                #pragma unroll
                for (int kx = 0; kx < 3; kx++) {
                    const float4* wr = (const float4*)(wbase + kx * COUTP);
                    #pragma unroll
                    for (int o4 = 0; o4 < COUTP / 4; o4++) {
                        float4 wv = wr[o4];
                        #pragma unroll
                        for (int p = 0; p < 4; p++) {
                            float v = rr[p + kx];
                            acc[p][4*o4+0] = fmaf(v, wv.x, acc[p][4*o4+0]);
                            acc[p][4*o4+1] = fmaf(v, wv.y, acc[p][4*o4+1]);
                            acc[p][4*o4+2] = fmaf(v, wv.z, acc[p][4*o4+2]);
                            acc[p][4*o4+3] = fmaf(v, wv.w, acc[p][4*o4+3]);
                        }
                    }
                }
            }
        }
    }
    // epilogue: addend + float4 store
    const int pixbase = row * W + xs;
    #pragma unroll
    for (int o = 0; o < COUT; o++) {
        float4 v = make_float4(acc[0][o], acc[1][o], acc[2][o], acc[3][o]);
        if (ADDEND) {
            float4 a = *(const float4*)(addend + (size_t)(b * COUT + o) * HW + pixbase);
            v.x += a.x; v.y += a.y; v.z += a.z; v.w += a.w;
        }
        *(float4*)(out + (size_t)(b * outCt + oc0 + o) * HW + pixbase) = v;
        acc[0][o] = v.x; acc[1][o] = v.y; acc[2][o] = v.z; acc[3][o] = v.w;
    }
    if constexpr (STATS > 0) {
        int lane = tid & 31, wid = tid >> 5;
        #pragma unroll 1
        for (int o = 0; o < COUT; o++) {
            float s = acc[0][o] + acc[1][o] + acc[2][o] + acc[3][o];
            float q = acc[0][o]*acc[0][o] + acc[1][o]*acc[1][o]
                    + acc[2][o]*acc[2][o] + acc[3][o]*acc[3][o];
            float mx = fmaxf(fmaxf(acc[0][o], acc[1][o]), fmaxf(acc[2][o], acc[3][o]));
            #pragma unroll
            for (int d = 16; d > 0; d >>= 1) {
                s += __shfl_down_sync(0xffffffffu, s, d);
                q += __shfl_down_sync(0xffffffffu, q, d);
                if (STATS == 2) mx = fmaxf(mx, __shfl_down_sync(0xffffffffu, mx, d));
            }
            if (lane == 0) {
                reds[o * 4 + wid] = s;
                redq[o * 4 + wid] = q;
                if (STATS == 2) redm[o * 4 + wid] = mx;
            }
        }
        __syncthreads();
        if (tid < COUT) {
            float s = 0.f, q = 0.f, mx = -INFINITY;
            #pragma unroll
            for (int j = 0; j < 4; j++) {
                s += reds[tid * 4 + j];
                q += redq[tid * 4 + j];
                if (STATS == 2) mx = fmaxf(mx, redm[tid * 4 + j]);
            }
            int rowi = b * gridDim.x + blockIdx.x;
            g_bsum[rowi * 64 + oc0 + tid] = s;
            g_bsq[rowi * 64 + oc0 + tid] = q;
            if (STATS == 2) g_bmax[rowi * 64 + oc0 + tid] = mx;
        }
    }
}

// ---------------- generic 3x3 conv (PIX=1) — used for dilated convs only -----
template<int CIN, int COUT, bool BIAS, bool NORM, bool RELU, bool ADDEND, int STATS>
__global__ void __launch_bounds__(256) conv3x3_g(
    const float* __restrict__ in, int inCt, int inCo,
    const float* __restrict__ stats,
    const float* __restrict__ w, int wCt, int wCo,
    const float* __restrict__ bias,
    const float* __restrict__ addend,
    float* __restrict__ out, int outCt,
    int dil)
{
    constexpr int CCH = (CIN < 16) ? CIN : 16;
    constexpr int COUTP = (COUT + 3) & ~3;
    __shared__ __align__(16) float ws[CCH * 9 * COUTP];
    __shared__ float reds[STATS ? COUT * 8 : 1];
    __shared__ float redq[STATS ? COUT * 8 : 1];

    const int tid = threadIdx.x;
    const int b = blockIdx.y;
    const int oc0 = blockIdx.z * COUT;
    const int pix = blockIdx.x * 256 + tid;
    const int y = pix >> 8, x = pix & 255;

    bool vy[3], vx[3];
    int yo[3], xo[3];
    #pragma unroll
    for (int t = 0; t < 3; t++) {
        int yy = y + (t - 1) * dil;
        int xx = x + (t - 1) * dil;
        vy[t] = (unsigned)yy < (unsigned)H;
        vx[t] = (unsigned)xx < (unsigned)W;
        yo[t] = yy * W;
        xo[t] = xx;
    }

    float acc[COUTP];
    #pragma unroll
    for (int o = 0; o < COUTP; o++)
        acc[o] = (BIAS && o < COUT) ? __ldg(&bias[oc0 + o]) : 0.f;

    for (int c0 = 0; c0 < CIN; c0 += CCH) {
        __syncthreads();
        for (int i = tid; i < CCH * 9 * COUTP; i += 256) {
            int o = i % COUTP;
            int rem = i / COUTP;
            int k = rem % 9;
            int cl = rem / 9;
            ws[i] = (o < COUT) ? w[((size_t)(oc0 + o) * wCt + wCo + c0 + cl) * 9 + k] : 0.f;
        }
        __syncthreads();
        #pragma unroll 1
        for (int cl = 0; cl < CCH; cl++) {
            const float* __restrict__ inp = in + (size_t)(b * inCt + inCo + c0 + cl) * HW;
            float iv = 1.f, nm = 0.f;
            if (NORM) {
                float m = stats[c0 + cl];
                iv = stats[64 + c0 + cl];
                nm = -m * iv;
            }
            #pragma unroll
            for (int ky = 0; ky < 3; ky++) {
                #pragma unroll
                for (int kx = 0; kx < 3; kx++) {
                    float v = 0.f;
                    if (vy[ky] && vx[kx]) {
                        v = inp[yo[ky] + xo[kx]];
                        if (NORM) v = fmaf(v, iv, nm);
                        if (RELU) v = fmaxf(v, 0.f);
                    }
                    const float* wrow = &ws[(cl * 9 + ky * 3 + kx) * COUTP];
                    #pragma unroll
                    for (int o4 = 0; o4 < COUTP / 4; o4++) {
                        float4 wv = *(const float4*)(wrow + 4 * o4);
                        acc[4*o4+0] = fmaf(v, wv.x, acc[4*o4+0]);
                        acc[4*o4+1] = fmaf(v, wv.y, acc[4*o4+1]);
                        acc[4*o4+2] = fmaf(v, wv.z, acc[4*o4+2]);
                        acc[4*o4+3] = fmaf(v, wv.w, acc[4*o4+3]);
                    }
                }
            }
        }
    }
    #pragma unroll
    for (int o = 0; o < COUT; o++) {
        float val = acc[o];
        if (ADDEND) val += addend[(size_t)(b * COUT + o) * HW + pix];
        out[(size_t)(b * outCt + oc0 + o) * HW + pix] = val;
        acc[o] = val;
    }
    if constexpr (STATS > 0) {
        int lane = tid & 31, wid = tid >> 5;
        #pragma unroll 1
        for (int o = 0; o < COUT; o++) {
            float s = acc[o], q = acc[o] * acc[o];
            #pragma unroll
            for (int d = 16; d > 0; d >>= 1) {
                s += __shfl_down_sync(0xffffffffu, s, d);
                q += __shfl_down_sync(0xffffffffu, q, d);
            }
            if (lane == 0) {
                reds[o * 8 + wid] = s;
                redq[o * 8 + wid] = q;
            }
        }
        __syncthreads();
        if (tid < COUT) {
            float s = 0.f, q = 0.f;
            #pragma unroll
            for (int j = 0; j < 8; j++) {
                s += reds[tid * 8 + j];
                q += redq[tid * 8 + j];
            }
            int rowi = b * gridDim.x + blockIdx.x;
            g_bsum[rowi * 64 + oc0 + tid] = s;
            g_bsq[rowi * 64 + oc0 + tid] = q;
        }
    }
}

// ---------------- 1x1 convs, 4 pixels/thread ---------------------------------
__global__ void __launch_bounds__(128) conv1x1_64_16_p4(
    const float* __restrict__ in, const float* __restrict__ w,
    const float* __restrict__ bias, float* __restrict__ out)
{
    __shared__ __align__(16) float ws[64*16];
    __shared__ float reds[16*4], redq[16*4];
    int tid = threadIdx.x;
    for (int i = tid; i < 64*16; i += 128) {
        int o = i & 15, c = i >> 4;
        ws[i] = w[o * 64 + c];
    }
    __syncthreads();
    int p4 = blockIdx.x * 128 + tid;   // float4 pixel index
    int b = blockIdx.y;
    const float4* inb = (const float4*)(in + (size_t)b * 64 * HW) + p4;
    float acc[4][16];
    #pragma unroll
    for (int o = 0; o < 16; o++) {
        float bv = __ldg(&bias[o]);
        acc[0][o] = bv; acc[1][o] = bv; acc[2][o] = bv; acc[3][o] = bv;
    }
    #pragma unroll 1
    for (int c = 0; c < 64; c++) {
        float4 v = inb[(size_t)c * (HW / 4)];
        const float4* wr = (const float4*)&ws[c * 16];
        #pragma unroll
        for (int o4 = 0; o4 < 4; o4++) {
            float4 wv = wr[o4];
            acc[0][4*o4+0] = fmaf(v.x, wv.x, acc[0][4*o4+0]);
            acc[0][4*o4+1] = fmaf(v.x, wv.y, acc[0][4*o4+1]);
            acc[0][4*o4+2] = fmaf(v.x, wv.z, acc[0][4*o4+2]);
            acc[0][4*o4+3] = fmaf(v.x, wv.w, acc[0][4*o4+3]);
            acc[1][4*o4+0] = fmaf(v.y, wv.x, acc[1][4*o4+0]);
            acc[1][4*o4+1] = fmaf(v.y, wv.y, acc[1][4*o4+1]);
            acc[1][4*o4+2] = fmaf(v.y, wv.z, acc[1][4*o4+2]);
            acc[1][4*o4+3] = fmaf(v.y, wv.w, acc[1][4*o4+3]);
            acc[2][4*o4+0] = fmaf(v.z, wv.x, acc[2][4*o4+0]);
            acc[2][4*o4+1] = fmaf(v.z, wv.y, acc[2][4*o4+1]);
            acc[2][4*o4+2] = fmaf(v.z, wv.z, acc[2][4*o4+2]);
            acc[2][4*o4+3] = fmaf(v.z, wv.w, acc[2][4*o4+3]);
            acc[3][4*o4+0] = fmaf(v.w, wv.x, acc[3][4*o4+0]);
            acc[3][4*o4+1] = fmaf(v.w, wv.y, acc[3][4*o4+1]);
            acc[3][4*o4+2] = fmaf(v.w, wv.z, acc[3][4*o4+2]);
            acc[3][4*o4+3] = fmaf(v.w, wv.w, acc[3][4*o4+3]);
        }
    }
    #pragma unroll
    for (int o = 0; o < 16; o++) {
        float4 v = make_float4(acc[0][o], acc[1][o], acc[2][o], acc[3][o]);
        ((float4*)out)[(size_t)(b * 16 + o) * (HW / 4) + p4] = v;
    }
    int lane = tid & 31, wid = tid >> 5;
    #pragma unroll 1
    for (int o = 0; o < 16; o++) {
        float s = acc[0][o] + acc[1][o] + acc[2][o] + acc[3][o];
        float q = acc[0][o]*acc[0][o] + acc[1][o]*acc[1][o]
                + acc[2][o]*acc[2][o] + acc[3][o]*acc[3][o];
        #pragma unroll
        for (int d = 16; d > 0; d >>= 1) {
            s += __shfl_down_sync(0xffffffffu, s, d);
            q += __shfl_down_sync(0xffffffffu, q, d);
        }
        if (lane == 0) { reds[o*4+wid] = s; redq[o*4+wid] = q; }
    }
    __syncthreads();
    if (tid < 16) {
        float s = 0.f, q = 0.f;
        #pragma unroll
        for (int j = 0; j < 4; j++) { s += reds[tid*4+j]; q += redq[tid*4+j]; }
        int rowi = b * gridDim.x + blockIdx.x;
        g_bsum[rowi * 64 + tid] = s;
        g_bsq[rowi * 64 + tid] = q;
    }
}

// 64->64 1x1 over normalized cat4; split 4 x 16 outputs; 4 px/thread
__global__ void __launch_bounds__(128) conv1x1_cat4_p4(
    const float* __restrict__ xb, const float* __restrict__ w,
    const float* __restrict__ bias, float* __restrict__ out)
{
    __shared__ __align__(16) float ws[64*16];
    __shared__ float siv[64], snm[64];
    __shared__ float reds[16*4], redq[16*4];
    int tid = threadIdx.x;
    int oc0 = blockIdx.z * 16;
    if (tid < 64) {
        int s = tid >> 4, c = tid & 15;
        float m = g_stats[(1 + s) * 128 + c];
        float iv = g_stats[(1 + s) * 128 + 64 + c];
        siv[tid] = iv; snm[tid] = -m * iv;
    }
    for (int i = tid; i < 64*16; i += 128) {
        int o = i & 15, c = i >> 4;
        ws[i] = w[(oc0 + o) * 64 + c];
    }
    __syncthreads();
    int p4 = blockIdx.x * 128 + tid;
    int b = blockIdx.y;
    float acc[4][16];
    #pragma unroll
    for (int o = 0; o < 16; o++) {
        float bv = __ldg(&bias[oc0 + o]);
        acc[0][o] = bv; acc[1][o] = bv; acc[2][o] = bv; acc[3][o] = bv;
    }
    #pragma unroll 1
    for (int c = 0; c < 64; c++) {
        const float* src = xb + (size_t)(c >> 4) * SZ16 + (size_t)(b * 16 + (c & 15)) * HW;
        float4 v = ((const float4*)src)[p4];
        float ivc = siv[c], nmc = snm[c];
        v.x = fmaf(v.x, ivc, nmc); v.y = fmaf(v.y, ivc, nmc);
        v.z = fmaf(v.z, ivc, nmc); v.w = fmaf(v.w, ivc, nmc);
        const float4* wr = (const float4*)&ws[c * 16];
        #pragma unroll
        for (int o4 = 0; o4 < 4; o4++) {
            float4 wv = wr[o4];
            acc[0][4*o4+0] = fmaf(v.x, wv.x, acc[0][4*o4+0]);
            acc[0][4*o4+1] = fmaf(v.x, wv.y, acc[0][4*o4+1]);
            acc[0][4*o4+2] = fmaf(v.x, wv.z, acc[0][4*o4+2]);
            acc[0][4*o4+3] = fmaf(v.x, wv.w, acc[0][4*o4+3]);
            acc[1][4*o4+0] = fmaf(v.y, wv.x, acc[1][4*o4+0]);
            acc[1][4*o4+1] = fmaf(v.y, wv.y, acc[1][4*o4+1]);
            acc[1][4*o4+2] = fmaf(v.y, wv.z, acc[1][4*o4+2]);
            acc[1][4*o4+3] = fmaf(v.y, wv.w, acc[1][4*o4+3]);
            acc[2][4*o4+0] = fmaf(v.z, wv.x, acc[2][4*o4+0]);
            acc[2][4*o4+1] = fmaf(v.z, wv.y, acc[2][4*o4+1]);
            acc[2][4*o4+2] = fmaf(v.z, wv.z, acc[2][4*o4+2]);
            acc[2][4*o4+3] = fmaf(v.z, wv.w, acc[2][4*o4+3]);
            acc[3][4*o4+0] = fmaf(v.w, wv.x, acc[3][4*o4+0]);
            acc[3][4*o4+1] = fmaf(v.w, wv.y, acc[3][4*o4+1]);
            acc[3][4*o4+2] = fmaf(v.w, wv.z, acc[3][4*o4+2]);
            acc[3][4*o4+3] = fmaf(v.w, wv.w, acc[3][4*o4+3]);
        }
    }
    #pragma unroll
    for (int o = 0; o < 16; o++) {
        float4 v = make_float4(acc[0][o], acc[1][o], acc[2][o], acc[3][o]);
        ((float4*)out)[(size_t)(b * 64 + oc0 + o) * (HW / 4) + p4] = v;
    }
    int lane = tid & 31, wid = tid >> 5;
    #pragma unroll 1
    for (int o = 0; o < 16; o++) {
        float s = acc[0][o] + acc[1][o] + acc[2][o] + acc[3][o];
        float q = acc[0][o]*acc[0][o] + acc[1][o]*acc[1][o]
                + acc[2][o]*acc[2][o] + acc[3][o]*acc[3][o];
        #pragma unroll
        for (int d = 16; d > 0; d >>= 1) {
            s += __shfl_down_sync(0xffffffffu, s, d);
            q += __shfl_down_sync(0xffffffffu, q, d);
        }
        if (lane == 0) { reds[o*4+wid] = s; redq[o*4+wid] = q; }
    }
    __syncthreads();
    if (tid < 16) {
        float s = 0.f, q = 0.f;
        #pragma unroll
        for (int j = 0; j < 4; j++) { s += reds[tid*4+j]; q += redq[tid*4+j]; }
        int rowi = b * gridDim.x + blockIdx.x;
        g_bsum[rowi * 64 + oc0 + tid] = s;
        g_bsq[rowi * 64 + oc0 + tid] = q;
    }
}

// ---------------- t materialization (float4) ----------------------------------
__global__ void norm_t_k(const float* __restrict__ pre,
                         const float* __restrict__ add1, const float* __restrict__ st1,
                         const float* __restrict__ lfsrc, int lfco)
{
    int i4 = blockIdx.x * 256 + threadIdx.x;  // SZ16/4 elements
    int idx = i4 * 4;
    int pix = idx & (HW - 1);
    int rest = idx >> 16;
    int c = rest & 15, b = rest >> 4;
    float m = g_stats[5 * 128 + c], iv = g_stats[5 * 128 + 64 + c];
    float nm = -m * iv;
    float4 v = ((const float4*)pre)[i4];
    v.x = fmaf(v.x, iv, nm); v.y = fmaf(v.y, iv, nm);
    v.z = fmaf(v.z, iv, nm); v.w = fmaf(v.w, iv, nm);
    if (add1) {
        float4 a = ((const float4*)add1)[i4];
        if (st1) {
            float m1 = st1[c], i1 = st1[64 + c], n1 = -m1 * i1;
            a.x = fmaf(a.x, i1, n1); a.y = fmaf(a.y, i1, n1);
            a.z = fmaf(a.z, i1, n1); a.w = fmaf(a.w, i1, n1);
        }
        v.x += a.x; v.y += a.y; v.z += a.z; v.w += a.w;
    }
    if (lfsrc) {
        float4 l = *(const float4*)(lfsrc + (size_t)(b * 64 + lfco + c) * HW + pix);
        v.x += l.x; v.y += l.y; v.z += l.z; v.w += l.w;
    }
    ((float4*)g_t)[i4] = v;
}

// ---------------- deformable conv (exact reference semantics) ------------------
__global__ void __launch_bounds__(256) deform_k(
    const float* __restrict__ t, const float* __restrict__ off,
    const float* __restrict__ wd, float* __restrict__ out)
{
    __shared__ __align__(16) float ws[16*16*9];
    for (int i = threadIdx.x; i < 2304; i += blockDim.x) {
        int o = i & 15;
        int rem = i >> 4;
        int n = rem % 9;
        int c = rem / 9;
        ws[i] = wd[(o * 16 + c) * 9 + n];
    }
    __syncthreads();
    int pix = blockIdx.x * blockDim.x + threadIdx.x;
    int b = blockIdx.y;
    int yi = pix >> 8, xj = pix & 255;

    float acc[16];
    #pragma unroll
    for (int o = 0; o < 16; o++) acc[o] = 0.f;

    const float* offb = off + (size_t)b * 18 * HW + pix;
    const float* tb = t + (size_t)b * 16 * HW;

    #pragma unroll 1
    for (int n = 0; n < 9; n++) {
        int dx = n / 3 - 1, dy = n % 3 - 1;
        float ox = offb[(size_t)(2 * n) * HW];
        float oy = offb[(size_t)(2 * n + 1) * HW];
        float plx = (float)(yi + 1 + dx) + ox;
        float ply = (float)(xj + 1 + dy) + oy;
        float flx = floorf(plx), fly = floorf(ply);
        int qltx = min(max((int)flx, 0), 257);
        int qlty = min(max((int)fly, 0), 257);
        int qrbx = min(max((int)flx + 1, 0), 257);
        int qrby = min(max((int)fly + 1, 0), 257);
        bool mx = (plx < 1.0f) || (plx > 256.0f);
        bool my = (ply < 1.0f) || (ply > 256.0f);
        float px = mx ? flx : plx; px = fminf(fmaxf(px, 0.f), 257.f);
        float py = my ? fly : ply; py = fminf(fmaxf(py, 0.f), 257.f);
        float wltx = 1.f + ((float)qltx - px);
        float wrbx = 1.f - ((float)qrbx - px);
        float wlty = 1.f + ((float)qlty - py);
        float wrby = 1.f - ((float)qrby - py);
        float glt = wltx * wlty, grb = wrbx * wrby;
        float glb = wltx * wrby, grt = wrbx * wlty;
        bool vltx = (qltx >= 1 && qltx <= 256);
        bool vlty = (qlty >= 1 && qlty <= 256);
        bool vrbx = (qrbx >= 1 && qrbx <= 256);
        bool vrby = (qrby >= 1 && qrby <= 256);
        int rlt = (qltx - 1) * W + (qlty - 1);
        int rrb = (qrbx - 1) * W + (qrby - 1);
        int rlb = (qltx - 1) * W + (qrby - 1);
        int rrt = (qrbx - 1) * W + (qlty - 1);
        #pragma unroll 1
        for (int c = 0; c < 16; c++) {
            const float* tc = tb + (size_t)c * HW;
            float vlt = (vltx && vlty) ? tc[rlt] : 0.f;
            float vrb = (vrbx && vrby) ? tc[rrb] : 0.f;
            float vlb = (vltx && vrby) ? tc[rlb] : 0.f;
            float vrt = (vrbx && vlty) ? tc[rrt] : 0.f;
            float val = glt * vlt + grb * vrb + glb * vlb + grt * vrt;
            const float* wr = &ws[(c * 9 + n) * 16];
            #pragma unroll
            for (int o4 = 0; o4 < 4; o4++) {
                float4 wv = *(const float4*)(wr + 4 * o4);
                acc[4*o4+0] = fmaf(val, wv.x, acc[4*o4+0]);
                acc[4*o4+1] = fmaf(val, wv.y, acc[4*o4+1]);
                acc[4*o4+2] = fmaf(val, wv.z, acc[4*o4+2]);
                acc[4*o4+3] = fmaf(val, wv.w, acc[4*o4+3]);
            }
        }
    }
    #pragma unroll
    for (int o = 0; o < 16; o++) out[(size_t)(b * 16 + o) * HW + pix] = acc[o];
}

// ---------------- CBAM ----------------------------------------------------------
__global__ void cbam_final_k(int gridX, const float* __restrict__ w1,
                             const float* __restrict__ w2)
{
    int t = threadIdx.x;          // 256 threads: t = b*64 + c
    int b = t >> 6, c = t & 63;
    float s = 0.f, q = 0.f, mx = -INFINITY;
    for (int j = 0; j < gridX; j++) {
        int idx = (b * gridX + j) * 64 + c;
        s += g_bsum[idx]; q += g_bsq[idx]; mx = fmaxf(mx, g_bmax[idx]);
    }
    __shared__ float sh_s[4][64], sh_q[4][64], sh_m[4][64];
    sh_s[b][c] = s; sh_q[b][c] = q; sh_m[b][c] = mx;
    __syncthreads();
    __shared__ float sm[64], si[64];
    if (t < 64) {
        float ts = 0.f, tq = 0.f;
        #pragma unroll
        for (int bb = 0; bb < 4; bb++) { ts += sh_s[bb][t]; tq += sh_q[bb][t]; }
        float m = ts / (float)NSTAT;
        float v = tq / (float)NSTAT - m * m;
        float iv = rsqrtf(v + 1e-5f);
        g_stats[7 * 128 + t] = m;
        g_stats[7 * 128 + 64 + t] = iv;
        sm[t] = m; si[t] = iv;
    }
    __syncthreads();
    __shared__ float av[4][64], xmv[4][64];
    av[b][c]  = (sh_s[b][c] / (float)HW - sm[c]) * si[c];
    xmv[b][c] = (sh_m[b][c] - sm[c]) * si[c];
    __syncthreads();
    __shared__ float hid[4][4][2];
    if (t < 32) {
        int bb = t >> 3, h = (t >> 1) & 3, which = t & 1;
        float acc = 0.f;
        for (int cc = 0; cc < 64; cc++)
            acc += w1[h * 64 + cc] * (which ? xmv[bb][cc] : av[bb][cc]);
        hid[bb][h][which] = fmaxf(acc, 0.f);
    }
    __syncthreads();
    {
        float va = 0.f, vm = 0.f;
        #pragma unroll
        for (int h = 0; h < 4; h++) {
            float wv = w2[c * 4 + h];
            va = fmaf(wv, hid[b][h][0], va);
            vm = fmaf(wv, hid[b][h][1], vm);
        }
        g_ca[b * 64 + c] = 1.f / (1.f + expf(-(va + vm)));
    }
}

// sp (mean,max over channels of (z norm * ca)), float4 over pixels
__global__ void apply1_k()
{
    __shared__ float sc[64], sb[64];
    int b = blockIdx.y;
    if (threadIdx.x < 64) {
        int c = threadIdx.x;
        float iv = g_stats[7 * 128 + 64 + c], m = g_stats[7 * 128 + c];
        float s = iv * g_ca[b * 64 + c];
        sc[c] = s; sb[c] = -m * s;
    }
    __syncthreads();
    int p4 = blockIdx.x * 256 + threadIdx.x;   // HW/4 per batch
    const float4* zp = (const float4*)(g_z + (size_t)b * 64 * HW) + p4;
    float4 smv = make_float4(0.f, 0.f, 0.f, 0.f);
    float4 mxv = make_float4(-INFINITY, -INFINITY, -INFINITY, -INFINITY);
    #pragma unroll 1
    for (int c = 0; c < 64; c++) {
        float4 v = zp[(size_t)c * (HW / 4)];
        float s = sc[c], bb = sb[c];
        v.x = fmaf(v.x, s, bb); v.y = fmaf(v.y, s, bb);
        v.z = fmaf(v.z, s, bb); v.w = fmaf(v.w, s, bb);
        smv.x += v.x; smv.y += v.y; smv.z += v.z; smv.w += v.w;
        mxv.x = fmaxf(mxv.x, v.x); mxv.y = fmaxf(mxv.y, v.y);
        mxv.z = fmaxf(mxv.z, v.z); mxv.w = fmaxf(mxv.w, v.w);
    }
    const float k = 1.f / 64.f;
    smv.x *= k; smv.y *= k; smv.z *= k; smv.w *= k;
    ((float4*)(g_sp + (size_t)(b * 2) * HW))[p4] = smv;
    ((float4*)(g_sp + (size_t)(b * 2 + 1) * HW))[p4] = mxv;
}

// sg = sigmoid(conv7x7(sp))
__global__ void apply2_k(const float* __restrict__ wsp)
{
    __shared__ float w[98];
    if (threadIdx.x < 98) w[threadIdx.x] = wsp[threadIdx.x];
    __syncthreads();
    int pix = blockIdx.x * 256 + threadIdx.x;
    int b = blockIdx.y;
    int y = pix >> 8, x = pix & 255;
    const float* s0 = g_sp + (size_t)(b * 2) * HW;
    const float* s1 = s0 + HW;
    float acc = 0.f;
    #pragma unroll 1
    for (int ky = 0; ky < 7; ky++) {
        int yy = y + ky - 3;
        if ((unsigned)yy >= (unsigned)H) continue;
        #pragma unroll
        for (int kx = 0; kx < 7; kx++) {
            int xx = x + kx - 3;
            if ((unsigned)xx >= (unsigned)W) continue;
            int ip = yy * W + xx;
            acc += w[ky * 7 + kx] * s0[ip] + w[49 + ky * 7 + kx] * s1[ip];
        }
    }
    g_sg[(size_t)b * HW + pix] = 1.f / (1.f + expf(-acc));
}

// conv2: 64->16 over (z norm * ca * sg) on load; 4 px/thread; stats epilogue
__global__ void __launch_bounds__(128) conv2_casg_d1(
    const float* __restrict__ w, float* __restrict__ out)
{
    __shared__ __align__(16) float ws[16 * 9 * 16];
    __shared__ float reds[16 * 4], redq[16 * 4];
    __shared__ float sc[64], sb[64];
    int tid = threadIdx.x, b = blockIdx.y;
    if (tid < 64) {
        float iv = g_stats[7 * 128 + 64 + tid], m = g_stats[7 * 128 + tid];
        float s = iv * g_ca[b * 64 + tid];
        sc[tid] = s; sb[tid] = -m * s;
    }
    const int row = blockIdx.x * 2 + (tid >> 6);
    const int xs = (tid & 63) * 4;

    // sg windows (channel-invariant): sgr[ky][j], j=0..5 <-> x = xs-1+j
    float sgr[3][6];
    const float* sgp = g_sg + (size_t)b * HW;
    #pragma unroll
    for (int ky = 0; ky < 3; ky++) {
        int yy = row + ky - 1;
        if ((unsigned)yy < (unsigned)H) {
            const float* rp = sgp + yy * W + xs;
            float4 mid = *(const float4*)rp;
            sgr[ky][0] = (xs > 0)   ? rp[-1] : 0.f;
            sgr[ky][1] = mid.x; sgr[ky][2] = mid.y;
            sgr[ky][3] = mid.z; sgr[ky][4] = mid.w;
            sgr[ky][5] = (xs < 252) ? rp[4] : 0.f;
        } else {
            #pragma unroll
            for (int j = 0; j < 6; j++) sgr[ky][j] = 0.f;
        }
    }

    float acc[4][16];
    #pragma unroll
    for (int p = 0; p < 4; p++)
        #pragma unroll
        for (int o = 0; o < 16; o++) acc[p][o] = 0.f;

    for (int c0 = 0; c0 < 64; c0 += 16) {
        __syncthreads();
        for (int i = tid; i < 16 * 9 * 16; i += 128) {
            int o = i & 15;
            int rem = i >> 4;
            int k = rem % 9;
            int cl = rem / 9;
            ws[i] = w[((size_t)o * 64 + c0 + cl) * 9 + k];
        }
        __syncthreads();
        #pragma unroll 1
        for (int cl = 0; cl < 16; cl++) {
            const float* __restrict__ inp = g_z + (size_t)(b * 64 + c0 + cl) * HW;
            float scc = sc[c0 + cl], bcc = sb[c0 + cl];
            #pragma unroll
            for (int ky = 0; ky < 3; ky++) {
                int yy = row + ky - 1;
                float pr[6];
                if ((unsigned)yy < (unsigned)H) {
                    const float* rp = inp + yy * W + xs;
                    float4 mid = *(const float4*)rp;
                    float e0 = (xs > 0)   ? rp[-1] : 0.f;
                    float e5 = (xs < 252) ? rp[4]  : 0.f;
                    pr[0] = fmaf(e0,    scc, bcc) * sgr[ky][0];
                    pr[1] = fmaf(mid.x, scc, bcc) * sgr[ky][1];
                    pr[2] = fmaf(mid.y, scc, bcc) * sgr[ky][2];
                    pr[3] = fmaf(mid.z, scc, bcc) * sgr[ky][3];
                    pr[4] = fmaf(mid.w, scc, bcc) * sgr[ky][4];
                    pr[5] = fmaf(e5,    scc, bcc) * sgr[ky][5];
                } else {
                    #pragma unroll
                    for (int j = 0; j < 6; j++) pr[j] = 0.f;
                }
                const float* wbase = &ws[(cl * 9 + ky * 3) * 16];
                #pragma unroll
                for (int kx = 0; kx < 3; kx++) {
                    const float4* wr = (const float4*)(wbase + kx * 16);
                    #pragma unroll
                    for (int o4 = 0; o4 < 4; o4++) {
                        float4 wv = wr[o4];
                        #pragma unroll
                        for (int p = 0; p < 4; p++) {
                            float v = pr[p + kx];
                            acc[p][4*o4+0] = fmaf(v, wv.x, acc[p][4*o4+0]);
                            acc[p][4*o4+1] = fmaf(v, wv.y, acc[p][4*o4+1]);
                            acc[p][4*o4+2] = fmaf(v, wv.z, acc[p][4*o4+2]);
                            acc[p][4*o4+3] = fmaf(v, wv.w, acc[p][4*o4+3]);
                        }
                    }
                }
            }
        }
    }
    const int pixbase = row * W + xs;
    #pragma unroll
    for (int o = 0; o < 16; o++) {
        float4 v = make_float4(acc[0][o], acc[1][o], acc[2][o], acc[3][o]);
        *(float4*)(out + (size_t)(b * 16 + o) * HW + pixbase) = v;
    }
    int lane = tid & 31, wid = tid >> 5;
    #pragma unroll 1
    for (int o = 0; o < 16; o++) {
        float s = acc[0][o] + acc[1][o] + acc[2][o] + acc[3][o];
        float q = acc[0][o]*acc[0][o] + acc[1][o]*acc[1][o]
                + acc[2][o]*acc[2][o] + acc[3][o]*acc[3][o];
        #pragma unroll
        for (int d = 16; d > 0; d >>= 1) {
            s += __shfl_down_sync(0xffffffffu, s, d);
            q += __shfl_down_sync(0xffffffffu, q, d);
        }
        if (lane == 0) { reds[o*4+wid] = s; redq[o*4+wid] = q; }
    }
    __syncthreads();
    if (tid < 16) {
        float s = 0.f, q = 0.f;
        #pragma unroll
        for (int j = 0; j < 4; j++) { s += reds[tid*4+j]; q += redq[tid*4+j]; }
        int rowi = b * gridDim.x + blockIdx.x;
        g_bsum[rowi * 64 + tid] = s;
        g_bsq[rowi * 64 + tid] = q;
    }
}

// ---------------- final elementwise ----------------------------------------------
__global__ void norm_s_k(const float* __restrict__ xx, const float* __restrict__ lf)
{
    int i4 = blockIdx.x * 256 + threadIdx.x;   // SZ64/4
    int idx = i4 * 4;
    int c = (idx >> 16) & 63;
    float m = g_stats[8 * 128 + c], iv = g_stats[8 * 128 + 64 + c];
    float nm = -m * iv;
    float4 v = ((const float4*)xx)[i4];
    float4 l = ((const float4*)lf)[i4];
    v.x = fmaxf(fmaf(v.x, iv, nm), 0.f) + l.x;
    v.y = fmaxf(fmaf(v.y, iv, nm), 0.f) + l.y;
    v.z = fmaxf(fmaf(v.z, iv, nm), 0.f) + l.z;
    v.w = fmaxf(fmaf(v.w, iv, nm), 0.f) + l.w;
    ((float4*)g_s)[i4] = v;
}

__global__ void norm_out_k(float* __restrict__ o)
{
    int i4 = blockIdx.x * 256 + threadIdx.x;
    int idx = i4 * 4;
    int c = (idx >> 16) & 63;
    float m = g_stats[9 * 128 + c], iv = g_stats[9 * 128 + 64 + c];
    float nm = -m * iv;
    float4 v = ((float4*)o)[i4];
    v.x = fmaf(v.x, iv, nm); v.y = fmaf(v.y, iv, nm);
    v.z = fmaf(v.z, iv, nm); v.w = fmaf(v.w, iv, nm);
    ((float4*)o)[i4] = v;
}

// ---------------- host orchestration ----------------------------------------------
extern "C" void kernel_launch(void* const* d_in, const int* in_sizes, int n_in,
                              void* d_out, int out_size)
{
    const float* lf   = (const float*)d_in[0];
    const float* hf   = (const float*)d_in[1];
    const float* w11  = (const float*)d_in[2];
    const float* b11  = (const float*)d_in[3];
    const float* wconv= (const float*)d_in[4];
    const float* woff = (const float*)d_in[5];
    const float* boff = (const float*)d_in[6];
    const float* wdef = (const float*)d_in[7];
    const float* wdil[4] = {(const float*)d_in[8], (const float*)d_in[9],
                            (const float*)d_in[10], (const float*)d_in[11]};
    const float* wc1  = (const float*)d_in[12];
    const float* wc2  = (const float*)d_in[13];
    const float* wfc1 = (const float*)d_in[14];
    const float* wfc2 = (const float*)d_in[15];
    const float* wsp  = (const float*)d_in[16];
    const float* wc12 = (const float*)d_in[17];
    const float* bc12 = (const float*)d_in[18];
    const float* wc33 = (const float*)d_in[19];
    float* out = (float*)d_out;

    void* tmp;
#define GETP(name, sym) cudaGetSymbolAddress(&tmp, sym); float* name = (float*)tmp;
    GETP(p_hfpre, g_hfpre) GETP(p_prehf, g_prehf) GETP(p_pre, g_pre)
    GETP(p_t, g_t)         GETP(p_off, g_off)     GETP(p_d16, g_d16)
    GETP(p_y, g_y)         GETP(p_z, g_z)         GETP(p_s, g_s)
    GETP(p_xb, g_xb)       GETP(p_stats, g_stats)
#undef GETP

    const dim3 D1(128, BATCH);           // d1 convs: 512 blocks of 128 thr
    const dim3 D1z4(128, BATCH, 4);      // 4-way COUT split
    const dim3 PGo(256, BATCH);          // old-style 256-thr kernels

    // Stage A: hf_pre = conv1x1(hf)+bias; stats slot0
    conv1x1_64_16_p4<<<D1, 128>>>(hf, w11, b11, p_hfpre);
    bn_final_k<<<16, 32>>>(512, 0);

    // Shared hf-part: conv3x3(relu(bn(hf_pre)), wconv[:,16:32])
    conv3x3_d1<16,16,false,true,true,false,0><<<D1, 128>>>(
        p_hfpre, 16, 0, p_stats + 0*128, wconv, 32, 16, nullptr, nullptr,
        p_prehf, 16);

    for (int k = 0; k < 4; k++) {
        // pre = conv3x3(prev_norm, wconv[:,0:16]) + prehf ; stats slot5
        if (k == 0)
            conv3x3_d1<16,16,false,false,false,true,1><<<D1, 128>>>(
                lf, 64, 0, nullptr, wconv, 32, 0, nullptr, p_prehf, p_pre, 16);
        else
            conv3x3_d1<16,16,false,true,false,true,1><<<D1, 128>>>(
                p_xb + (size_t)(k-1) * SZ16, 16, 0, p_stats + k*128,
                wconv, 32, 0, nullptr, p_prehf, p_pre, 16);
        bn_final_k<<<16, 32>>>(512, 5);

        // t = bn(pre) + extras
        const float* add1 = (k >= 1) ? p_xb + (size_t)(k-1) * SZ16 : nullptr;
        const float* st1  = (k >= 1) ? p_stats + k*128 : nullptr;
        const float* lfa  = (k <= 2) ? lf : nullptr;
        int lfco = (k == 0) ? 16 : (k == 1) ? 32 : 48;
        norm_t_k<<<SZ16 / 1024, 256>>>(p_pre, add1, st1, lfa, lfco);

        // offsets + deformable conv
        conv3x3_d1<16,18,true,false,false,false,0><<<D1, 128>>>(
            p_t, 16, 0, nullptr, woff, 16, 0, boff, nullptr, p_off, 18);
        deform_k<<<PGo, 256>>>(p_t, p_off, wdef, p_d16);

        // dilated conv ; stats slot6
        int nblk6;
        if (k == 0) {
            conv3x3_d1<16,16,false,false,false,false,1><<<D1, 128>>>(
                p_d16, 16, 0, nullptr, wdil[0], 16, 0, nullptr, nullptr, p_y, 16);
            nblk6 = 512;
        } else {
            conv3x3_g<16,16,false,false,false,false,1><<<PGo, 256>>>(
                p_d16, 16, 0, nullptr, wdil[k], 16, 0, nullptr, nullptr, p_y, 16, k + 1);
            nblk6 = 1024;
        }
        bn_final_k<<<16, 32>>>(nblk6, 6);

        // z = conv3x3(bn(y), wc1) 16->64 split 4x16 ; stats+max slot7 partials
        conv3x3_d1<16,16,false,true,false,false,2><<<D1z4, 128>>>(
            p_y, 16, 0, p_stats + 6*128, wc1, 16, 0, nullptr, nullptr, p_z, 64);
        cbam_final_k<<<1, 256>>>(128, wfc1, wfc2);

        // spatial attention
        apply1_k<<<dim3(64, BATCH), 256>>>();
        apply2_k<<<PGo, 256>>>(wsp);

        // branch output: conv2 with fused norm*ca*sg on load ; stats slot 1+k
        conv2_casg_d1<<<D1, 128>>>(wc2, p_xb + (size_t)k * SZ16);
        bn_final_k<<<16, 32>>>(512, 1 + k);
    }

    // xx_pre = conv1x1(cat4_normalized)+bias ; stats slot8
    conv1x1_cat4_p4<<<D1z4, 128>>>(p_xb, wc12, bc12, p_z);
    bn_final_k<<<64, 32>>>(512, 8);
    // s = lf + relu(bn(xx_pre))
    norm_s_k<<<SZ64 / 1024, 256>>>(p_z, lf);

    // out_pre = conv3x3(s, wc33) 64->64 split 4x16 ; stats slot9 ; normalize
    conv3x3_d1<64,16,false,false,false,false,1><<<D1z4, 128>>>(
        p_s, 64, 0, nullptr, wc33, 64, 0, nullptr, nullptr, out, 64);
    bn_final_k<<<64, 32>>>(512, 9);
    norm_out_k<<<SZ64 / 1024, 256>>>(out);
}

// round 5
// speedup vs baseline: 1.8727x; 1.8727x over previous
#include <cuda_runtime.h>
#include <math.h>

#define H 256
#define W 256
#define HW 65536
#define BATCH 4
#define NSTAT (BATCH*HW)
#define NBLKMAX 1024

#define SZ16 (BATCH*16*HW)
#define SZ18 (BATCH*18*HW)
#define SZ64 (BATCH*64*HW)

// ---------------- scratch (static device globals; no allocations) ----------
__device__ __align__(16) float g_hfpre[SZ16];
__device__ __align__(16) float g_prehf[SZ16];
__device__ __align__(16) float g_pre[SZ16];
__device__ __align__(16) float g_t[SZ16];
__device__ __align__(16) float g_off[SZ18];
__device__ __align__(16) float g_d16[SZ16];
__device__ __align__(16) float g_y[SZ16];
__device__ __align__(16) float g_z[SZ64];
__device__ __align__(16) float g_s[SZ64];
__device__ __align__(16) float g_sp[BATCH*2*HW];
__device__ __align__(16) float g_sg[BATCH*HW];
__device__ __align__(16) float g_xb[4*SZ16];
__device__ float g_bsum[NBLKMAX*64];
__device__ float g_bsq[NBLKMAX*64];
__device__ float g_bmax[NBLKMAX*64];
// stats slots: 0=hf, 1..4=branch outs, 5=pre, 6=y, 7=z, 8=xx, 9=final
__device__ float g_stats[10*128];
__device__ float g_ca[BATCH*64];

// ---------------- f32x2 helpers ---------------------------------------------
__device__ __forceinline__ unsigned long long pack2(float lo, float hi) {
    unsigned long long r;
    asm("mov.b64 %0, {%1, %2};" : "=l"(r) : "f"(lo), "f"(hi));
    return r;
}
__device__ __forceinline__ void fma2(unsigned long long& d,
                                     unsigned long long a, unsigned long long b) {
    asm("fma.rn.f32x2 %0, %1, %2, %0;" : "+l"(d) : "l"(a), "l"(b));
}
__device__ __forceinline__ float lo32(unsigned long long u) {
    return __uint_as_float((unsigned)u);
}
__device__ __forceinline__ float hi32(unsigned long long u) {
    return __uint_as_float((unsigned)(u >> 32));
}

// ---------------- BN finalize ------------------------------------------------
__global__ void bn_final_k(int nblk, int slot)
{
    int c = blockIdx.x, lane = threadIdx.x;
    float s = 0.f, q = 0.f;
    for (int j = lane; j < nblk; j += 32) {
        s += g_bsum[j * 64 + c];
        q += g_bsq[j * 64 + c];
    }
    #pragma unroll
    for (int d = 16; d > 0; d >>= 1) {
        s += __shfl_down_sync(0xffffffffu, s, d);
        q += __shfl_down_sync(0xffffffffu, q, d);
    }
    if (lane == 0) {
        float m = s / (float)NSTAT;
        float v = q / (float)NSTAT - m * m;
        g_stats[slot * 128 + c] = m;
        g_stats[slot * 128 + 64 + c] = rsqrtf(v + 1e-5f);
    }
}

// =============== smem-staged 3x3 conv, 4 px/thread, f32x2 =====================
// Block: 256 threads -> 4 rows x 256 cols of output. Grid (64, BATCH, zsplit).
template<int CIN, int COUT, int DIL, bool BIAS, bool NORM, bool RELU, bool ADDEND, int STATS>
__global__ void __launch_bounds__(256, 2) conv3x3_s(
    const float* __restrict__ in, int inCt, int inCo,
    const float* __restrict__ stats,
    const float* __restrict__ w, int wCt, int wCo,
    const float* __restrict__ bias,
    const float* __restrict__ addend,
    float* __restrict__ out, int outCt)
{
    constexpr int CCH = (CIN < 16) ? CIN : 16;
    constexpr int COUTP = (COUT + 3) & ~3;
    constexpr int NP = COUTP / 2;
    constexpr int ITR = 4 + 2 * DIL;
    constexpr int TS = 272;
    __shared__ __align__(16) float tile[ITR * TS];
    __shared__ __align__(16) float ws[CCH * 9 * COUTP];
    __shared__ float reds[STATS ? COUT * 8 : 1];
    __shared__ float redq[STATS ? COUT * 8 : 1];
    __shared__ float redm[(STATS == 2) ? COUT * 8 : 1];

    const int tid = threadIdx.x;
    const int b = blockIdx.y;
    const int oc0 = blockIdx.z * COUT;
    const int y0 = blockIdx.x * 4;
    const int ry = tid >> 6;
    const int cg = (tid & 63) * 4;

    unsigned long long binit[NP];
    #pragma unroll
    for (int j = 0; j < NP; j++) {
        float b0 = (BIAS && 2*j     < COUT) ? __ldg(&bias[oc0 + 2*j])     : 0.f;
        float b1 = (BIAS && 2*j + 1 < COUT) ? __ldg(&bias[oc0 + 2*j + 1]) : 0.f;
        binit[j] = pack2(b0, b1);
    }
    unsigned long long acc2[4][NP];
    #pragma unroll
    for (int p = 0; p < 4; p++)
        #pragma unroll
        for (int j = 0; j < NP; j++)
            acc2[p][j] = binit[j];

    for (int c0 = 0; c0 < CIN; c0 += CCH) {
        __syncthreads();
        for (int i = tid; i < CCH * 9 * COUTP; i += 256) {
            int o = i % COUTP;
            int rem = i / COUTP;
            int k = rem % 9;
            int cl = rem / 9;
            ws[i] = (o < COUT) ? w[((size_t)(oc0 + o) * wCt + wCo + c0 + cl) * 9 + k] : 0.f;
        }
        #pragma unroll 1
        for (int cl = 0; cl < CCH; cl++) {
            __syncthreads();
            {
                const float* __restrict__ inp =
                    in + (size_t)(b * inCt + inCo + c0 + cl) * HW;
                float iv = 1.f, nm = 0.f;
                if (NORM) {
                    float m = stats[c0 + cl];
                    iv = stats[64 + c0 + cl];
                    nm = -m * iv;
                }
                for (int i = tid; i < ITR * TS; i += 256) {
                    int r = i / TS;
                    int gx = i - r * TS - 4;
                    int gy = y0 - DIL + r;
                    float v = 0.f;
                    if ((unsigned)gy < (unsigned)H && (unsigned)gx < (unsigned)W) {
                        v = inp[gy * W + gx];
                        if (NORM) v = fmaf(v, iv, nm);
                        if (RELU) v = fmaxf(v, 0.f);
                    }
                    tile[i] = v;
                }
            }
            __syncthreads();
            #pragma unroll
            for (int ky = 0; ky < 3; ky++) {
                const float* trow = &tile[(ry + ky * DIL) * TS + cg];
                float4 ta = *(const float4*)(trow);
                float4 tb = *(const float4*)(trow + 4);
                float4 tc = *(const float4*)(trow + 8);
                float t[12] = {ta.x, ta.y, ta.z, ta.w,
                               tb.x, tb.y, tb.z, tb.w,
                               tc.x, tc.y, tc.z, tc.w};
                unsigned long long vp[12];
                #pragma unroll
                for (int j = 4 - DIL; j <= 7 + DIL; j++)
                    vp[j] = pack2(t[j], t[j]);
                #pragma unroll
                for (int kx = 0; kx < 3; kx++) {
                    const ulonglong2* wr =
                        (const ulonglong2*)&ws[(cl * 9 + ky * 3 + kx) * COUTP];
                    #pragma unroll
                    for (int q = 0; q < COUTP / 4; q++) {
                        ulonglong2 wp = wr[q];
                        #pragma unroll
                        for (int p = 0; p < 4; p++) {
                            fma2(acc2[p][2*q],   vp[4 + p + (kx-1)*DIL], wp.x);
                            fma2(acc2[p][2*q+1], vp[4 + p + (kx-1)*DIL], wp.y);
                        }
                    }
                }
            }
        }
    }

    // ---- epilogue: unpack, addend, store, stats ----
    const int pixb = (y0 + ry) * W + cg;
    const int lane = tid & 31, wid = tid >> 5;
    #pragma unroll
    for (int o = 0; o < COUT; o++) {
        float a0 = (o & 1) ? hi32(acc2[0][o >> 1]) : lo32(acc2[0][o >> 1]);
        float a1 = (o & 1) ? hi32(acc2[1][o >> 1]) : lo32(acc2[1][o >> 1]);
        float a2 = (o & 1) ? hi32(acc2[2][o >> 1]) : lo32(acc2[2][o >> 1]);
        float a3 = (o & 1) ? hi32(acc2[3][o >> 1]) : lo32(acc2[3][o >> 1]);
        if (ADDEND) {
            float4 ad = *(const float4*)(addend + (size_t)(b * COUT + o) * HW + pixb);
            a0 += ad.x; a1 += ad.y; a2 += ad.z; a3 += ad.w;
        }
        float4 v = make_float4(a0, a1, a2, a3);
        *(float4*)(out + (size_t)(b * outCt + oc0 + o) * HW + pixb) = v;
        if constexpr (STATS > 0) {
            float s = a0 + a1 + a2 + a3;
            float q = a0*a0 + a1*a1 + a2*a2 + a3*a3;
            float mx = fmaxf(fmaxf(a0, a1), fmaxf(a2, a3));
            #pragma unroll
            for (int d = 16; d > 0; d >>= 1) {
                s += __shfl_down_sync(0xffffffffu, s, d);
                q += __shfl_down_sync(0xffffffffu, q, d);
                if (STATS == 2) mx = fmaxf(mx, __shfl_down_sync(0xffffffffu, mx, d));
            }
            if (lane == 0) {
                reds[o * 8 + wid] = s;
                redq[o * 8 + wid] = q;
                if (STATS == 2) redm[o * 8 + wid] = mx;
            }
        }
    }
    if constexpr (STATS > 0) {
        __syncthreads();
        if (tid < COUT) {
            float s = 0.f, q = 0.f, mx = -INFINITY;
            #pragma unroll
            for (int j = 0; j < 8; j++) {
                s += reds[tid * 8 + j];
                q += redq[tid * 8 + j];
                if (STATS == 2) mx = fmaxf(mx, redm[tid * 8 + j]);
            }
            int rowi = b * gridDim.x + blockIdx.x;
            g_bsum[rowi * 64 + oc0 + tid] = s;
            g_bsq[rowi * 64 + oc0 + tid] = q;
            if (STATS == 2) g_bmax[rowi * 64 + oc0 + tid] = mx;
        }
    }
}

// =============== conv2 (64->16) with fused norm*ca*sg, smem-staged ============
__global__ void __launch_bounds__(256, 2) conv2_casg_s(
    const float* __restrict__ w, float* __restrict__ out)
{
    constexpr int TS = 272;
    constexpr int ITR = 6;
    __shared__ __align__(16) float tile[ITR * TS];
    __shared__ __align__(16) float sgt[ITR * TS];
    __shared__ __align__(16) float ws[16 * 9 * 16];
    __shared__ float reds[16 * 8], redq[16 * 8];
    __shared__ float sc[64], sb[64];

    const int tid = threadIdx.x;
    const int b = blockIdx.y;
    const int y0 = blockIdx.x * 4;
    const int ry = tid >> 6;
    const int cg = (tid & 63) * 4;

    if (tid < 64) {
        float iv = g_stats[7 * 128 + 64 + tid], m = g_stats[7 * 128 + tid];
        float s = iv * g_ca[b * 64 + tid];
        sc[tid] = s; sb[tid] = -m * s;
    }
    {
        const float* sgp = g_sg + (size_t)b * HW;
        for (int i = tid; i < ITR * TS; i += 256) {
            int r = i / TS;
            int gx = i - r * TS - 4;
            int gy = y0 - 1 + r;
            sgt[i] = ((unsigned)gy < (unsigned)H && (unsigned)gx < (unsigned)W)
                     ? sgp[gy * W + gx] : 0.f;
        }
    }

    unsigned long long acc2[4][8];
    #pragma unroll
    for (int p = 0; p < 4; p++)
        #pragma unroll
        for (int j = 0; j < 8; j++) acc2[p][j] = 0ull;

    for (int c0 = 0; c0 < 64; c0 += 16) {
        __syncthreads();
        for (int i = tid; i < 16 * 9 * 16; i += 256) {
            int o = i & 15;
            int rem = i >> 4;
            int k = rem % 9;
            int cl = rem / 9;
            ws[i] = w[((size_t)o * 64 + c0 + cl) * 9 + k];
        }
        #pragma unroll 1
        for (int cl = 0; cl < 16; cl++) {
            __syncthreads();
            {
                const float* __restrict__ inp = g_z + (size_t)(b * 64 + c0 + cl) * HW;
                float scc = sc[c0 + cl], bcc = sb[c0 + cl];
                for (int i = tid; i < ITR * TS; i += 256) {
                    int r = i / TS;
                    int gx = i - r * TS - 4;
                    int gy = y0 - 1 + r;
                    float v = 0.f;
                    if ((unsigned)gy < (unsigned)H && (unsigned)gx < (unsigned)W)
                        v = fmaf(inp[gy * W + gx], scc, bcc) * sgt[i];
                    tile[i] = v;
                }
            }
            __syncthreads();
            #pragma unroll
            for (int ky = 0; ky < 3; ky++) {
                const float* trow = &tile[(ry + ky) * TS + cg];
                float4 ta = *(const float4*)(trow);
                float4 tb = *(const float4*)(trow + 4);
                float4 tc = *(const float4*)(trow + 8);
                float t[12] = {ta.x, ta.y, ta.z, ta.w,
                               tb.x, tb.y, tb.z, tb.w,
                               tc.x, tc.y, tc.z, tc.w};
                unsigned long long vp[12];
                #pragma unroll
                for (int j = 3; j <= 8; j++) vp[j] = pack2(t[j], t[j]);
                #pragma unroll
                for (int kx = 0; kx < 3; kx++) {
                    const ulonglong2* wr = (const ulonglong2*)&ws[(cl*9 + ky*3 + kx) * 16];
                    #pragma unroll
                    for (int q = 0; q < 4; q++) {
                        ulonglong2 wp = wr[q];
                        #pragma unroll
                        for (int p = 0; p < 4; p++) {
                            fma2(acc2[p][2*q],   vp[4 + p + (kx-1)], wp.x);
                            fma2(acc2[p][2*q+1], vp[4 + p + (kx-1)], wp.y);
                        }
                    }
                }
            }
        }
    }

    const int pixb = (y0 + ry) * W + cg;
    const int lane = tid & 31, wid = tid >> 5;
    #pragma unroll
    for (int o = 0; o < 16; o++) {
        float a0 = (o & 1) ? hi32(acc2[0][o >> 1]) : lo32(acc2[0][o >> 1]);
        float a1 = (o & 1) ? hi32(acc2[1][o >> 1]) : lo32(acc2[1][o >> 1]);
        float a2 = (o & 1) ? hi32(acc2[2][o >> 1]) : lo32(acc2[2][o >> 1]);
        float a3 = (o & 1) ? hi32(acc2[3][o >> 1]) : lo32(acc2[3][o >> 1]);
        *(float4*)(out + (size_t)(b * 16 + o) * HW + pixb) = make_float4(a0, a1, a2, a3);
        float s = a0 + a1 + a2 + a3;
        float q = a0*a0 + a1*a1 + a2*a2 + a3*a3;
        #pragma unroll
        for (int d = 16; d > 0; d >>= 1) {
            s += __shfl_down_sync(0xffffffffu, s, d);
            q += __shfl_down_sync(0xffffffffu, q, d);
        }
        if (lane == 0) { reds[o * 8 + wid] = s; redq[o * 8 + wid] = q; }
    }
    __syncthreads();
    if (tid < 16) {
        float s = 0.f, q = 0.f;
        #pragma unroll
        for (int j = 0; j < 8; j++) { s += reds[tid*8+j]; q += redq[tid*8+j]; }
        int rowi = b * gridDim.x + blockIdx.x;
        g_bsum[rowi * 64 + tid] = s;
        g_bsq[rowi * 64 + tid] = q;
    }
}

// ---------------- 1x1 convs, 4 pixels/thread (coalesced float4) --------------
__global__ void __launch_bounds__(128) conv1x1_64_16_p4(
    const float* __restrict__ in, const float* __restrict__ w,
    const float* __restrict__ bias, float* __restrict__ out)
{
    __shared__ __align__(16) float ws[64*16];
    __shared__ float reds[16*4], redq[16*4];
    int tid = threadIdx.x;
    for (int i = tid; i < 64*16; i += 128) {
        int o = i & 15, c = i >> 4;
        ws[i] = w[o * 64 + c];
    }
    __syncthreads();
    int p4 = blockIdx.x * 128 + tid;
    int b = blockIdx.y;
    const float4* inb = (const float4*)(in + (size_t)b * 64 * HW) + p4;
    unsigned long long acc2[4][8];
    #pragma unroll
    for (int j = 0; j < 8; j++) {
        unsigned long long bv = pack2(__ldg(&bias[2*j]), __ldg(&bias[2*j+1]));
        acc2[0][j] = bv; acc2[1][j] = bv; acc2[2][j] = bv; acc2[3][j] = bv;
    }
    #pragma unroll 1
    for (int c = 0; c < 64; c++) {
        float4 v = inb[(size_t)c * (HW / 4)];
        unsigned long long v0 = pack2(v.x, v.x), v1 = pack2(v.y, v.y);
        unsigned long long v2 = pack2(v.z, v.z), v3 = pack2(v.w, v.w);
        const ulonglong2* wr = (const ulonglong2*)&ws[c * 16];
        #pragma unroll
        for (int q = 0; q < 4; q++) {
            ulonglong2 wp = wr[q];
            fma2(acc2[0][2*q], v0, wp.x); fma2(acc2[0][2*q+1], v0, wp.y);
            fma2(acc2[1][2*q], v1, wp.x); fma2(acc2[1][2*q+1], v1, wp.y);
            fma2(acc2[2][2*q], v2, wp.x); fma2(acc2[2][2*q+1], v2, wp.y);
            fma2(acc2[3][2*q], v3, wp.x); fma2(acc2[3][2*q+1], v3, wp.y);
        }
    }
    int lane = tid & 31, wid = tid >> 5;
    #pragma unroll
    for (int o = 0; o < 16; o++) {
        float a0 = (o&1) ? hi32(acc2[0][o>>1]) : lo32(acc2[0][o>>1]);
        float a1 = (o&1) ? hi32(acc2[1][o>>1]) : lo32(acc2[1][o>>1]);
        float a2 = (o&1) ? hi32(acc2[2][o>>1]) : lo32(acc2[2][o>>1]);
        float a3 = (o&1) ? hi32(acc2[3][o>>1]) : lo32(acc2[3][o>>1]);
        ((float4*)out)[(size_t)(b * 16 + o) * (HW / 4) + p4] = make_float4(a0,a1,a2,a3);
        float s = a0+a1+a2+a3;
        float q = a0*a0+a1*a1+a2*a2+a3*a3;
        #pragma unroll
        for (int d = 16; d > 0; d >>= 1) {
            s += __shfl_down_sync(0xffffffffu, s, d);
            q += __shfl_down_sync(0xffffffffu, q, d);
        }
        if (lane == 0) { reds[o*4+wid] = s; redq[o*4+wid] = q; }
    }
    __syncthreads();
    if (tid < 16) {
        float s = 0.f, q = 0.f;
        #pragma unroll
        for (int j = 0; j < 4; j++) { s += reds[tid*4+j]; q += redq[tid*4+j]; }
        int rowi = b * gridDim.x + blockIdx.x;
        g_bsum[rowi * 64 + tid] = s;
        g_bsq[rowi * 64 + tid] = q;
    }
}

// 64->64 1x1 over normalized cat4; split 4 x 16 outputs; 4 px/thread
__global__ void __launch_bounds__(128) conv1x1_cat4_p4(
    const float* __restrict__ xb, const float* __restrict__ w,
    const float* __restrict__ bias, float* __restrict__ out)
{
    __shared__ __align__(16) float ws[64*16];
    __shared__ float siv[64], snm[64];
    __shared__ float reds[16*4], redq[16*4];
    int tid = threadIdx.x;
    int oc0 = blockIdx.z * 16;
    if (tid < 64) {
        int s = tid >> 4, c = tid & 15;
        float m = g_stats[(1 + s) * 128 + c];
        float iv = g_stats[(1 + s) * 128 + 64 + c];
        siv[tid] = iv; snm[tid] = -m * iv;
    }
    for (int i = tid; i < 64*16; i += 128) {
        int o = i & 15, c = i >> 4;
        ws[i] = w[(oc0 + o) * 64 + c];
    }
    __syncthreads();
    int p4 = blockIdx.x * 128 + tid;
    int b = blockIdx.y;
    unsigned long long acc2[4][8];
    #pragma unroll
    for (int j = 0; j < 8; j++) {
        unsigned long long bv = pack2(__ldg(&bias[oc0+2*j]), __ldg(&bias[oc0+2*j+1]));
        acc2[0][j] = bv; acc2[1][j] = bv; acc2[2][j] = bv; acc2[3][j] = bv;
    }
    #pragma unroll 1
    for (int c = 0; c < 64; c++) {
        const float* src = xb + (size_t)(c >> 4) * SZ16 + (size_t)(b * 16 + (c & 15)) * HW;
        float4 v = ((const float4*)src)[p4];
        float ivc = siv[c], nmc = snm[c];
        v.x = fmaf(v.x, ivc, nmc); v.y = fmaf(v.y, ivc, nmc);
        v.z = fmaf(v.z, ivc, nmc); v.w = fmaf(v.w, ivc, nmc);
        unsigned long long v0 = pack2(v.x, v.x), v1 = pack2(v.y, v.y);
        unsigned long long v2 = pack2(v.z, v.z), v3 = pack2(v.w, v.w);
        const ulonglong2* wr = (const ulonglong2*)&ws[c * 16];
        #pragma unroll
        for (int q = 0; q < 4; q++) {
            ulonglong2 wp = wr[q];
            fma2(acc2[0][2*q], v0, wp.x); fma2(acc2[0][2*q+1], v0, wp.y);
            fma2(acc2[1][2*q], v1, wp.x); fma2(acc2[1][2*q+1], v1, wp.y);
            fma2(acc2[2][2*q], v2, wp.x); fma2(acc2[2][2*q+1], v2, wp.y);
            fma2(acc2[3][2*q], v3, wp.x); fma2(acc2[3][2*q+1], v3, wp.y);
        }
    }
    int lane = tid & 31, wid = tid >> 5;
    #pragma unroll
    for (int o = 0; o < 16; o++) {
        float a0 = (o&1) ? hi32(acc2[0][o>>1]) : lo32(acc2[0][o>>1]);
        float a1 = (o&1) ? hi32(acc2[1][o>>1]) : lo32(acc2[1][o>>1]);
        float a2 = (o&1) ? hi32(acc2[2][o>>1]) : lo32(acc2[2][o>>1]);
        float a3 = (o&1) ? hi32(acc2[3][o>>1]) : lo32(acc2[3][o>>1]);
        ((float4*)out)[(size_t)(b * 64 + oc0 + o) * (HW / 4) + p4] = make_float4(a0,a1,a2,a3);
        float s = a0+a1+a2+a3;
        float q = a0*a0+a1*a1+a2*a2+a3*a3;
        #pragma unroll
        for (int d = 16; d > 0; d >>= 1) {
            s += __shfl_down_sync(0xffffffffu, s, d);
            q += __shfl_down_sync(0xffffffffu, q, d);
        }
        if (lane == 0) { reds[o*4+wid] = s; redq[o*4+wid] = q; }
    }
    __syncthreads();
    if (tid < 16) {
        float s = 0.f, q = 0.f;
        #pragma unroll
        for (int j = 0; j < 4; j++) { s += reds[tid*4+j]; q += redq[tid*4+j]; }
        int rowi = b * gridDim.x + blockIdx.x;
        g_bsum[rowi * 64 + oc0 + tid] = s;
        g_bsq[rowi * 64 + oc0 + tid] = q;
    }
}

// ---------------- t materialization (float4) ----------------------------------
__global__ void norm_t_k(const float* __restrict__ pre,
                         const float* __restrict__ add1, const float* __restrict__ st1,
                         const float* __restrict__ lfsrc, int lfco)
{
    int i4 = blockIdx.x * 256 + threadIdx.x;
    int idx = i4 * 4;
    int pix = idx & (HW - 1);
    int rest = idx >> 16;
    int c = rest & 15, b = rest >> 4;
    float m = g_stats[5 * 128 + c], iv = g_stats[5 * 128 + 64 + c];
    float nm = -m * iv;
    float4 v = ((const float4*)pre)[i4];
    v.x = fmaf(v.x, iv, nm); v.y = fmaf(v.y, iv, nm);
    v.z = fmaf(v.z, iv, nm); v.w = fmaf(v.w, iv, nm);
    if (add1) {
        float4 a = ((const float4*)add1)[i4];
        if (st1) {
            float m1 = st1[c], i1 = st1[64 + c], n1 = -m1 * i1;
            a.x = fmaf(a.x, i1, n1); a.y = fmaf(a.y, i1, n1);
            a.z = fmaf(a.z, i1, n1); a.w = fmaf(a.w, i1, n1);
        }
        v.x += a.x; v.y += a.y; v.z += a.z; v.w += a.w;
    }
    if (lfsrc) {
        float4 l = *(const float4*)(lfsrc + (size_t)(b * 64 + lfco + c) * HW + pix);
        v.x += l.x; v.y += l.y; v.z += l.z; v.w += l.w;
    }
    ((float4*)g_t)[i4] = v;
}

// ---------------- deformable conv (exact reference semantics, f32x2) ----------
__global__ void __launch_bounds__(256) deform_k(
    const float* __restrict__ t, const float* __restrict__ off,
    const float* __restrict__ wd, float* __restrict__ out)
{
    __shared__ __align__(16) float ws[16*16*9];
    for (int i = threadIdx.x; i < 2304; i += blockDim.x) {
        int o = i & 15;
        int rem = i >> 4;
        int n = rem % 9;
        int c = rem / 9;
        ws[i] = wd[(o * 16 + c) * 9 + n];
    }
    __syncthreads();
    int pix = blockIdx.x * blockDim.x + threadIdx.x;
    int b = blockIdx.y;
    int yi = pix >> 8, xj = pix & 255;

    unsigned long long acc2[8];
    #pragma unroll
    for (int j = 0; j < 8; j++) acc2[j] = 0ull;

    const float* offb = off + (size_t)b * 18 * HW + pix;
    const float* tb = t + (size_t)b * 16 * HW;

    #pragma unroll 1
    for (int n = 0; n < 9; n++) {
        int dx = n / 3 - 1, dy = n % 3 - 1;
        float ox = offb[(size_t)(2 * n) * HW];
        float oy = offb[(size_t)(2 * n + 1) * HW];
        float plx = (float)(yi + 1 + dx) + ox;
        float ply = (float)(xj + 1 + dy) + oy;
        float flx = floorf(plx), fly = floorf(ply);
        int qltx = min(max((int)flx, 0), 257);
        int qlty = min(max((int)fly, 0), 257);
        int qrbx = min(max((int)flx + 1, 0), 257);
        int qrby = min(max((int)fly + 1, 0), 257);
        bool mx = (plx < 1.0f) || (plx > 256.0f);
        bool my = (ply < 1.0f) || (ply > 256.0f);
        float px = mx ? flx : plx; px = fminf(fmaxf(px, 0.f), 257.f);
        float py = my ? fly : ply; py = fminf(fmaxf(py, 0.f), 257.f);
        float wltx = 1.f + ((float)qltx - px);
        float wrbx = 1.f - ((float)qrbx - px);
        float wlty = 1.f + ((float)qlty - py);
        float wrby = 1.f - ((float)qrby - py);
        float glt = wltx * wlty, grb = wrbx * wrby;
        float glb = wltx * wrby, grt = wrbx * wlty;
        bool vltx = (qltx >= 1 && qltx <= 256);
        bool vlty = (qlty >= 1 && qlty <= 256);
        bool vrbx = (qrbx >= 1 && qrbx <= 256);
        bool vrby = (qrby >= 1 && qrby <= 256);
        int rlt = (qltx - 1) * W + (qlty - 1);
        int rrb = (qrbx - 1) * W + (qrby - 1);
        int rlb = (qltx - 1) * W + (qrby - 1);
        int rrt = (qrbx - 1) * W + (qlty - 1);
        #pragma unroll 1
        for (int c = 0; c < 16; c++) {
            const float* tc = tb + (size_t)c * HW;
            float vlt = (vltx && vlty) ? tc[rlt] : 0.f;
            float vrb = (vrbx && vrby) ? tc[rrb] : 0.f;
            float vlb = (vltx && vrby) ? tc[rlb] : 0.f;
            float vrt = (vrbx && vlty) ? tc[rrt] : 0.f;
            float val = glt * vlt + grb * vrb + glb * vlb + grt * vrt;
            unsigned long long vp = pack2(val, val);
            const ulonglong2* wr = (const ulonglong2*)&ws[(c * 9 + n) * 16];
            #pragma unroll
            for (int q = 0; q < 4; q++) {
                ulonglong2 wp = wr[q];
                fma2(acc2[2*q],   vp, wp.x);
                fma2(acc2[2*q+1], vp, wp.y);
            }
        }
    }
    #pragma unroll
    for (int o = 0; o < 16; o++) {
        float v = (o & 1) ? hi32(acc2[o >> 1]) : lo32(acc2[o >> 1]);
        out[(size_t)(b * 16 + o) * HW + pix] = v;
    }
}

// ---------------- CBAM ----------------------------------------------------------
__global__ void cbam_final_k(int gridX, const float* __restrict__ w1,
                             const float* __restrict__ w2)
{
    int t = threadIdx.x;
    int b = t >> 6, c = t & 63;
    float s = 0.f, q = 0.f, mx = -INFINITY;
    for (int j = 0; j < gridX; j++) {
        int idx = (b * gridX + j) * 64 + c;
        s += g_bsum[idx]; q += g_bsq[idx]; mx = fmaxf(mx, g_bmax[idx]);
    }
    __shared__ float sh_s[4][64], sh_q[4][64], sh_m[4][64];
    sh_s[b][c] = s; sh_q[b][c] = q; sh_m[b][c] = mx;
    __syncthreads();
    __shared__ float sm[64], si[64];
    if (t < 64) {
        float ts = 0.f, tq = 0.f;
        #pragma unroll
        for (int bb = 0; bb < 4; bb++) { ts += sh_s[bb][t]; tq += sh_q[bb][t]; }
        float m = ts / (float)NSTAT;
        float v = tq / (float)NSTAT - m * m;
        float iv = rsqrtf(v + 1e-5f);
        g_stats[7 * 128 + t] = m;
        g_stats[7 * 128 + 64 + t] = iv;
        sm[t] = m; si[t] = iv;
    }
    __syncthreads();
    __shared__ float av[4][64], xmv[4][64];
    av[b][c]  = (sh_s[b][c] / (float)HW - sm[c]) * si[c];
    xmv[b][c] = (sh_m[b][c] - sm[c]) * si[c];
    __syncthreads();
    __shared__ float hid[4][4][2];
    if (t < 32) {
        int bb = t >> 3, h = (t >> 1) & 3, which = t & 1;
        float acc = 0.f;
        for (int cc = 0; cc < 64; cc++)
            acc += w1[h * 64 + cc] * (which ? xmv[bb][cc] : av[bb][cc]);
        hid[bb][h][which] = fmaxf(acc, 0.f);
    }
    __syncthreads();
    {
        float va = 0.f, vm = 0.f;
        #pragma unroll
        for (int h = 0; h < 4; h++) {
            float wv = w2[c * 4 + h];
            va = fmaf(wv, hid[b][h][0], va);
            vm = fmaf(wv, hid[b][h][1], vm);
        }
        g_ca[b * 64 + c] = 1.f / (1.f + expf(-(va + vm)));
    }
}

// sp (mean,max over channels of (z norm * ca)), float4 over pixels
__global__ void apply1_k()
{
    __shared__ float sc[64], sb[64];
    int b = blockIdx.y;
    if (threadIdx.x < 64) {
        int c = threadIdx.x;
        float iv = g_stats[7 * 128 + 64 + c], m = g_stats[7 * 128 + c];
        float s = iv * g_ca[b * 64 + c];
        sc[c] = s; sb[c] = -m * s;
    }
    __syncthreads();
    int p4 = blockIdx.x * 256 + threadIdx.x;
    const float4* zp = (const float4*)(g_z + (size_t)b * 64 * HW) + p4;
    float4 smv = make_float4(0.f, 0.f, 0.f, 0.f);
    float4 mxv = make_float4(-INFINITY, -INFINITY, -INFINITY, -INFINITY);
    #pragma unroll 1
    for (int c = 0; c < 64; c++) {
        float4 v = zp[(size_t)c * (HW / 4)];
        float s = sc[c], bb = sb[c];
        v.x = fmaf(v.x, s, bb); v.y = fmaf(v.y, s, bb);
        v.z = fmaf(v.z, s, bb); v.w = fmaf(v.w, s, bb);
        smv.x += v.x; smv.y += v.y; smv.z += v.z; smv.w += v.w;
        mxv.x = fmaxf(mxv.x, v.x); mxv.y = fmaxf(mxv.y, v.y);
        mxv.z = fmaxf(mxv.z, v.z); mxv.w = fmaxf(mxv.w, v.w);
    }
    const float k = 1.f / 64.f;
    smv.x *= k; smv.y *= k; smv.z *= k; smv.w *= k;
    ((float4*)(g_sp + (size_t)(b * 2) * HW))[p4] = smv;
    ((float4*)(g_sp + (size_t)(b * 2 + 1) * HW))[p4] = mxv;
}

// sg = sigmoid(conv7x7(sp))
__global__ void apply2_k(const float* __restrict__ wsp)
{
    __shared__ float w[98];
    if (threadIdx.x < 98) w[threadIdx.x] = wsp[threadIdx.x];
    __syncthreads();
    int pix = blockIdx.x * 256 + threadIdx.x;
    int b = blockIdx.y;
    int y = pix >> 8, x = pix & 255;
    const float* s0 = g_sp + (size_t)(b * 2) * HW;
    const float* s1 = s0 + HW;
    float acc = 0.f;
    #pragma unroll 1
    for (int ky = 0; ky < 7; ky++) {
        int yy = y + ky - 3;
        if ((unsigned)yy >= (unsigned)H) continue;
        #pragma unroll
        for (int kx = 0; kx < 7; kx++) {
            int xx = x + kx - 3;
            if ((unsigned)xx >= (unsigned)W) continue;
            int ip = yy * W + xx;
            acc += w[ky * 7 + kx] * s0[ip] + w[49 + ky * 7 + kx] * s1[ip];
        }
    }
    g_sg[(size_t)b * HW + pix] = 1.f / (1.f + expf(-acc));
}

// ---------------- final elementwise ----------------------------------------------
__global__ void norm_s_k(const float* __restrict__ xx, const float* __restrict__ lf)
{
    int i4 = blockIdx.x * 256 + threadIdx.x;
    int idx = i4 * 4;
    int c = (idx >> 16) & 63;
    float m = g_stats[8 * 128 + c], iv = g_stats[8 * 128 + 64 + c];
    float nm = -m * iv;
    float4 v = ((const float4*)xx)[i4];
    float4 l = ((const float4*)lf)[i4];
    v.x = fmaxf(fmaf(v.x, iv, nm), 0.f) + l.x;
    v.y = fmaxf(fmaf(v.y, iv, nm), 0.f) + l.y;
    v.z = fmaxf(fmaf(v.z, iv, nm), 0.f) + l.z;
    v.w = fmaxf(fmaf(v.w, iv, nm), 0.f) + l.w;
    ((float4*)g_s)[i4] = v;
}

__global__ void norm_out_k(float* __restrict__ o)
{
    int i4 = blockIdx.x * 256 + threadIdx.x;
    int idx = i4 * 4;
    int c = (idx >> 16) & 63;
    float m = g_stats[9 * 128 + c], iv = g_stats[9 * 128 + 64 + c];
    float nm = -m * iv;
    float4 v = ((float4*)o)[i4];
    v.x = fmaf(v.x, iv, nm); v.y = fmaf(v.y, iv, nm);
    v.z = fmaf(v.z, iv, nm); v.w = fmaf(v.w, iv, nm);
    ((float4*)o)[i4] = v;
}

// ---------------- host orchestration ----------------------------------------------
extern "C" void kernel_launch(void* const* d_in, const int* in_sizes, int n_in,
                              void* d_out, int out_size)
{
    const float* lf   = (const float*)d_in[0];
    const float* hf   = (const float*)d_in[1];
    const float* w11  = (const float*)d_in[2];
    const float* b11  = (const float*)d_in[3];
    const float* wconv= (const float*)d_in[4];
    const float* woff = (const float*)d_in[5];
    const float* boff = (const float*)d_in[6];
    const float* wdef = (const float*)d_in[7];
    const float* wdil[4] = {(const float*)d_in[8], (const float*)d_in[9],
                            (const float*)d_in[10], (const float*)d_in[11]};
    const float* wc1  = (const float*)d_in[12];
    const float* wc2  = (const float*)d_in[13];
    const float* wfc1 = (const float*)d_in[14];
    const float* wfc2 = (const float*)d_in[15];
    const float* wsp  = (const float*)d_in[16];
    const float* wc12 = (const float*)d_in[17];
    const float* bc12 = (const float*)d_in[18];
    const float* wc33 = (const float*)d_in[19];
    float* out = (float*)d_out;

    void* tmp;
#define GETP(name, sym) cudaGetSymbolAddress(&tmp, sym); float* name = (float*)tmp;
    GETP(p_hfpre, g_hfpre) GETP(p_prehf, g_prehf) GETP(p_pre, g_pre)
    GETP(p_t, g_t)         GETP(p_off, g_off)     GETP(p_d16, g_d16)
    GETP(p_y, g_y)         GETP(p_z, g_z)         GETP(p_s, g_s)
    GETP(p_xb, g_xb)       GETP(p_stats, g_stats)
#undef GETP

    const dim3 CS(64, BATCH);            // staged convs: 256 blocks of 256 thr
    const dim3 CSz2(64, BATCH, 2);
    const dim3 CSz4(64, BATCH, 4);
    const dim3 P4(128, BATCH);           // 1x1 p4 kernels
    const dim3 P4z4(128, BATCH, 4);
    const dim3 PGo(256, BATCH);

    // Stage A: hf_pre = conv1x1(hf)+bias; stats slot0
    conv1x1_64_16_p4<<<P4, 128>>>(hf, w11, b11, p_hfpre);
    bn_final_k<<<16, 32>>>(512, 0);

    // Shared hf-part: conv3x3(relu(bn(hf_pre)), wconv[:,16:32])
    conv3x3_s<16,16,1,false,true,true,false,0><<<CS, 256>>>(
        p_hfpre, 16, 0, p_stats + 0*128, wconv, 32, 16, nullptr, nullptr,
        p_prehf, 16);

    for (int k = 0; k < 4; k++) {
        // pre = conv3x3(prev_norm, wconv[:,0:16]) + prehf ; stats slot5
        if (k == 0)
            conv3x3_s<16,16,1,false,false,false,true,1><<<CS, 256>>>(
                lf, 64, 0, nullptr, wconv, 32, 0, nullptr, p_prehf, p_pre, 16);
        else
            conv3x3_s<16,16,1,false,true,false,true,1><<<CS, 256>>>(
                p_xb + (size_t)(k-1) * SZ16, 16, 0, p_stats + k*128,
                wconv, 32, 0, nullptr, p_prehf, p_pre, 16);
        bn_final_k<<<16, 32>>>(256, 5);

        // t = bn(pre) + extras
        const float* add1 = (k >= 1) ? p_xb + (size_t)(k-1) * SZ16 : nullptr;
        const float* st1  = (k >= 1) ? p_stats + k*128 : nullptr;
        const float* lfa  = (k <= 2) ? lf : nullptr;
        int lfco = (k == 0) ? 16 : (k == 1) ? 32 : 48;
        norm_t_k<<<SZ16 / 1024, 256>>>(p_pre, add1, st1, lfa, lfco);

        // offsets (COUT 18 as 2x9) + deformable conv
        conv3x3_s<16,9,1,true,false,false,false,0><<<CSz2, 256>>>(
            p_t, 16, 0, nullptr, woff, 16, 0, boff, nullptr, p_off, 18);
        deform_k<<<PGo, 256>>>(p_t, p_off, wdef, p_d16);

        // dilated conv ; stats slot6
        switch (k) {
        case 0: conv3x3_s<16,16,1,false,false,false,false,1><<<CS, 256>>>(
                    p_d16, 16, 0, nullptr, wdil[0], 16, 0, nullptr, nullptr, p_y, 16); break;
        case 1: conv3x3_s<16,16,2,false,false,false,false,1><<<CS, 256>>>(
                    p_d16, 16, 0, nullptr, wdil[1], 16, 0, nullptr, nullptr, p_y, 16); break;
        case 2: conv3x3_s<16,16,3,false,false,false,false,1><<<CS, 256>>>(
                    p_d16, 16, 0, nullptr, wdil[2], 16, 0, nullptr, nullptr, p_y, 16); break;
        default: conv3x3_s<16,16,4,false,false,false,false,1><<<CS, 256>>>(
                    p_d16, 16, 0, nullptr, wdil[3], 16, 0, nullptr, nullptr, p_y, 16); break;
        }
        bn_final_k<<<16, 32>>>(256, 6);

        // z = conv3x3(bn(y), wc1) 16->64 split 4x16 ; stats+max slot7 partials
        conv3x3_s<16,16,1,false,true,false,false,2><<<CSz4, 256>>>(
            p_y, 16, 0, p_stats + 6*128, wc1, 16, 0, nullptr, nullptr, p_z, 64);
        cbam_final_k<<<1, 256>>>(64, wfc1, wfc2);

        // spatial attention
        apply1_k<<<dim3(64, BATCH), 256>>>();
        apply2_k<<<PGo, 256>>>(wsp);

        // branch output: conv2 with fused norm*ca*sg on load ; stats slot 1+k
        conv2_casg_s<<<CS, 256>>>(wc2, p_xb + (size_t)k * SZ16);
        bn_final_k<<<16, 32>>>(256, 1 + k);
    }

    // xx_pre = conv1x1(cat4_normalized)+bias ; stats slot8
    conv1x1_cat4_p4<<<P4z4, 128>>>(p_xb, wc12, bc12, p_z);
    bn_final_k<<<64, 32>>>(512, 8);
    // s = lf + relu(bn(xx_pre))
    norm_s_k<<<SZ64 / 1024, 256>>>(p_z, lf);

    // out_pre = conv3x3(s, wc33) 64->64 split 4x16 ; stats slot9 ; normalize
    conv3x3_s<64,16,1,false,false,false,false,1><<<CSz4, 256>>>(
        p_s, 64, 0, nullptr, wc33, 64, 0, nullptr, nullptr, out, 64);
    bn_final_k<<<64, 32>>>(256, 9);
    norm_out_k<<<SZ64 / 1024, 256>>>(out);
}

// round 6
// speedup vs baseline: 1.9513x; 1.0420x over previous
#include <cuda_runtime.h>
#include <math.h>

#define H 256
#define W 256
#define HW 65536
#define BATCH 4
#define NSTAT (BATCH*HW)
#define NBLKMAX 1024

#define SZ16 (BATCH*16*HW)
#define SZ18 (BATCH*18*HW)
#define SZ64 (BATCH*64*HW)

// ---------------- scratch (static device globals; no allocations) ----------
__device__ __align__(16) float g_hfpre[SZ16];
__device__ __align__(16) float g_prehf[SZ16];
__device__ __align__(16) float g_pre[SZ16];
__device__ __align__(16) float g_t[SZ16];
__device__ __align__(16) float g_off[SZ18];
__device__ __align__(16) float g_d16[SZ16];
__device__ __align__(16) float g_y[SZ16];
__device__ __align__(16) float g_z[SZ64];
__device__ __align__(16) float g_s[SZ64];
__device__ __align__(16) float g_sp[BATCH*2*HW];
__device__ __align__(16) float g_sg[BATCH*HW];
__device__ __align__(16) float g_xb[4*SZ16];
__device__ float g_bsum[NBLKMAX*64];
__device__ float g_bsq[NBLKMAX*64];
__device__ float g_bmax[NBLKMAX*64];
// stats slots: 0=hf, 1..4=branch outs, 5=pre, 6=y, 7=z, 8=xx, 9=final
__device__ float g_stats[10*128];
__device__ float g_ca[BATCH*64];

// ---------------- f32x2 helpers ---------------------------------------------
__device__ __forceinline__ unsigned long long pack2(float lo, float hi) {
    unsigned long long r;
    asm("mov.b64 %0, {%1, %2};" : "=l"(r) : "f"(lo), "f"(hi));
    return r;
}
__device__ __forceinline__ void fma2(unsigned long long& d,
                                     unsigned long long a, unsigned long long b) {
    asm("fma.rn.f32x2 %0, %1, %2, %0;" : "+l"(d) : "l"(a), "l"(b));
}
__device__ __forceinline__ float lo32(unsigned long long u) {
    return __uint_as_float((unsigned)u);
}
__device__ __forceinline__ float hi32(unsigned long long u) {
    return __uint_as_float((unsigned)(u >> 32));
}

// ---------------- BN finalize ------------------------------------------------
__global__ void bn_final_k(int nblk, int slot)
{
    int c = blockIdx.x, lane = threadIdx.x;
    float s = 0.f, q = 0.f;
    for (int j = lane; j < nblk; j += 32) {
        s += g_bsum[j * 64 + c];
        q += g_bsq[j * 64 + c];
    }
    #pragma unroll
    for (int d = 16; d > 0; d >>= 1) {
        s += __shfl_down_sync(0xffffffffu, s, d);
        q += __shfl_down_sync(0xffffffffu, q, d);
    }
    if (lane == 0) {
        float m = s / (float)NSTAT;
        float v = q / (float)NSTAT - m * m;
        g_stats[slot * 128 + c] = m;
        g_stats[slot * 128 + 64 + c] = rsqrtf(v + 1e-5f);
    }
}

// =============== smem-staged, double-buffered 3x3 conv, f32x2 =================
// Block: 256 threads -> 4 rows x 256 cols of output. Grid (64, BATCH, zsplit).
template<int CIN, int COUT, int DIL, bool BIAS, bool NORM, bool RELU, bool ADDEND, int STATS>
__global__ void __launch_bounds__(256, 2) conv3x3_s(
    const float* __restrict__ in, int inCt, int inCo,
    const float* __restrict__ stats,
    const float* __restrict__ w, int wCt, int wCo,
    const float* __restrict__ bias,
    const float* __restrict__ addend,
    float* __restrict__ out, int outCt)
{
    constexpr int CCH = (CIN < 16) ? CIN : 16;
    constexpr int COUTP = (COUT + 3) & ~3;
    constexpr int NP = COUTP / 2;
    constexpr int CPS = (DIL == 1) ? 2 : 1;   // channels per pipeline stage
    constexpr int ITR = 4 + 2 * DIL;
    constexpr int TS = 272;
    constexpr int TSZ = ITR * TS;
    constexpr int NST = CIN / CPS;
    __shared__ __align__(16) float tile[2][CPS][TSZ];
    __shared__ __align__(16) float ws[CCH * 9 * COUTP];
    __shared__ float reds[STATS ? COUT * 8 : 1];
    __shared__ float redq[STATS ? COUT * 8 : 1];
    __shared__ float redm[(STATS == 2) ? COUT * 8 : 1];

    const int tid = threadIdx.x;
    const int b = blockIdx.y;
    const int oc0 = blockIdx.z * COUT;
    const int y0 = blockIdx.x * 4;
    const int ry = tid >> 6;
    const int cg = (tid & 63) * 4;

    unsigned long long acc2[4][NP];
    {
        unsigned long long binit[NP];
        #pragma unroll
        for (int j = 0; j < NP; j++) {
            float b0 = (BIAS && 2*j     < COUT) ? __ldg(&bias[oc0 + 2*j])     : 0.f;
            float b1 = (BIAS && 2*j + 1 < COUT) ? __ldg(&bias[oc0 + 2*j + 1]) : 0.f;
            binit[j] = pack2(b0, b1);
        }
        #pragma unroll
        for (int p = 0; p < 4; p++)
            #pragma unroll
            for (int j = 0; j < NP; j++)
                acc2[p][j] = binit[j];
    }

    auto load_ws = [&](int c0) {
        for (int i = tid; i < CCH * 9 * COUTP; i += 256) {
            int o = i % COUTP;
            int rem = i / COUTP;
            int k = rem % 9;
            int cl = rem / 9;
            ws[i] = (o < COUT) ? w[((size_t)(oc0 + o) * wCt + wCo + c0 + cl) * 9 + k] : 0.f;
        }
    };
    auto load_stage = [&](int g, int buf) {
        #pragma unroll
        for (int cc = 0; cc < CPS; cc++) {
            int c = g * CPS + cc;
            const float* __restrict__ inp = in + (size_t)(b * inCt + inCo + c) * HW;
            float iv = 1.f, nm = 0.f;
            if (NORM) {
                float m = stats[c];
                iv = stats[64 + c];
                nm = -m * iv;
            }
            for (int i = tid; i < TSZ; i += 256) {
                int r = i / TS;
                int gx = i - r * TS - 4;
                int gy = y0 - DIL + r;
                float v = 0.f;
                if ((unsigned)gy < (unsigned)H && (unsigned)gx < (unsigned)W) {
                    v = inp[gy * W + gx];
                    if (NORM) v = fmaf(v, iv, nm);
                    if (RELU) v = fmaxf(v, 0.f);
                }
                tile[buf][cc][i] = v;
            }
        }
    };
    auto compute_stage = [&](int g, int buf) {
        #pragma unroll
        for (int cc = 0; cc < CPS; cc++) {
            int cl = (g * CPS + cc) % CCH;
            const float* tb0 = &tile[buf][cc][0];
            #pragma unroll
            for (int ky = 0; ky < 3; ky++) {
                const float* trow = tb0 + (ry + ky * DIL) * TS + cg;
                float4 ta = *(const float4*)(trow);
                float4 tb = *(const float4*)(trow + 4);
                float4 tc = *(const float4*)(trow + 8);
                float t[12] = {ta.x, ta.y, ta.z, ta.w,
                               tb.x, tb.y, tb.z, tb.w,
                               tc.x, tc.y, tc.z, tc.w};
                unsigned long long vp[12];
                #pragma unroll
                for (int j = 4 - DIL; j <= 7 + DIL; j++)
                    vp[j] = pack2(t[j], t[j]);
                #pragma unroll
                for (int kx = 0; kx < 3; kx++) {
                    const ulonglong2* wr =
                        (const ulonglong2*)&ws[(cl * 9 + ky * 3 + kx) * COUTP];
                    #pragma unroll
                    for (int q = 0; q < COUTP / 4; q++) {
                        ulonglong2 wp = wr[q];
                        #pragma unroll
                        for (int p = 0; p < 4; p++) {
                            fma2(acc2[p][2*q],   vp[4 + p + (kx-1)*DIL], wp.x);
                            fma2(acc2[p][2*q+1], vp[4 + p + (kx-1)*DIL], wp.y);
                        }
                    }
                }
            }
        }
    };

    // ---- software pipeline: load g+1 while computing g; 1 sync per stage ----
    load_ws(0);
    load_stage(0, 0);
    __syncthreads();
    for (int g = 0; g < NST; g++) {
        bool have_next = (g + 1 < NST);
        bool next_new_chunk = have_next && (((g + 1) * CPS) % CCH == 0);
        if (have_next && !next_new_chunk)
            load_stage(g + 1, (g + 1) & 1);
        compute_stage(g, g & 1);
        __syncthreads();
        if (next_new_chunk) {
            load_ws((g + 1) * CPS);
            load_stage(g + 1, (g + 1) & 1);
            __syncthreads();
        }
    }

    // ---- epilogue: unpack, addend, store, stats ----
    const int pixb = (y0 + ry) * W + cg;
    const int lane = tid & 31, wid = tid >> 5;
    #pragma unroll
    for (int o = 0; o < COUT; o++) {
        float a0 = (o & 1) ? hi32(acc2[0][o >> 1]) : lo32(acc2[0][o >> 1]);
        float a1 = (o & 1) ? hi32(acc2[1][o >> 1]) : lo32(acc2[1][o >> 1]);
        float a2 = (o & 1) ? hi32(acc2[2][o >> 1]) : lo32(acc2[2][o >> 1]);
        float a3 = (o & 1) ? hi32(acc2[3][o >> 1]) : lo32(acc2[3][o >> 1]);
        if (ADDEND) {
            float4 ad = *(const float4*)(addend + (size_t)(b * COUT + o) * HW + pixb);
            a0 += ad.x; a1 += ad.y; a2 += ad.z; a3 += ad.w;
        }
        float4 v = make_float4(a0, a1, a2, a3);
        *(float4*)(out + (size_t)(b * outCt + oc0 + o) * HW + pixb) = v;
        if constexpr (STATS > 0) {
            float s = a0 + a1 + a2 + a3;
            float q = a0*a0 + a1*a1 + a2*a2 + a3*a3;
            float mx = fmaxf(fmaxf(a0, a1), fmaxf(a2, a3));
            #pragma unroll
            for (int d = 16; d > 0; d >>= 1) {
                s += __shfl_down_sync(0xffffffffu, s, d);
                q += __shfl_down_sync(0xffffffffu, q, d);
                if (STATS == 2) mx = fmaxf(mx, __shfl_down_sync(0xffffffffu, mx, d));
            }
            if (lane == 0) {
                reds[o * 8 + wid] = s;
                redq[o * 8 + wid] = q;
                if (STATS == 2) redm[o * 8 + wid] = mx;
            }
        }
    }
    if constexpr (STATS > 0) {
        __syncthreads();
        if (tid < COUT) {
            float s = 0.f, q = 0.f, mx = -INFINITY;
            #pragma unroll
            for (int j = 0; j < 8; j++) {
                s += reds[tid * 8 + j];
                q += redq[tid * 8 + j];
                if (STATS == 2) mx = fmaxf(mx, redm[tid * 8 + j]);
            }
            int rowi = b * gridDim.x + blockIdx.x;
            g_bsum[rowi * 64 + oc0 + tid] = s;
            g_bsq[rowi * 64 + oc0 + tid] = q;
            if (STATS == 2) g_bmax[rowi * 64 + oc0 + tid] = mx;
        }
    }
}

// =============== conv2 (64->16) fused norm*ca*sg, double-buffered =============
__global__ void __launch_bounds__(256, 2) conv2_casg_s(
    const float* __restrict__ w, float* __restrict__ out)
{
    constexpr int TS = 272;
    constexpr int ITR = 6;
    constexpr int TSZ = ITR * TS;
    constexpr int CPS = 2;
    constexpr int NST = 64 / CPS;
    __shared__ __align__(16) float tile[2][CPS][TSZ];
    __shared__ __align__(16) float sgt[TSZ];
    __shared__ __align__(16) float ws[16 * 9 * 16];
    __shared__ float reds[16 * 8], redq[16 * 8];
    __shared__ float sc[64], sb[64];

    const int tid = threadIdx.x;
    const int b = blockIdx.y;
    const int y0 = blockIdx.x * 4;
    const int ry = tid >> 6;
    const int cg = (tid & 63) * 4;

    if (tid < 64) {
        float iv = g_stats[7 * 128 + 64 + tid], m = g_stats[7 * 128 + tid];
        float s = iv * g_ca[b * 64 + tid];
        sc[tid] = s; sb[tid] = -m * s;
    }
    {
        const float* sgp = g_sg + (size_t)b * HW;
        for (int i = tid; i < TSZ; i += 256) {
            int r = i / TS;
            int gx = i - r * TS - 4;
            int gy = y0 - 1 + r;
            sgt[i] = ((unsigned)gy < (unsigned)H && (unsigned)gx < (unsigned)W)
                     ? sgp[gy * W + gx] : 0.f;
        }
    }

    unsigned long long acc2[4][8];
    #pragma unroll
    for (int p = 0; p < 4; p++)
        #pragma unroll
        for (int j = 0; j < 8; j++) acc2[p][j] = 0ull;

    auto load_ws = [&](int c0) {
        for (int i = tid; i < 16 * 9 * 16; i += 256) {
            int o = i & 15;
            int rem = i >> 4;
            int k = rem % 9;
            int cl = rem / 9;
            ws[i] = w[((size_t)o * 64 + c0 + cl) * 9 + k];
        }
    };
    auto load_stage = [&](int g, int buf) {
        #pragma unroll
        for (int cc = 0; cc < CPS; cc++) {
            int c = g * CPS + cc;
            const float* __restrict__ inp = g_z + (size_t)(b * 64 + c) * HW;
            float scc = sc[c], bcc = sb[c];
            for (int i = tid; i < TSZ; i += 256) {
                int r = i / TS;
                int gx = i - r * TS - 4;
                int gy = y0 - 1 + r;
                float v = 0.f;
                if ((unsigned)gy < (unsigned)H && (unsigned)gx < (unsigned)W)
                    v = fmaf(inp[gy * W + gx], scc, bcc) * sgt[i];
                tile[buf][cc][i] = v;
            }
        }
    };
    auto compute_stage = [&](int g, int buf) {
        #pragma unroll
        for (int cc = 0; cc < CPS; cc++) {
            int cl = (g * CPS + cc) & 15;
            const float* tb0 = &tile[buf][cc][0];
            #pragma unroll
            for (int ky = 0; ky < 3; ky++) {
                const float* trow = tb0 + (ry + ky) * TS + cg;
                float4 ta = *(const float4*)(trow);
                float4 tb = *(const float4*)(trow + 4);
                float4 tc = *(const float4*)(trow + 8);
                float t[12] = {ta.x, ta.y, ta.z, ta.w,
                               tb.x, tb.y, tb.z, tb.w,
                               tc.x, tc.y, tc.z, tc.w};
                unsigned long long vp[12];
                #pragma unroll
                for (int j = 3; j <= 8; j++) vp[j] = pack2(t[j], t[j]);
                #pragma unroll
                for (int kx = 0; kx < 3; kx++) {
                    const ulonglong2* wr = (const ulonglong2*)&ws[(cl*9 + ky*3 + kx) * 16];
                    #pragma unroll
                    for (int q = 0; q < 4; q++) {
                        ulonglong2 wp = wr[q];
                        #pragma unroll
                        for (int p = 0; p < 4; p++) {
                            fma2(acc2[p][2*q],   vp[4 + p + (kx-1)], wp.x);
                            fma2(acc2[p][2*q+1], vp[4 + p + (kx-1)], wp.y);
                        }
                    }
                }
            }
        }
    };

    load_ws(0);
    __syncthreads();     // sc/sb + sgt ready (used by load_stage)
    load_stage(0, 0);
    __syncthreads();
    for (int g = 0; g < NST; g++) {
        bool have_next = (g + 1 < NST);
        bool next_new_chunk = have_next && (((g + 1) * CPS) & 15) == 0;
        if (have_next && !next_new_chunk)
            load_stage(g + 1, (g + 1) & 1);
        compute_stage(g, g & 1);
        __syncthreads();
        if (next_new_chunk) {
            load_ws((g + 1) * CPS);
            load_stage(g + 1, (g + 1) & 1);
            __syncthreads();
        }
    }

    const int pixb = (y0 + ry) * W + cg;
    const int lane = tid & 31, wid = tid >> 5;
    #pragma unroll
    for (int o = 0; o < 16; o++) {
        float a0 = (o & 1) ? hi32(acc2[0][o >> 1]) : lo32(acc2[0][o >> 1]);
        float a1 = (o & 1) ? hi32(acc2[1][o >> 1]) : lo32(acc2[1][o >> 1]);
        float a2 = (o & 1) ? hi32(acc2[2][o >> 1]) : lo32(acc2[2][o >> 1]);
        float a3 = (o & 1) ? hi32(acc2[3][o >> 1]) : lo32(acc2[3][o >> 1]);
        *(float4*)(out + (size_t)(b * 16 + o) * HW + pixb) = make_float4(a0, a1, a2, a3);
        float s = a0 + a1 + a2 + a3;
        float q = a0*a0 + a1*a1 + a2*a2 + a3*a3;
        #pragma unroll
        for (int d = 16; d > 0; d >>= 1) {
            s += __shfl_down_sync(0xffffffffu, s, d);
            q += __shfl_down_sync(0xffffffffu, q, d);
        }
        if (lane == 0) { reds[o * 8 + wid] = s; redq[o * 8 + wid] = q; }
    }
    __syncthreads();
    if (tid < 16) {
        float s = 0.f, q = 0.f;
        #pragma unroll
        for (int j = 0; j < 8; j++) { s += reds[tid*8+j]; q += redq[tid*8+j]; }
        int rowi = b * gridDim.x + blockIdx.x;
        g_bsum[rowi * 64 + tid] = s;
        g_bsq[rowi * 64 + tid] = q;
    }
}

// ---------------- 1x1 convs, 4 pixels/thread (coalesced float4) --------------
__global__ void __launch_bounds__(128) conv1x1_64_16_p4(
    const float* __restrict__ in, const float* __restrict__ w,
    const float* __restrict__ bias, float* __restrict__ out)
{
    __shared__ __align__(16) float ws[64*16];
    __shared__ float reds[16*4], redq[16*4];
    int tid = threadIdx.x;
    for (int i = tid; i < 64*16; i += 128) {
        int o = i & 15, c = i >> 4;
        ws[i] = w[o * 64 + c];
    }
    __syncthreads();
    int p4 = blockIdx.x * 128 + tid;
    int b = blockIdx.y;
    const float4* inb = (const float4*)(in + (size_t)b * 64 * HW) + p4;
    unsigned long long acc2[4][8];
    #pragma unroll
    for (int j = 0; j < 8; j++) {
        unsigned long long bv = pack2(__ldg(&bias[2*j]), __ldg(&bias[2*j+1]));
        acc2[0][j] = bv; acc2[1][j] = bv; acc2[2][j] = bv; acc2[3][j] = bv;
    }
    #pragma unroll 1
    for (int c = 0; c < 64; c++) {
        float4 v = inb[(size_t)c * (HW / 4)];
        unsigned long long v0 = pack2(v.x, v.x), v1 = pack2(v.y, v.y);
        unsigned long long v2 = pack2(v.z, v.z), v3 = pack2(v.w, v.w);
        const ulonglong2* wr = (const ulonglong2*)&ws[c * 16];
        #pragma unroll
        for (int q = 0; q < 4; q++) {
            ulonglong2 wp = wr[q];
            fma2(acc2[0][2*q], v0, wp.x); fma2(acc2[0][2*q+1], v0, wp.y);
            fma2(acc2[1][2*q], v1, wp.x); fma2(acc2[1][2*q+1], v1, wp.y);
            fma2(acc2[2][2*q], v2, wp.x); fma2(acc2[2][2*q+1], v2, wp.y);
            fma2(acc2[3][2*q], v3, wp.x); fma2(acc2[3][2*q+1], v3, wp.y);
        }
    }
    int lane = tid & 31, wid = tid >> 5;
    #pragma unroll
    for (int o = 0; o < 16; o++) {
        float a0 = (o&1) ? hi32(acc2[0][o>>1]) : lo32(acc2[0][o>>1]);
        float a1 = (o&1) ? hi32(acc2[1][o>>1]) : lo32(acc2[1][o>>1]);
        float a2 = (o&1) ? hi32(acc2[2][o>>1]) : lo32(acc2[2][o>>1]);
        float a3 = (o&1) ? hi32(acc2[3][o>>1]) : lo32(acc2[3][o>>1]);
        ((float4*)out)[(size_t)(b * 16 + o) * (HW / 4) + p4] = make_float4(a0,a1,a2,a3);
        float s = a0+a1+a2+a3;
        float q = a0*a0+a1*a1+a2*a2+a3*a3;
        #pragma unroll
        for (int d = 16; d > 0; d >>= 1) {
            s += __shfl_down_sync(0xffffffffu, s, d);
            q += __shfl_down_sync(0xffffffffu, q, d);
        }
        if (lane == 0) { reds[o*4+wid] = s; redq[o*4+wid] = q; }
    }
    __syncthreads();
    if (tid < 16) {
        float s = 0.f, q = 0.f;
        #pragma unroll
        for (int j = 0; j < 4; j++) { s += reds[tid*4+j]; q += redq[tid*4+j]; }
        int rowi = b * gridDim.x + blockIdx.x;
        g_bsum[rowi * 64 + tid] = s;
        g_bsq[rowi * 64 + tid] = q;
    }
}

// 64->64 1x1 over normalized cat4; split 4 x 16 outputs; 4 px/thread
__global__ void __launch_bounds__(128) conv1x1_cat4_p4(
    const float* __restrict__ xb, const float* __restrict__ w,
    const float* __restrict__ bias, float* __restrict__ out)
{
    __shared__ __align__(16) float ws[64*16];
    __shared__ float siv[64], snm[64];
    __shared__ float reds[16*4], redq[16*4];
    int tid = threadIdx.x;
    int oc0 = blockIdx.z * 16;
    if (tid < 64) {
        int s = tid >> 4, c = tid & 15;
        float m = g_stats[(1 + s) * 128 + c];
        float iv = g_stats[(1 + s) * 128 + 64 + c];
        siv[tid] = iv; snm[tid] = -m * iv;
    }
    for (int i = tid; i < 64*16; i += 128) {
        int o = i & 15, c = i >> 4;
        ws[i] = w[(oc0 + o) * 64 + c];
    }
    __syncthreads();
    int p4 = blockIdx.x * 128 + tid;
    int b = blockIdx.y;
    unsigned long long acc2[4][8];
    #pragma unroll
    for (int j = 0; j < 8; j++) {
        unsigned long long bv = pack2(__ldg(&bias[oc0+2*j]), __ldg(&bias[oc0+2*j+1]));
        acc2[0][j] = bv; acc2[1][j] = bv; acc2[2][j] = bv; acc2[3][j] = bv;
    }
    #pragma unroll 1
    for (int c = 0; c < 64; c++) {
        const float* src = xb + (size_t)(c >> 4) * SZ16 + (size_t)(b * 16 + (c & 15)) * HW;
        float4 v = ((const float4*)src)[p4];
        float ivc = siv[c], nmc = snm[c];
        v.x = fmaf(v.x, ivc, nmc); v.y = fmaf(v.y, ivc, nmc);
        v.z = fmaf(v.z, ivc, nmc); v.w = fmaf(v.w, ivc, nmc);
        unsigned long long v0 = pack2(v.x, v.x), v1 = pack2(v.y, v.y);
        unsigned long long v2 = pack2(v.z, v.z), v3 = pack2(v.w, v.w);
        const ulonglong2* wr = (const ulonglong2*)&ws[c * 16];
        #pragma unroll
        for (int q = 0; q < 4; q++) {
            ulonglong2 wp = wr[q];
            fma2(acc2[0][2*q], v0, wp.x); fma2(acc2[0][2*q+1], v0, wp.y);
            fma2(acc2[1][2*q], v1, wp.x); fma2(acc2[1][2*q+1], v1, wp.y);
            fma2(acc2[2][2*q], v2, wp.x); fma2(acc2[2][2*q+1], v2, wp.y);
            fma2(acc2[3][2*q], v3, wp.x); fma2(acc2[3][2*q+1], v3, wp.y);
        }
    }
    int lane = tid & 31, wid = tid >> 5;
    #pragma unroll
    for (int o = 0; o < 16; o++) {
        float a0 = (o&1) ? hi32(acc2[0][o>>1]) : lo32(acc2[0][o>>1]);
        float a1 = (o&1) ? hi32(acc2[1][o>>1]) : lo32(acc2[1][o>>1]);
        float a2 = (o&1) ? hi32(acc2[2][o>>1]) : lo32(acc2[2][o>>1]);
        float a3 = (o&1) ? hi32(acc2[3][o>>1]) : lo32(acc2[3][o>>1]);
        ((float4*)out)[(size_t)(b * 64 + oc0 + o) * (HW / 4) + p4] = make_float4(a0,a1,a2,a3);
        float s = a0+a1+a2+a3;
        float q = a0*a0+a1*a1+a2*a2+a3*a3;
        #pragma unroll
        for (int d = 16; d > 0; d >>= 1) {
            s += __shfl_down_sync(0xffffffffu, s, d);
            q += __shfl_down_sync(0xffffffffu, q, d);
        }
        if (lane == 0) { reds[o*4+wid] = s; redq[o*4+wid] = q; }
    }
    __syncthreads();
    if (tid < 16) {
        float s = 0.f, q = 0.f;
        #pragma unroll
        for (int j = 0; j < 4; j++) { s += reds[tid*4+j]; q += redq[tid*4+j]; }
        int rowi = b * gridDim.x + blockIdx.x;
        g_bsum[rowi * 64 + oc0 + tid] = s;
        g_bsq[rowi * 64 + oc0 + tid] = q;
    }
}

// ---------------- t materialization (float4) ----------------------------------
__global__ void norm_t_k(const float* __restrict__ pre,
                         const float* __restrict__ add1, const float* __restrict__ st1,
                         const float* __restrict__ lfsrc, int lfco)
{
    int i4 = blockIdx.x * 256 + threadIdx.x;
    int idx = i4 * 4;
    int pix = idx & (HW - 1);
    int rest = idx >> 16;
    int c = rest & 15, b = rest >> 4;
    float m = g_stats[5 * 128 + c], iv = g_stats[5 * 128 + 64 + c];
    float nm = -m * iv;
    float4 v = ((const float4*)pre)[i4];
    v.x = fmaf(v.x, iv, nm); v.y = fmaf(v.y, iv, nm);
    v.z = fmaf(v.z, iv, nm); v.w = fmaf(v.w, iv, nm);
    if (add1) {
        float4 a = ((const float4*)add1)[i4];
        if (st1) {
            float m1 = st1[c], i1 = st1[64 + c], n1 = -m1 * i1;
            a.x = fmaf(a.x, i1, n1); a.y = fmaf(a.y, i1, n1);
            a.z = fmaf(a.z, i1, n1); a.w = fmaf(a.w, i1, n1);
        }
        v.x += a.x; v.y += a.y; v.z += a.z; v.w += a.w;
    }
    if (lfsrc) {
        float4 l = *(const float4*)(lfsrc + (size_t)(b * 64 + lfco + c) * HW + pix);
        v.x += l.x; v.y += l.y; v.z += l.z; v.w += l.w;
    }
    ((float4*)g_t)[i4] = v;
}

// ---------------- deformable conv (exact reference semantics, f32x2) ----------
__global__ void __launch_bounds__(256) deform_k(
    const float* __restrict__ t, const float* __restrict__ off,
    const float* __restrict__ wd, float* __restrict__ out)
{
    __shared__ __align__(16) float ws[16*16*9];
    for (int i = threadIdx.x; i < 2304; i += blockDim.x) {
        int o = i & 15;
        int rem = i >> 4;
        int n = rem % 9;
        int c = rem / 9;
        ws[i] = wd[(o * 16 + c) * 9 + n];
    }
    __syncthreads();
    int pix = blockIdx.x * blockDim.x + threadIdx.x;
    int b = blockIdx.y;
    int yi = pix >> 8, xj = pix & 255;

    unsigned long long acc2[8];
    #pragma unroll
    for (int j = 0; j < 8; j++) acc2[j] = 0ull;

    const float* offb = off + (size_t)b * 18 * HW + pix;
    const float* tb = t + (size_t)b * 16 * HW;

    #pragma unroll 1
    for (int n = 0; n < 9; n++) {
        int dx = n / 3 - 1, dy = n % 3 - 1;
        float ox = offb[(size_t)(2 * n) * HW];
        float oy = offb[(size_t)(2 * n + 1) * HW];
        float plx = (float)(yi + 1 + dx) + ox;
        float ply = (float)(xj + 1 + dy) + oy;
        float flx = floorf(plx), fly = floorf(ply);
        int qltx = min(max((int)flx, 0), 257);
        int qlty = min(max((int)fly, 0), 257);
        int qrbx = min(max((int)flx + 1, 0), 257);
        int qrby = min(max((int)fly + 1, 0), 257);
        bool mx = (plx < 1.0f) || (plx > 256.0f);
        bool my = (ply < 1.0f) || (ply > 256.0f);
        float px = mx ? flx : plx; px = fminf(fmaxf(px, 0.f), 257.f);
        float py = my ? fly : ply; py = fminf(fmaxf(py, 0.f), 257.f);
        float wltx = 1.f + ((float)qltx - px);
        float wrbx = 1.f - ((float)qrbx - px);
        float wlty = 1.f + ((float)qlty - py);
        float wrby = 1.f - ((float)qrby - py);
        float glt = wltx * wlty, grb = wrbx * wrby;
        float glb = wltx * wrby, grt = wrbx * wlty;
        bool vltx = (qltx >= 1 && qltx <= 256);
        bool vlty = (qlty >= 1 && qlty <= 256);
        bool vrbx = (qrbx >= 1 && qrbx <= 256);
        bool vrby = (qrby >= 1 && qrby <= 256);
        int rlt = (qltx - 1) * W + (qlty - 1);
        int rrb = (qrbx - 1) * W + (qrby - 1);
        int rlb = (qltx - 1) * W + (qrby - 1);
        int rrt = (qrbx - 1) * W + (qlty - 1);
        #pragma unroll 4
        for (int c = 0; c < 16; c++) {
            const float* tc = tb + (size_t)c * HW;
            float vlt = (vltx && vlty) ? tc[rlt] : 0.f;
            float vrb = (vrbx && vrby) ? tc[rrb] : 0.f;
            float vlb = (vltx && vrby) ? tc[rlb] : 0.f;
            float vrt = (vrbx && vlty) ? tc[rrt] : 0.f;
            float val = glt * vlt + grb * vrb + glb * vlb + grt * vrt;
            unsigned long long vp = pack2(val, val);
            const ulonglong2* wr = (const ulonglong2*)&ws[(c * 9 + n) * 16];
            #pragma unroll
            for (int q = 0; q < 4; q++) {
                ulonglong2 wp = wr[q];
                fma2(acc2[2*q],   vp, wp.x);
                fma2(acc2[2*q+1], vp, wp.y);
            }
        }
    }
    #pragma unroll
    for (int o = 0; o < 16; o++) {
        float v = (o & 1) ? hi32(acc2[o >> 1]) : lo32(acc2[o >> 1]);
        out[(size_t)(b * 16 + o) * HW + pix] = v;
    }
}

// ---------------- CBAM ----------------------------------------------------------
__global__ void cbam_final_k(int gridX, const float* __restrict__ w1,
                             const float* __restrict__ w2)
{
    int t = threadIdx.x;
    int b = t >> 6, c = t & 63;
    float s = 0.f, q = 0.f, mx = -INFINITY;
    for (int j = 0; j < gridX; j++) {
        int idx = (b * gridX + j) * 64 + c;
        s += g_bsum[idx]; q += g_bsq[idx]; mx = fmaxf(mx, g_bmax[idx]);
    }
    __shared__ float sh_s[4][64], sh_q[4][64], sh_m[4][64];
    sh_s[b][c] = s; sh_q[b][c] = q; sh_m[b][c] = mx;
    __syncthreads();
    __shared__ float sm[64], si[64];
    if (t < 64) {
        float ts = 0.f, tq = 0.f;
        #pragma unroll
        for (int bb = 0; bb < 4; bb++) { ts += sh_s[bb][t]; tq += sh_q[bb][t]; }
        float m = ts / (float)NSTAT;
        float v = tq / (float)NSTAT - m * m;
        float iv = rsqrtf(v + 1e-5f);
        g_stats[7 * 128 + t] = m;
        g_stats[7 * 128 + 64 + t] = iv;
        sm[t] = m; si[t] = iv;
    }
    __syncthreads();
    __shared__ float av[4][64], xmv[4][64];
    av[b][c]  = (sh_s[b][c] / (float)HW - sm[c]) * si[c];
    xmv[b][c] = (sh_m[b][c] - sm[c]) * si[c];
    __syncthreads();
    __shared__ float hid[4][4][2];
    if (t < 32) {
        int bb = t >> 3, h = (t >> 1) & 3, which = t & 1;
        float acc = 0.f;
        for (int cc = 0; cc < 64; cc++)
            acc += w1[h * 64 + cc] * (which ? xmv[bb][cc] : av[bb][cc]);
        hid[bb][h][which] = fmaxf(acc, 0.f);
    }
    __syncthreads();
    {
        float va = 0.f, vm = 0.f;
        #pragma unroll
        for (int h = 0; h < 4; h++) {
            float wv = w2[c * 4 + h];
            va = fmaf(wv, hid[b][h][0], va);
            vm = fmaf(wv, hid[b][h][1], vm);
        }
        g_ca[b * 64 + c] = 1.f / (1.f + expf(-(va + vm)));
    }
}

// sp (mean,max over channels of (z norm * ca)), float4 over pixels
__global__ void apply1_k()
{
    __shared__ float sc[64], sb[64];
    int b = blockIdx.y;
    if (threadIdx.x < 64) {
        int c = threadIdx.x;
        float iv = g_stats[7 * 128 + 64 + c], m = g_stats[7 * 128 + c];
        float s = iv * g_ca[b * 64 + c];
        sc[c] = s; sb[c] = -m * s;
    }
    __syncthreads();
    int p4 = blockIdx.x * 256 + threadIdx.x;
    const float4* zp = (const float4*)(g_z + (size_t)b * 64 * HW) + p4;
    float4 smv = make_float4(0.f, 0.f, 0.f, 0.f);
    float4 mxv = make_float4(-INFINITY, -INFINITY, -INFINITY, -INFINITY);
    #pragma unroll 1
    for (int c = 0; c < 64; c++) {
        float4 v = zp[(size_t)c * (HW / 4)];
        float s = sc[c], bb = sb[c];
        v.x = fmaf(v.x, s, bb); v.y = fmaf(v.y, s, bb);
        v.z = fmaf(v.z, s, bb); v.w = fmaf(v.w, s, bb);
        smv.x += v.x; smv.y += v.y; smv.z += v.z; smv.w += v.w;
        mxv.x = fmaxf(mxv.x, v.x); mxv.y = fmaxf(mxv.y, v.y);
        mxv.z = fmaxf(mxv.z, v.z); mxv.w = fmaxf(mxv.w, v.w);
    }
    const float k = 1.f / 64.f;
    smv.x *= k; smv.y *= k; smv.z *= k; smv.w *= k;
    ((float4*)(g_sp + (size_t)(b * 2) * HW))[p4] = smv;
    ((float4*)(g_sp + (size_t)(b * 2 + 1) * HW))[p4] = mxv;
}

// sg = sigmoid(conv7x7(sp))
__global__ void apply2_k(const float* __restrict__ wsp)
{
    __shared__ float w[98];
    if (threadIdx.x < 98) w[threadIdx.x] = wsp[threadIdx.x];
    __syncthreads();
    int pix = blockIdx.x * 256 + threadIdx.x;
    int b = blockIdx.y;
    int y = pix >> 8, x = pix & 255;
    const float* s0 = g_sp + (size_t)(b * 2) * HW;
    const float* s1 = s0 + HW;
    float acc = 0.f;
    #pragma unroll 1
    for (int ky = 0; ky < 7; ky++) {
        int yy = y + ky - 3;
        if ((unsigned)yy >= (unsigned)H) continue;
        #pragma unroll
        for (int kx = 0; kx < 7; kx++) {
            int xx = x + kx - 3;
            if ((unsigned)xx >= (unsigned)W) continue;
            int ip = yy * W + xx;
            acc += w[ky * 7 + kx] * s0[ip] + w[49 + ky * 7 + kx] * s1[ip];
        }
    }
    g_sg[(size_t)b * HW + pix] = 1.f / (1.f + expf(-acc));
}

// ---------------- final elementwise ----------------------------------------------
__global__ void norm_s_k(const float* __restrict__ xx, const float* __restrict__ lf)
{
    int i4 = blockIdx.x * 256 + threadIdx.x;
    int idx = i4 * 4;
    int c = (idx >> 16) & 63;
    float m = g_stats[8 * 128 + c], iv = g_stats[8 * 128 + 64 + c];
    float nm = -m * iv;
    float4 v = ((const float4*)xx)[i4];
    float4 l = ((const float4*)lf)[i4];
    v.x = fmaxf(fmaf(v.x, iv, nm), 0.f) + l.x;
    v.y = fmaxf(fmaf(v.y, iv, nm), 0.f) + l.y;
    v.z = fmaxf(fmaf(v.z, iv, nm), 0.f) + l.z;
    v.w = fmaxf(fmaf(v.w, iv, nm), 0.f) + l.w;
    ((float4*)g_s)[i4] = v;
}

__global__ void norm_out_k(float* __restrict__ o)
{
    int i4 = blockIdx.x * 256 + threadIdx.x;
    int idx = i4 * 4;
    int c = (idx >> 16) & 63;
    float m = g_stats[9 * 128 + c], iv = g_stats[9 * 128 + 64 + c];
    float nm = -m * iv;
    float4 v = ((float4*)o)[i4];
    v.x = fmaf(v.x, iv, nm); v.y = fmaf(v.y, iv, nm);
    v.z = fmaf(v.z, iv, nm); v.w = fmaf(v.w, iv, nm);
    ((float4*)o)[i4] = v;
}

// ---------------- host orchestration ----------------------------------------------
extern "C" void kernel_launch(void* const* d_in, const int* in_sizes, int n_in,
                              void* d_out, int out_size)
{
    const float* lf   = (const float*)d_in[0];
    const float* hf   = (const float*)d_in[1];
    const float* w11  = (const float*)d_in[2];
    const float* b11  = (const float*)d_in[3];
    const float* wconv= (const float*)d_in[4];
    const float* woff = (const float*)d_in[5];
    const float* boff = (const float*)d_in[6];
    const float* wdef = (const float*)d_in[7];
    const float* wdil[4] = {(const float*)d_in[8], (const float*)d_in[9],
                            (const float*)d_in[10], (const float*)d_in[11]};
    const float* wc1  = (const float*)d_in[12];
    const float* wc2  = (const float*)d_in[13];
    const float* wfc1 = (const float*)d_in[14];
    const float* wfc2 = (const float*)d_in[15];
    const float* wsp  = (const float*)d_in[16];
    const float* wc12 = (const float*)d_in[17];
    const float* bc12 = (const float*)d_in[18];
    const float* wc33 = (const float*)d_in[19];
    float* out = (float*)d_out;

    void* tmp;
#define GETP(name, sym) cudaGetSymbolAddress(&tmp, sym); float* name = (float*)tmp;
    GETP(p_hfpre, g_hfpre) GETP(p_prehf, g_prehf) GETP(p_pre, g_pre)
    GETP(p_t, g_t)         GETP(p_off, g_off)     GETP(p_d16, g_d16)
    GETP(p_y, g_y)         GETP(p_z, g_z)         GETP(p_s, g_s)
    GETP(p_xb, g_xb)       GETP(p_stats, g_stats)
#undef GETP

    const dim3 CS(64, BATCH);            // staged convs: 256 blocks of 256 thr
    const dim3 CSz2(64, BATCH, 2);
    const dim3 CSz4(64, BATCH, 4);
    const dim3 P4(128, BATCH);           // 1x1 p4 kernels
    const dim3 P4z4(128, BATCH, 4);
    const dim3 PGo(256, BATCH);

    // Stage A: hf_pre = conv1x1(hf)+bias; stats slot0
    conv1x1_64_16_p4<<<P4, 128>>>(hf, w11, b11, p_hfpre);
    bn_final_k<<<16, 32>>>(512, 0);

    // Shared hf-part: conv3x3(relu(bn(hf_pre)), wconv[:,16:32])
    conv3x3_s<16,16,1,false,true,true,false,0><<<CS, 256>>>(
        p_hfpre, 16, 0, p_stats + 0*128, wconv, 32, 16, nullptr, nullptr,
        p_prehf, 16);

    for (int k = 0; k < 4; k++) {
        // pre = conv3x3(prev_norm, wconv[:,0:16]) + prehf ; stats slot5
        if (k == 0)
            conv3x3_s<16,16,1,false,false,false,true,1><<<CS, 256>>>(
                lf, 64, 0, nullptr, wconv, 32, 0, nullptr, p_prehf, p_pre, 16);
        else
            conv3x3_s<16,16,1,false,true,false,true,1><<<CS, 256>>>(
                p_xb + (size_t)(k-1) * SZ16, 16, 0, p_stats + k*128,
                wconv, 32, 0, nullptr, p_prehf, p_pre, 16);
        bn_final_k<<<16, 32>>>(256, 5);

        // t = bn(pre) + extras
        const float* add1 = (k >= 1) ? p_xb + (size_t)(k-1) * SZ16 : nullptr;
        const float* st1  = (k >= 1) ? p_stats + k*128 : nullptr;
        const float* lfa  = (k <= 2) ? lf : nullptr;
        int lfco = (k == 0) ? 16 : (k == 1) ? 32 : 48;
        norm_t_k<<<SZ16 / 1024, 256>>>(p_pre, add1, st1, lfa, lfco);

        // offsets (COUT 18 as 2x9) + deformable conv
        conv3x3_s<16,9,1,true,false,false,false,0><<<CSz2, 256>>>(
            p_t, 16, 0, nullptr, woff, 16, 0, boff, nullptr, p_off, 18);
        deform_k<<<PGo, 256>>>(p_t, p_off, wdef, p_d16);

        // dilated conv ; stats slot6
        switch (k) {
        case 0: conv3x3_s<16,16,1,false,false,false,false,1><<<CS, 256>>>(
                    p_d16, 16, 0, nullptr, wdil[0], 16, 0, nullptr, nullptr, p_y, 16); break;
        case 1: conv3x3_s<16,16,2,false,false,false,false,1><<<CS, 256>>>(
                    p_d16, 16, 0, nullptr, wdil[1], 16, 0, nullptr, nullptr, p_y, 16); break;
        case 2: conv3x3_s<16,16,3,false,false,false,false,1><<<CS, 256>>>(
                    p_d16, 16, 0, nullptr, wdil[2], 16, 0, nullptr, nullptr, p_y, 16); break;
        default: conv3x3_s<16,16,4,false,false,false,false,1><<<CS, 256>>>(
                    p_d16, 16, 0, nullptr, wdil[3], 16, 0, nullptr, nullptr, p_y, 16); break;
        }
        bn_final_k<<<16, 32>>>(256, 6);

        // z = conv3x3(bn(y), wc1) 16->64 split 4x16 ; stats+max slot7 partials
        conv3x3_s<16,16,1,false,true,false,false,2><<<CSz4, 256>>>(
            p_y, 16, 0, p_stats + 6*128, wc1, 16, 0, nullptr, nullptr, p_z, 64);
        cbam_final_k<<<1, 256>>>(64, wfc1, wfc2);

        // spatial attention
        apply1_k<<<dim3(64, BATCH), 256>>>();
        apply2_k<<<PGo, 256>>>(wsp);

        // branch output: conv2 with fused norm*ca*sg on load ; stats slot 1+k
        conv2_casg_s<<<CS, 256>>>(wc2, p_xb + (size_t)k * SZ16);
        bn_final_k<<<16, 32>>>(256, 1 + k);
    }

    // xx_pre = conv1x1(cat4_normalized)+bias ; stats slot8
    conv1x1_cat4_p4<<<P4z4, 128>>>(p_xb, wc12, bc12, p_z);
    bn_final_k<<<64, 32>>>(512, 8);
    // s = lf + relu(bn(xx_pre))
    norm_s_k<<<SZ64 / 1024, 256>>>(p_z, lf);

    // out_pre = conv3x3(s, wc33) 64->64 split 4x16 ; stats slot9 ; normalize
    conv3x3_s<64,16,1,false,false,false,false,1><<<CSz4, 256>>>(
        p_s, 64, 0, nullptr, wc33, 64, 0, nullptr, nullptr, out, 64);
    bn_final_k<<<64, 32>>>(256, 9);
    norm_out_k<<<SZ64 / 1024, 256>>>(out);
}

// round 7
// speedup vs baseline: 2.6459x; 1.3560x over previous
#include <cuda_runtime.h>
#include <math.h>

#define H 256
#define W 256
#define HW 65536
#define BATCH 4
#define NSTAT (BATCH*HW)
#define NBLKMAX 1024

#define SZ16 (BATCH*16*HW)
#define SZ18 (BATCH*18*HW)
#define SZ64 (BATCH*64*HW)

// ---------------- scratch (static device globals; no allocations) ----------
__device__ __align__(16) float g_hfpre[SZ16];
__device__ __align__(16) float g_prehf[SZ16];
__device__ __align__(16) float g_pre[SZ16];
__device__ __align__(16) float g_t[SZ16];
__device__ __align__(16) float g_off[SZ18];
__device__ __align__(16) float g_d16[SZ16];
__device__ __align__(16) float g_y[SZ16];
__device__ __align__(16) float g_z[SZ64];
__device__ __align__(16) float g_s[SZ64];
__device__ __align__(16) float g_sp[BATCH*2*HW];
__device__ __align__(16) float g_sg[BATCH*HW];
__device__ __align__(16) float g_xb[4*SZ16];
__device__ float g_bsum[NBLKMAX*64];
__device__ float g_bsq[NBLKMAX*64];
__device__ float g_bmax[NBLKMAX*64];
// stats slots: 0=hf, 1..4=branch outs, 5=pre, 6=y, 7=z, 8=xx, 9=final
__device__ float g_stats[10*128];
__device__ float g_ca[BATCH*64];

// ---------------- f32x2 / cp.async helpers -----------------------------------
__device__ __forceinline__ unsigned long long pack2(float lo, float hi) {
    unsigned long long r;
    asm("mov.b64 %0, {%1, %2};" : "=l"(r) : "f"(lo), "f"(hi));
    return r;
}
__device__ __forceinline__ void fma2(unsigned long long& d,
                                     unsigned long long a, unsigned long long b) {
    asm("fma.rn.f32x2 %0, %1, %2, %0;" : "+l"(d) : "l"(a), "l"(b));
}
__device__ __forceinline__ float lo32(unsigned long long u) {
    return __uint_as_float((unsigned)u);
}
__device__ __forceinline__ float hi32(unsigned long long u) {
    return __uint_as_float((unsigned)(u >> 32));
}
__device__ __forceinline__ unsigned smem_u32(const void* p) {
    unsigned a;
    asm("{ .reg .u64 t; cvta.to.shared.u64 t, %1; cvt.u32.u64 %0, t; }"
        : "=r"(a) : "l"(p));
    return a;
}
#define CP_ASYNC16(sa, gp, ss) \
    asm volatile("cp.async.ca.shared.global [%0], [%1], 16, %2;" \
                 :: "r"(sa), "l"(gp), "r"(ss))
#define CP_COMMIT() asm volatile("cp.async.commit_group;" ::: "memory")
#define CP_WAIT1()  asm volatile("cp.async.wait_group 1;" ::: "memory")
#define CP_WAIT0()  asm volatile("cp.async.wait_group 0;" ::: "memory")

// ---------------- BN finalize ------------------------------------------------
__global__ void bn_final_k(int nblk, int slot)
{
    int c = blockIdx.x, lane = threadIdx.x;
    float s = 0.f, q = 0.f;
    for (int j = lane; j < nblk; j += 32) {
        s += g_bsum[j * 64 + c];
        q += g_bsq[j * 64 + c];
    }
    #pragma unroll
    for (int d = 16; d > 0; d >>= 1) {
        s += __shfl_down_sync(0xffffffffu, s, d);
        q += __shfl_down_sync(0xffffffffu, q, d);
    }
    if (lane == 0) {
        float m = s / (float)NSTAT;
        float v = q / (float)NSTAT - m * m;
        g_stats[slot * 128 + c] = m;
        g_stats[slot * 128 + 64 + c] = rsqrtf(v + 1e-5f);
    }
}

// =============== cp.async-staged 3x3 conv, f32x2, consume-side norm ===========
// Block: 256 threads -> 4 rows x 256 cols of output. Grid (64, BATCH, zsplit).
template<int CIN, int COUT, int DIL, bool BIAS, bool NORM, bool RELU, bool ADDEND, int STATS>
__global__ void __launch_bounds__(256, 2) conv3x3_s(
    const float* __restrict__ in, int inCt, int inCo,
    const float* __restrict__ stats,
    const float* __restrict__ w, int wCt, int wCo,
    const float* __restrict__ bias,
    const float* __restrict__ addend,
    float* __restrict__ out, int outCt)
{
    constexpr int CCH = (CIN < 16) ? CIN : 16;
    constexpr int COUTP = (COUT + 3) & ~3;
    constexpr int NP = COUTP / 2;
    constexpr int ITR = 4 + 2 * DIL;
    constexpr int TS = 272;
    constexpr int TSZ = ITR * TS;
    constexpr int NCHUNK = ITR * 68;
    __shared__ __align__(16) float tile[2][TSZ];
    __shared__ __align__(16) float ws[CCH * 9 * COUTP];
    __shared__ float sIv[NORM ? CIN : 1], sNm[NORM ? CIN : 1];
    __shared__ float reds[STATS ? COUT * 8 : 1];
    __shared__ float redq[STATS ? COUT * 8 : 1];
    __shared__ float redm[(STATS == 2) ? COUT * 8 : 1];

    const int tid = threadIdx.x;
    const int b = blockIdx.y;
    const int oc0 = blockIdx.z * COUT;
    const int y0 = blockIdx.x * 4;
    const int ry = tid >> 6;
    const int cg = (tid & 63) * 4;

    if (NORM && tid < CIN) {
        float m = stats[tid];
        float iv = stats[64 + tid];
        sIv[tid] = iv; sNm[tid] = -m * iv;
    }

    unsigned long long acc2[4][NP];
    {
        unsigned long long binit[NP];
        #pragma unroll
        for (int j = 0; j < NP; j++) {
            float b0 = (BIAS && 2*j     < COUT) ? __ldg(&bias[oc0 + 2*j])     : 0.f;
            float b1 = (BIAS && 2*j + 1 < COUT) ? __ldg(&bias[oc0 + 2*j + 1]) : 0.f;
            binit[j] = pack2(b0, b1);
        }
        #pragma unroll
        for (int p = 0; p < 4; p++)
            #pragma unroll
            for (int j = 0; j < NP; j++)
                acc2[p][j] = binit[j];
    }

    auto load_ws = [&](int c0) {
        for (int i = tid; i < CCH * 9 * COUTP; i += 256) {
            int o = i % COUTP;
            int rem = i / COUTP;
            int k = rem % 9;
            int cl = rem / 9;
            ws[i] = (o < COUT) ? w[((size_t)(oc0 + o) * wCt + wCo + c0 + cl) * 9 + k] : 0.f;
        }
    };
    auto cp_stage = [&](int c, int buf) {
        const float* __restrict__ inp = in + (size_t)(b * inCt + inCo + c) * HW;
        unsigned sbase = smem_u32(&tile[buf][0]);
        #pragma unroll
        for (int it = 0; it < (NCHUNK + 255) / 256; it++) {
            int i = it * 256 + tid;
            if (i < NCHUNK) {
                int r = i / 68;
                int j = i - r * 68;
                int gy = y0 - DIL + r;
                bool ok = (j >= 1) && (j <= 64) && ((unsigned)gy < (unsigned)H);
                const float* gp = ok ? (inp + gy * W + 4 * (j - 1)) : inp;
                unsigned sa = sbase + (unsigned)(r * TS + 4 * j) * 4u;
                CP_ASYNC16(sa, gp, ok ? 16 : 0);
            }
        }
        CP_COMMIT();
    };
    auto compute_stage = [&](int g, int buf) {
        int cl = g % CCH;
        float iv = NORM ? sIv[g] : 1.f;
        float nm = NORM ? sNm[g] : 0.f;
        #pragma unroll
        for (int ky = 0; ky < 3; ky++) {
            int gy = y0 + ry + (ky - 1) * DIL;
            if ((unsigned)gy >= (unsigned)H) continue;
            const float* trow = &tile[buf][(ry + ky * DIL) * TS + cg];
            float4 ta = *(const float4*)(trow);
            float4 tb4 = *(const float4*)(trow + 4);
            float4 tc4 = *(const float4*)(trow + 8);
            float t[12] = {ta.x, ta.y, ta.z, ta.w,
                           tb4.x, tb4.y, tb4.z, tb4.w,
                           tc4.x, tc4.y, tc4.z, tc4.w};
            unsigned long long vp[12];
            #pragma unroll
            for (int j = 4 - DIL; j <= 7 + DIL; j++) {
                float v = t[j];
                if (NORM) v = fmaf(v, iv, nm);
                if (RELU) v = fmaxf(v, 0.f);
                if (NORM) {   // normalized padding must be exactly 0 at OOB x
                    if (j < 4 && cg == 0)   v = 0.f;
                    if (j > 7 && cg == 252) v = 0.f;
                }
                vp[j] = pack2(v, v);
            }
            #pragma unroll
            for (int kx = 0; kx < 3; kx++) {
                const ulonglong2* wr =
                    (const ulonglong2*)&ws[(cl * 9 + ky * 3 + kx) * COUTP];
                #pragma unroll
                for (int q = 0; q < COUTP / 4; q++) {
                    ulonglong2 wp = wr[q];
                    #pragma unroll
                    for (int p = 0; p < 4; p++) {
                        fma2(acc2[p][2*q],   vp[4 + p + (kx-1)*DIL], wp.x);
                        fma2(acc2[p][2*q+1], vp[4 + p + (kx-1)*DIL], wp.y);
                    }
                }
            }
        }
    };

    // ---- pipeline: prefetch distance 1, 2 buffers, 2 barriers/stage ----
    load_ws(0);
    cp_stage(0, 0);
    #pragma unroll 1
    for (int g = 0; g < CIN; g++) {
        if (g + 1 < CIN) { cp_stage(g + 1, (g + 1) & 1); CP_WAIT1(); }
        else             { CP_WAIT0(); }
        __syncthreads();
        if (CIN > CCH && g > 0 && (g % CCH) == 0) {
            load_ws(g);
            __syncthreads();
        }
        compute_stage(g, g & 1);
        __syncthreads();
    }

    // ---- epilogue: unpack, addend, store, stats ----
    const int pixb = (y0 + ry) * W + cg;
    const int lane = tid & 31, wid = tid >> 5;
    #pragma unroll
    for (int o = 0; o < COUT; o++) {
        float a0 = (o & 1) ? hi32(acc2[0][o >> 1]) : lo32(acc2[0][o >> 1]);
        float a1 = (o & 1) ? hi32(acc2[1][o >> 1]) : lo32(acc2[1][o >> 1]);
        float a2 = (o & 1) ? hi32(acc2[2][o >> 1]) : lo32(acc2[2][o >> 1]);
        float a3 = (o & 1) ? hi32(acc2[3][o >> 1]) : lo32(acc2[3][o >> 1]);
        if (ADDEND) {
            float4 ad = *(const float4*)(addend + (size_t)(b * COUT + o) * HW + pixb);
            a0 += ad.x; a1 += ad.y; a2 += ad.z; a3 += ad.w;
        }
        float4 v = make_float4(a0, a1, a2, a3);
        *(float4*)(out + (size_t)(b * outCt + oc0 + o) * HW + pixb) = v;
        if constexpr (STATS > 0) {
            float s = a0 + a1 + a2 + a3;
            float q = a0*a0 + a1*a1 + a2*a2 + a3*a3;
            float mx = fmaxf(fmaxf(a0, a1), fmaxf(a2, a3));
            #pragma unroll
            for (int d = 16; d > 0; d >>= 1) {
                s += __shfl_down_sync(0xffffffffu, s, d);
                q += __shfl_down_sync(0xffffffffu, q, d);
                if (STATS == 2) mx = fmaxf(mx, __shfl_down_sync(0xffffffffu, mx, d));
            }
            if (lane == 0) {
                reds[o * 8 + wid] = s;
                redq[o * 8 + wid] = q;
                if (STATS == 2) redm[o * 8 + wid] = mx;
            }
        }
    }
    if constexpr (STATS > 0) {
        __syncthreads();
        if (tid < COUT) {
            float s = 0.f, q = 0.f, mx = -INFINITY;
            #pragma unroll
            for (int j = 0; j < 8; j++) {
                s += reds[tid * 8 + j];
                q += redq[tid * 8 + j];
                if (STATS == 2) mx = fmaxf(mx, redm[tid * 8 + j]);
            }
            int rowi = b * gridDim.x + blockIdx.x;
            g_bsum[rowi * 64 + oc0 + tid] = s;
            g_bsq[rowi * 64 + oc0 + tid] = q;
            if (STATS == 2) g_bmax[rowi * 64 + oc0 + tid] = mx;
        }
    }
}

// =============== conv2 (64->16) fused norm*ca*sg, cp.async staged =============
__global__ void __launch_bounds__(256, 2) conv2_casg_s(
    const float* __restrict__ w, float* __restrict__ out)
{
    constexpr int TS = 272;
    constexpr int ITR = 6;
    constexpr int TSZ = ITR * TS;
    constexpr int NCHUNK = ITR * 68;
    __shared__ __align__(16) float tile[2][TSZ];
    __shared__ __align__(16) float sgt[TSZ];
    __shared__ __align__(16) float ws[16 * 9 * 16];
    __shared__ float reds[16 * 8], redq[16 * 8];
    __shared__ float sc[64], sb[64];

    const int tid = threadIdx.x;
    const int b = blockIdx.y;
    const int y0 = blockIdx.x * 4;
    const int ry = tid >> 6;
    const int cg = (tid & 63) * 4;

    if (tid < 64) {
        float iv = g_stats[7 * 128 + 64 + tid], m = g_stats[7 * 128 + tid];
        float s = iv * g_ca[b * 64 + tid];
        sc[tid] = s; sb[tid] = -m * s;
    }
    {
        const float* sgp = g_sg + (size_t)b * HW;
        for (int i = tid; i < TSZ; i += 256) {
            int r = i / TS;
            int gx = i - r * TS - 4;
            int gy = y0 - 1 + r;
            sgt[i] = ((unsigned)gy < (unsigned)H && (unsigned)gx < (unsigned)W)
                     ? sgp[gy * W + gx] : 0.f;
        }
    }

    unsigned long long acc2[4][8];
    #pragma unroll
    for (int p = 0; p < 4; p++)
        #pragma unroll
        for (int j = 0; j < 8; j++) acc2[p][j] = 0ull;

    auto load_ws = [&](int c0) {
        for (int i = tid; i < 16 * 9 * 16; i += 256) {
            int o = i & 15;
            int rem = i >> 4;
            int k = rem % 9;
            int cl = rem / 9;
            ws[i] = w[((size_t)o * 64 + c0 + cl) * 9 + k];
        }
    };
    auto cp_stage = [&](int c, int buf) {
        const float* __restrict__ inp = g_z + (size_t)(b * 64 + c) * HW;
        unsigned sbase = smem_u32(&tile[buf][0]);
        #pragma unroll
        for (int it = 0; it < (NCHUNK + 255) / 256; it++) {
            int i = it * 256 + tid;
            if (i < NCHUNK) {
                int r = i / 68;
                int j = i - r * 68;
                int gy = y0 - 1 + r;
                bool ok = (j >= 1) && (j <= 64) && ((unsigned)gy < (unsigned)H);
                const float* gp = ok ? (inp + gy * W + 4 * (j - 1)) : inp;
                unsigned sa = sbase + (unsigned)(r * TS + 4 * j) * 4u;
                CP_ASYNC16(sa, gp, ok ? 16 : 0);
            }
        }
        CP_COMMIT();
    };
    auto compute_stage = [&](int g, int buf) {
        int cl = g & 15;
        float scc = sc[g], bcc = sb[g];
        #pragma unroll
        for (int ky = 0; ky < 3; ky++) {
            int gy = y0 + ry + (ky - 1);
            if ((unsigned)gy >= (unsigned)H) continue;
            int roff = (ry + ky) * TS + cg;
            const float* trow = &tile[buf][roff];
            const float* srow = &sgt[roff];
            float4 ta = *(const float4*)(trow);
            float4 tb4 = *(const float4*)(trow + 4);
            float4 tc4 = *(const float4*)(trow + 8);
            float4 sa = *(const float4*)(srow);
            float4 sb4 = *(const float4*)(srow + 4);
            float4 sc4 = *(const float4*)(srow + 8);
            float t[12] = {ta.x, ta.y, ta.z, ta.w,
                           tb4.x, tb4.y, tb4.z, tb4.w,
                           tc4.x, tc4.y, tc4.z, tc4.w};
            float sg[12] = {sa.x, sa.y, sa.z, sa.w,
                            sb4.x, sb4.y, sb4.z, sb4.w,
                            sc4.x, sc4.y, sc4.z, sc4.w};
            unsigned long long vp[12];
            #pragma unroll
            for (int j = 3; j <= 8; j++) {
                float v = fmaf(t[j], scc, bcc) * sg[j];  // sg==0 at OOB -> v=0
                vp[j] = pack2(v, v);
            }
            #pragma unroll
            for (int kx = 0; kx < 3; kx++) {
                const ulonglong2* wr = (const ulonglong2*)&ws[(cl*9 + ky*3 + kx) * 16];
                #pragma unroll
                for (int q = 0; q < 4; q++) {
                    ulonglong2 wp = wr[q];
                    #pragma unroll
                    for (int p = 0; p < 4; p++) {
                        fma2(acc2[p][2*q],   vp[4 + p + (kx-1)], wp.x);
                        fma2(acc2[p][2*q+1], vp[4 + p + (kx-1)], wp.y);
                    }
                }
            }
        }
    };

    load_ws(0);
    cp_stage(0, 0);
    #pragma unroll 1
    for (int g = 0; g < 64; g++) {
        if (g + 1 < 64) { cp_stage(g + 1, (g + 1) & 1); CP_WAIT1(); }
        else            { CP_WAIT0(); }
        __syncthreads();   // also covers sc/sb + sgt on first iteration
        if (g > 0 && (g & 15) == 0) {
            load_ws(g);
            __syncthreads();
        }
        compute_stage(g, g & 1);
        __syncthreads();
    }

    const int pixb = (y0 + ry) * W + cg;
    const int lane = tid & 31, wid = tid >> 5;
    #pragma unroll
    for (int o = 0; o < 16; o++) {
        float a0 = (o & 1) ? hi32(acc2[0][o >> 1]) : lo32(acc2[0][o >> 1]);
        float a1 = (o & 1) ? hi32(acc2[1][o >> 1]) : lo32(acc2[1][o >> 1]);
        float a2 = (o & 1) ? hi32(acc2[2][o >> 1]) : lo32(acc2[2][o >> 1]);
        float a3 = (o & 1) ? hi32(acc2[3][o >> 1]) : lo32(acc2[3][o >> 1]);
        *(float4*)(out + (size_t)(b * 16 + o) * HW + pixb) = make_float4(a0, a1, a2, a3);
        float s = a0 + a1 + a2 + a3;
        float q = a0*a0 + a1*a1 + a2*a2 + a3*a3;
        #pragma unroll
        for (int d = 16; d > 0; d >>= 1) {
            s += __shfl_down_sync(0xffffffffu, s, d);
            q += __shfl_down_sync(0xffffffffu, q, d);
        }
        if (lane == 0) { reds[o * 8 + wid] = s; redq[o * 8 + wid] = q; }
    }
    __syncthreads();
    if (tid < 16) {
        float s = 0.f, q = 0.f;
        #pragma unroll
        for (int j = 0; j < 8; j++) { s += reds[tid*8+j]; q += redq[tid*8+j]; }
        int rowi = b * gridDim.x + blockIdx.x;
        g_bsum[rowi * 64 + tid] = s;
        g_bsq[rowi * 64 + tid] = q;
    }
}

// ---------------- 1x1 convs, 4 pixels/thread (coalesced float4) --------------
__global__ void __launch_bounds__(128) conv1x1_64_16_p4(
    const float* __restrict__ in, const float* __restrict__ w,
    const float* __restrict__ bias, float* __restrict__ out)
{
    __shared__ __align__(16) float ws[64*16];
    __shared__ float reds[16*4], redq[16*4];
    int tid = threadIdx.x;
    for (int i = tid; i < 64*16; i += 128) {
        int o = i & 15, c = i >> 4;
        ws[i] = w[o * 64 + c];
    }
    __syncthreads();
    int p4 = blockIdx.x * 128 + tid;
    int b = blockIdx.y;
    const float4* inb = (const float4*)(in + (size_t)b * 64 * HW) + p4;
    unsigned long long acc2[4][8];
    #pragma unroll
    for (int j = 0; j < 8; j++) {
        unsigned long long bv = pack2(__ldg(&bias[2*j]), __ldg(&bias[2*j+1]));
        acc2[0][j] = bv; acc2[1][j] = bv; acc2[2][j] = bv; acc2[3][j] = bv;
    }
    #pragma unroll 1
    for (int c = 0; c < 64; c++) {
        float4 v = inb[(size_t)c * (HW / 4)];
        unsigned long long v0 = pack2(v.x, v.x), v1 = pack2(v.y, v.y);
        unsigned long long v2 = pack2(v.z, v.z), v3 = pack2(v.w, v.w);
        const ulonglong2* wr = (const ulonglong2*)&ws[c * 16];
        #pragma unroll
        for (int q = 0; q < 4; q++) {
            ulonglong2 wp = wr[q];
            fma2(acc2[0][2*q], v0, wp.x); fma2(acc2[0][2*q+1], v0, wp.y);
            fma2(acc2[1][2*q], v1, wp.x); fma2(acc2[1][2*q+1], v1, wp.y);
            fma2(acc2[2][2*q], v2, wp.x); fma2(acc2[2][2*q+1], v2, wp.y);
            fma2(acc2[3][2*q], v3, wp.x); fma2(acc2[3][2*q+1], v3, wp.y);
        }
    }
    int lane = tid & 31, wid = tid >> 5;
    #pragma unroll
    for (int o = 0; o < 16; o++) {
        float a0 = (o&1) ? hi32(acc2[0][o>>1]) : lo32(acc2[0][o>>1]);
        float a1 = (o&1) ? hi32(acc2[1][o>>1]) : lo32(acc2[1][o>>1]);
        float a2 = (o&1) ? hi32(acc2[2][o>>1]) : lo32(acc2[2][o>>1]);
        float a3 = (o&1) ? hi32(acc2[3][o>>1]) : lo32(acc2[3][o>>1]);
        ((float4*)out)[(size_t)(b * 16 + o) * (HW / 4) + p4] = make_float4(a0,a1,a2,a3);
        float s = a0+a1+a2+a3;
        float q = a0*a0+a1*a1+a2*a2+a3*a3;
        #pragma unroll
        for (int d = 16; d > 0; d >>= 1) {
            s += __shfl_down_sync(0xffffffffu, s, d);
            q += __shfl_down_sync(0xffffffffu, q, d);
        }
        if (lane == 0) { reds[o*4+wid] = s; redq[o*4+wid] = q; }
    }
    __syncthreads();
    if (tid < 16) {
        float s = 0.f, q = 0.f;
        #pragma unroll
        for (int j = 0; j < 4; j++) { s += reds[tid*4+j]; q += redq[tid*4+j]; }
        int rowi = b * gridDim.x + blockIdx.x;
        g_bsum[rowi * 64 + tid] = s;
        g_bsq[rowi * 64 + tid] = q;
    }
}

// 64->64 1x1 over normalized cat4; split 4 x 16 outputs; 4 px/thread
__global__ void __launch_bounds__(128) conv1x1_cat4_p4(
    const float* __restrict__ xb, const float* __restrict__ w,
    const float* __restrict__ bias, float* __restrict__ out)
{
    __shared__ __align__(16) float ws[64*16];
    __shared__ float siv[64], snm[64];
    __shared__ float reds[16*4], redq[16*4];
    int tid = threadIdx.x;
    int oc0 = blockIdx.z * 16;
    if (tid < 64) {
        int s = tid >> 4, c = tid & 15;
        float m = g_stats[(1 + s) * 128 + c];
        float iv = g_stats[(1 + s) * 128 + 64 + c];
        siv[tid] = iv; snm[tid] = -m * iv;
    }
    for (int i = tid; i < 64*16; i += 128) {
        int o = i & 15, c = i >> 4;
        ws[i] = w[(oc0 + o) * 64 + c];
    }
    __syncthreads();
    int p4 = blockIdx.x * 128 + tid;
    int b = blockIdx.y;
    unsigned long long acc2[4][8];
    #pragma unroll
    for (int j = 0; j < 8; j++) {
        unsigned long long bv = pack2(__ldg(&bias[oc0+2*j]), __ldg(&bias[oc0+2*j+1]));
        acc2[0][j] = bv; acc2[1][j] = bv; acc2[2][j] = bv; acc2[3][j] = bv;
    }
    #pragma unroll 1
    for (int c = 0; c < 64; c++) {
        const float* src = xb + (size_t)(c >> 4) * SZ16 + (size_t)(b * 16 + (c & 15)) * HW;
        float4 v = ((const float4*)src)[p4];
        float ivc = siv[c], nmc = snm[c];
        v.x = fmaf(v.x, ivc, nmc); v.y = fmaf(v.y, ivc, nmc);
        v.z = fmaf(v.z, ivc, nmc); v.w = fmaf(v.w, ivc, nmc);
        unsigned long long v0 = pack2(v.x, v.x), v1 = pack2(v.y, v.y);
        unsigned long long v2 = pack2(v.z, v.z), v3 = pack2(v.w, v.w);
        const ulonglong2* wr = (const ulonglong2*)&ws[c * 16];
        #pragma unroll
        for (int q = 0; q < 4; q++) {
            ulonglong2 wp = wr[q];
            fma2(acc2[0][2*q], v0, wp.x); fma2(acc2[0][2*q+1], v0, wp.y);
            fma2(acc2[1][2*q], v1, wp.x); fma2(acc2[1][2*q+1], v1, wp.y);
            fma2(acc2[2][2*q], v2, wp.x); fma2(acc2[2][2*q+1], v2, wp.y);
            fma2(acc2[3][2*q], v3, wp.x); fma2(acc2[3][2*q+1], v3, wp.y);
        }
    }
    int lane = tid & 31, wid = tid >> 5;
    #pragma unroll
    for (int o = 0; o < 16; o++) {
        float a0 = (o&1) ? hi32(acc2[0][o>>1]) : lo32(acc2[0][o>>1]);
        float a1 = (o&1) ? hi32(acc2[1][o>>1]) : lo32(acc2[1][o>>1]);
        float a2 = (o&1) ? hi32(acc2[2][o>>1]) : lo32(acc2[2][o>>1]);
        float a3 = (o&1) ? hi32(acc2[3][o>>1]) : lo32(acc2[3][o>>1]);
        ((float4*)out)[(size_t)(b * 64 + oc0 + o) * (HW / 4) + p4] = make_float4(a0,a1,a2,a3);
        float s = a0+a1+a2+a3;
        float q = a0*a0+a1*a1+a2*a2+a3*a3;
        #pragma unroll
        for (int d = 16; d > 0; d >>= 1) {
            s += __shfl_down_sync(0xffffffffu, s, d);
            q += __shfl_down_sync(0xffffffffu, q, d);
        }
        if (lane == 0) { reds[o*4+wid] = s; redq[o*4+wid] = q; }
    }
    __syncthreads();
    if (tid < 16) {
        float s = 0.f, q = 0.f;
        #pragma unroll
        for (int j = 0; j < 4; j++) { s += reds[tid*4+j]; q += redq[tid*4+j]; }
        int rowi = b * gridDim.x + blockIdx.x;
        g_bsum[rowi * 64 + oc0 + tid] = s;
        g_bsq[rowi * 64 + oc0 + tid] = q;
    }
}

// ---------------- t materialization (float4) ----------------------------------
__global__ void norm_t_k(const float* __restrict__ pre,
                         const float* __restrict__ add1, const float* __restrict__ st1,
                         const float* __restrict__ lfsrc, int lfco)
{
    int i4 = blockIdx.x * 256 + threadIdx.x;
    int idx = i4 * 4;
    int pix = idx & (HW - 1);
    int rest = idx >> 16;
    int c = rest & 15, b = rest >> 4;
    float m = g_stats[5 * 128 + c], iv = g_stats[5 * 128 + 64 + c];
    float nm = -m * iv;
    float4 v = ((const float4*)pre)[i4];
    v.x = fmaf(v.x, iv, nm); v.y = fmaf(v.y, iv, nm);
    v.z = fmaf(v.z, iv, nm); v.w = fmaf(v.w, iv, nm);
    if (add1) {
        float4 a = ((const float4*)add1)[i4];
        if (st1) {
            float m1 = st1[c], i1 = st1[64 + c], n1 = -m1 * i1;
            a.x = fmaf(a.x, i1, n1); a.y = fmaf(a.y, i1, n1);
            a.z = fmaf(a.z, i1, n1); a.w = fmaf(a.w, i1, n1);
        }
        v.x += a.x; v.y += a.y; v.z += a.z; v.w += a.w;
    }
    if (lfsrc) {
        float4 l = *(const float4*)(lfsrc + (size_t)(b * 64 + lfco + c) * HW + pix);
        v.x += l.x; v.y += l.y; v.z += l.z; v.w += l.w;
    }
    ((float4*)g_t)[i4] = v;
}

// ---------------- deformable conv (exact reference semantics, f32x2) ----------
__global__ void __launch_bounds__(256) deform_k(
    const float* __restrict__ t, const float* __restrict__ off,
    const float* __restrict__ wd, float* __restrict__ out)
{
    __shared__ __align__(16) float ws[16*16*9];
    for (int i = threadIdx.x; i < 2304; i += blockDim.x) {
        int o = i & 15;
        int rem = i >> 4;
        int n = rem % 9;
        int c = rem / 9;
        ws[i] = wd[(o * 16 + c) * 9 + n];
    }
    __syncthreads();
    int pix = blockIdx.x * blockDim.x + threadIdx.x;
    int b = blockIdx.y;
    int yi = pix >> 8, xj = pix & 255;

    unsigned long long acc2[8];
    #pragma unroll
    for (int j = 0; j < 8; j++) acc2[j] = 0ull;

    const float* offb = off + (size_t)b * 18 * HW + pix;
    const float* tb = t + (size_t)b * 16 * HW;

    #pragma unroll 1
    for (int n = 0; n < 9; n++) {
        int dx = n / 3 - 1, dy = n % 3 - 1;
        float ox = offb[(size_t)(2 * n) * HW];
        float oy = offb[(size_t)(2 * n + 1) * HW];
        float plx = (float)(yi + 1 + dx) + ox;
        float ply = (float)(xj + 1 + dy) + oy;
        float flx = floorf(plx), fly = floorf(ply);
        int qltx = min(max((int)flx, 0), 257);
        int qlty = min(max((int)fly, 0), 257);
        int qrbx = min(max((int)flx + 1, 0), 257);
        int qrby = min(max((int)fly + 1, 0), 257);
        bool mx = (plx < 1.0f) || (plx > 256.0f);
        bool my = (ply < 1.0f) || (ply > 256.0f);
        float px = mx ? flx : plx; px = fminf(fmaxf(px, 0.f), 257.f);
        float py = my ? fly : ply; py = fminf(fmaxf(py, 0.f), 257.f);
        float wltx = 1.f + ((float)qltx - px);
        float wrbx = 1.f - ((float)qrbx - px);
        float wlty = 1.f + ((float)qlty - py);
        float wrby = 1.f - ((float)qrby - py);
        float glt = wltx * wlty, grb = wrbx * wrby;
        float glb = wltx * wrby, grt = wrbx * wlty;
        bool vltx = (qltx >= 1 && qltx <= 256);
        bool vlty = (qlty >= 1 && qlty <= 256);
        bool vrbx = (qrbx >= 1 && qrbx <= 256);
        bool vrby = (qrby >= 1 && qrby <= 256);
        int rlt = (qltx - 1) * W + (qlty - 1);
        int rrb = (qrbx - 1) * W + (qrby - 1);
        int rlb = (qltx - 1) * W + (qrby - 1);
        int rrt = (qrbx - 1) * W + (qlty - 1);
        #pragma unroll 4
        for (int c = 0; c < 16; c++) {
            const float* tc = tb + (size_t)c * HW;
            float vlt = (vltx && vlty) ? tc[rlt] : 0.f;
            float vrb = (vrbx && vrby) ? tc[rrb] : 0.f;
            float vlb = (vltx && vrby) ? tc[rlb] : 0.f;
            float vrt = (vrbx && vlty) ? tc[rrt] : 0.f;
            float val = glt * vlt + grb * vrb + glb * vlb + grt * vrt;
            unsigned long long vp = pack2(val, val);
            const ulonglong2* wr = (const ulonglong2*)&ws[(c * 9 + n) * 16];
            #pragma unroll
            for (int q = 0; q < 4; q++) {
                ulonglong2 wp = wr[q];
                fma2(acc2[2*q],   vp, wp.x);
                fma2(acc2[2*q+1], vp, wp.y);
            }
        }
    }
    #pragma unroll
    for (int o = 0; o < 16; o++) {
        float v = (o & 1) ? hi32(acc2[o >> 1]) : lo32(acc2[o >> 1]);
        out[(size_t)(b * 16 + o) * HW + pix] = v;
    }
}

// ---------------- CBAM ----------------------------------------------------------
__global__ void cbam_final_k(int gridX, const float* __restrict__ w1,
                             const float* __restrict__ w2)
{
    int t = threadIdx.x;
    int b = t >> 6, c = t & 63;
    float s = 0.f, q = 0.f, mx = -INFINITY;
    for (int j = 0; j < gridX; j++) {
        int idx = (b * gridX + j) * 64 + c;
        s += g_bsum[idx]; q += g_bsq[idx]; mx = fmaxf(mx, g_bmax[idx]);
    }
    __shared__ float sh_s[4][64], sh_q[4][64], sh_m[4][64];
    sh_s[b][c] = s; sh_q[b][c] = q; sh_m[b][c] = mx;
    __syncthreads();
    __shared__ float sm[64], si[64];
    if (t < 64) {
        float ts = 0.f, tq = 0.f;
        #pragma unroll
        for (int bb = 0; bb < 4; bb++) { ts += sh_s[bb][t]; tq += sh_q[bb][t]; }
        float m = ts / (float)NSTAT;
        float v = tq / (float)NSTAT - m * m;
        float iv = rsqrtf(v + 1e-5f);
        g_stats[7 * 128 + t] = m;
        g_stats[7 * 128 + 64 + t] = iv;
        sm[t] = m; si[t] = iv;
    }
    __syncthreads();
    __shared__ float av[4][64], xmv[4][64];
    av[b][c]  = (sh_s[b][c] / (float)HW - sm[c]) * si[c];
    xmv[b][c] = (sh_m[b][c] - sm[c]) * si[c];
    __syncthreads();
    __shared__ float hid[4][4][2];
    if (t < 32) {
        int bb = t >> 3, h = (t >> 1) & 3, which = t & 1;
        float acc = 0.f;
        for (int cc = 0; cc < 64; cc++)
            acc += w1[h * 64 + cc] * (which ? xmv[bb][cc] : av[bb][cc]);
        hid[bb][h][which] = fmaxf(acc, 0.f);
    }
    __syncthreads();
    {
        float va = 0.f, vm = 0.f;
        #pragma unroll
        for (int h = 0; h < 4; h++) {
            float wv = w2[c * 4 + h];
            va = fmaf(wv, hid[b][h][0], va);
            vm = fmaf(wv, hid[b][h][1], vm);
        }
        g_ca[b * 64 + c] = 1.f / (1.f + expf(-(va + vm)));
    }
}

// sp (mean,max over channels of (z norm * ca)), float4 over pixels
__global__ void apply1_k()
{
    __shared__ float sc[64], sb[64];
    int b = blockIdx.y;
    if (threadIdx.x < 64) {
        int c = threadIdx.x;
        float iv = g_stats[7 * 128 + 64 + c], m = g_stats[7 * 128 + c];
        float s = iv * g_ca[b * 64 + c];
        sc[c] = s; sb[c] = -m * s;
    }
    __syncthreads();
    int p4 = blockIdx.x * 256 + threadIdx.x;
    const float4* zp = (const float4*)(g_z + (size_t)b * 64 * HW) + p4;
    float4 smv = make_float4(0.f, 0.f, 0.f, 0.f);
    float4 mxv = make_float4(-INFINITY, -INFINITY, -INFINITY, -INFINITY);
    #pragma unroll 1
    for (int c = 0; c < 64; c++) {
        float4 v = zp[(size_t)c * (HW / 4)];
        float s = sc[c], bb = sb[c];
        v.x = fmaf(v.x, s, bb); v.y = fmaf(v.y, s, bb);
        v.z = fmaf(v.z, s, bb); v.w = fmaf(v.w, s, bb);
        smv.x += v.x; smv.y += v.y; smv.z += v.z; smv.w += v.w;
        mxv.x = fmaxf(mxv.x, v.x); mxv.y = fmaxf(mxv.y, v.y);
        mxv.z = fmaxf(mxv.z, v.z); mxv.w = fmaxf(mxv.w, v.w);
    }
    const float k = 1.f / 64.f;
    smv.x *= k; smv.y *= k; smv.z *= k; smv.w *= k;
    ((float4*)(g_sp + (size_t)(b * 2) * HW))[p4] = smv;
    ((float4*)(g_sp + (size_t)(b * 2 + 1) * HW))[p4] = mxv;
}

// sg = sigmoid(conv7x7(sp))
__global__ void apply2_k(const float* __restrict__ wsp)
{
    __shared__ float w[98];
    if (threadIdx.x < 98) w[threadIdx.x] = wsp[threadIdx.x];
    __syncthreads();
    int pix = blockIdx.x * 256 + threadIdx.x;
    int b = blockIdx.y;
    int y = pix >> 8, x = pix & 255;
    const float* s0 = g_sp + (size_t)(b * 2) * HW;
    const float* s1 = s0 + HW;
    float acc = 0.f;
    #pragma unroll 1
    for (int ky = 0; ky < 7; ky++) {
        int yy = y + ky - 3;
        if ((unsigned)yy >= (unsigned)H) continue;
        #pragma unroll
        for (int kx = 0; kx < 7; kx++) {
            int xx = x + kx - 3;
            if ((unsigned)xx >= (unsigned)W) continue;
            int ip = yy * W + xx;
            acc += w[ky * 7 + kx] * s0[ip] + w[49 + ky * 7 + kx] * s1[ip];
        }
    }
    g_sg[(size_t)b * HW + pix] = 1.f / (1.f + expf(-acc));
}

// ---------------- final elementwise ----------------------------------------------
__global__ void norm_s_k(const float* __restrict__ xx, const float* __restrict__ lf)
{
    int i4 = blockIdx.x * 256 + threadIdx.x;
    int idx = i4 * 4;
    int c = (idx >> 16) & 63;
    float m = g_stats[8 * 128 + c], iv = g_stats[8 * 128 + 64 + c];
    float nm = -m * iv;
    float4 v = ((const float4*)xx)[i4];
    float4 l = ((const float4*)lf)[i4];
    v.x = fmaxf(fmaf(v.x, iv, nm), 0.f) + l.x;
    v.y = fmaxf(fmaf(v.y, iv, nm), 0.f) + l.y;
    v.z = fmaxf(fmaf(v.z, iv, nm), 0.f) + l.z;
    v.w = fmaxf(fmaf(v.w, iv, nm), 0.f) + l.w;
    ((float4*)g_s)[i4] = v;
}

__global__ void norm_out_k(float* __restrict__ o)
{
    int i4 = blockIdx.x * 256 + threadIdx.x;
    int idx = i4 * 4;
    int c = (idx >> 16) & 63;
    float m = g_stats[9 * 128 + c], iv = g_stats[9 * 128 + 64 + c];
    float nm = -m * iv;
    float4 v = ((float4*)o)[i4];
    v.x = fmaf(v.x, iv, nm); v.y = fmaf(v.y, iv, nm);
    v.z = fmaf(v.z, iv, nm); v.w = fmaf(v.w, iv, nm);
    ((float4*)o)[i4] = v;
}

// ---------------- host orchestration ----------------------------------------------
extern "C" void kernel_launch(void* const* d_in, const int* in_sizes, int n_in,
                              void* d_out, int out_size)
{
    const float* lf   = (const float*)d_in[0];
    const float* hf   = (const float*)d_in[1];
    const float* w11  = (const float*)d_in[2];
    const float* b11  = (const float*)d_in[3];
    const float* wconv= (const float*)d_in[4];
    const float* woff = (const float*)d_in[5];
    const float* boff = (const float*)d_in[6];
    const float* wdef = (const float*)d_in[7];
    const float* wdil[4] = {(const float*)d_in[8], (const float*)d_in[9],
                            (const float*)d_in[10], (const float*)d_in[11]};
    const float* wc1  = (const float*)d_in[12];
    const float* wc2  = (const float*)d_in[13];
    const float* wfc1 = (const float*)d_in[14];
    const float* wfc2 = (const float*)d_in[15];
    const float* wsp  = (const float*)d_in[16];
    const float* wc12 = (const float*)d_in[17];
    const float* bc12 = (const float*)d_in[18];
    const float* wc33 = (const float*)d_in[19];
    float* out = (float*)d_out;

    void* tmp;
#define GETP(name, sym) cudaGetSymbolAddress(&tmp, sym); float* name = (float*)tmp;
    GETP(p_hfpre, g_hfpre) GETP(p_prehf, g_prehf) GETP(p_pre, g_pre)
    GETP(p_t, g_t)         GETP(p_off, g_off)     GETP(p_d16, g_d16)
    GETP(p_y, g_y)         GETP(p_z, g_z)         GETP(p_s, g_s)
    GETP(p_xb, g_xb)       GETP(p_stats, g_stats)
#undef GETP

    const dim3 CS(64, BATCH);            // staged convs: 256 blocks of 256 thr
    const dim3 CSz2(64, BATCH, 2);
    const dim3 CSz4(64, BATCH, 4);
    const dim3 P4(128, BATCH);           // 1x1 p4 kernels
    const dim3 P4z4(128, BATCH, 4);
    const dim3 PGo(256, BATCH);

    // Stage A: hf_pre = conv1x1(hf)+bias; stats slot0
    conv1x1_64_16_p4<<<P4, 128>>>(hf, w11, b11, p_hfpre);
    bn_final_k<<<16, 32>>>(512, 0);

    // Shared hf-part: conv3x3(relu(bn(hf_pre)), wconv[:,16:32])
    conv3x3_s<16,16,1,false,true,true,false,0><<<CS, 256>>>(
        p_hfpre, 16, 0, p_stats + 0*128, wconv, 32, 16, nullptr, nullptr,
        p_prehf, 16);

    for (int k = 0; k < 4; k++) {
        // pre = conv3x3(prev_norm, wconv[:,0:16]) + prehf ; stats slot5
        if (k == 0)
            conv3x3_s<16,16,1,false,false,false,true,1><<<CS, 256>>>(
                lf, 64, 0, nullptr, wconv, 32, 0, nullptr, p_prehf, p_pre, 16);
        else
            conv3x3_s<16,16,1,false,true,false,true,1><<<CS, 256>>>(
                p_xb + (size_t)(k-1) * SZ16, 16, 0, p_stats + k*128,
                wconv, 32, 0, nullptr, p_prehf, p_pre, 16);
        bn_final_k<<<16, 32>>>(256, 5);

        // t = bn(pre) + extras
        const float* add1 = (k >= 1) ? p_xb + (size_t)(k-1) * SZ16 : nullptr;
        const float* st1  = (k >= 1) ? p_stats + k*128 : nullptr;
        const float* lfa  = (k <= 2) ? lf : nullptr;
        int lfco = (k == 0) ? 16 : (k == 1) ? 32 : 48;
        norm_t_k<<<SZ16 / 1024, 256>>>(p_pre, add1, st1, lfa, lfco);

        // offsets (COUT 18 as 2x9) + deformable conv
        conv3x3_s<16,9,1,true,false,false,false,0><<<CSz2, 256>>>(
            p_t, 16, 0, nullptr, woff, 16, 0, boff, nullptr, p_off, 18);
        deform_k<<<PGo, 256>>>(p_t, p_off, wdef, p_d16);

        // dilated conv ; stats slot6
        switch (k) {
        case 0: conv3x3_s<16,16,1,false,false,false,false,1><<<CS, 256>>>(
                    p_d16, 16, 0, nullptr, wdil[0], 16, 0, nullptr, nullptr, p_y, 16); break;
        case 1: conv3x3_s<16,16,2,false,false,false,false,1><<<CS, 256>>>(
                    p_d16, 16, 0, nullptr, wdil[1], 16, 0, nullptr, nullptr, p_y, 16); break;
        case 2: conv3x3_s<16,16,3,false,false,false,false,1><<<CS, 256>>>(
                    p_d16, 16, 0, nullptr, wdil[2], 16, 0, nullptr, nullptr, p_y, 16); break;
        default: conv3x3_s<16,16,4,false,false,false,false,1><<<CS, 256>>>(
                    p_d16, 16, 0, nullptr, wdil[3], 16, 0, nullptr, nullptr, p_y, 16); break;
        }
        bn_final_k<<<16, 32>>>(256, 6);

        // z = conv3x3(bn(y), wc1) 16->64 split 4x16 ; stats+max slot7 partials
        conv3x3_s<16,16,1,false,true,false,false,2><<<CSz4, 256>>>(
            p_y, 16, 0, p_stats + 6*128, wc1, 16, 0, nullptr, nullptr, p_z, 64);
        cbam_final_k<<<1, 256>>>(64, wfc1, wfc2);

        // spatial attention
        apply1_k<<<dim3(64, BATCH), 256>>>();
        apply2_k<<<PGo, 256>>>(wsp);

        // branch output: conv2 with fused norm*ca*sg on load ; stats slot 1+k
        conv2_casg_s<<<CS, 256>>>(wc2, p_xb + (size_t)k * SZ16);
        bn_final_k<<<16, 32>>>(256, 1 + k);
    }

    // xx_pre = conv1x1(cat4_normalized)+bias ; stats slot8
    conv1x1_cat4_p4<<<P4z4, 128>>>(p_xb, wc12, bc12, p_z);
    bn_final_k<<<64, 32>>>(512, 8);
    // s = lf + relu(bn(xx_pre))
    norm_s_k<<<SZ64 / 1024, 256>>>(p_z, lf);

    // out_pre = conv3x3(s, wc33) 64->64 split 4x16 ; stats slot9 ; normalize
    conv3x3_s<64,16,1,false,false,false,false,1><<<CSz4, 256>>>(
        p_s, 64, 0, nullptr, wc33, 64, 0, nullptr, nullptr, out, 64);
    bn_final_k<<<64, 32>>>(256, 9);
    norm_out_k<<<SZ64 / 1024, 256>>>(out);
}

// round 8
// speedup vs baseline: 2.7409x; 1.0359x over previous
#include <cuda_runtime.h>
#include <math.h>

#define H 256
#define W 256
#define HW 65536
#define BATCH 4
#define NSTAT (BATCH*HW)
#define NBLKMAX 1024

#define SZ16 (BATCH*16*HW)
#define SZ18 (BATCH*18*HW)
#define SZ64 (BATCH*64*HW)

// ---------------- scratch (static device globals; no allocations) ----------
__device__ __align__(16) float g_hfpre[SZ16];
__device__ __align__(16) float g_prehf[SZ16];
__device__ __align__(16) float g_pre[SZ16];
__device__ __align__(16) float g_t[SZ16];
__device__ __align__(16) float g_off[SZ18];
__device__ __align__(16) float g_d16[SZ16];
__device__ __align__(16) float g_y[SZ16];
__device__ __align__(16) float g_z[SZ64];
__device__ __align__(16) float g_s[SZ64];
__device__ __align__(16) float g_sp[BATCH*2*HW];
__device__ __align__(16) float g_sg[BATCH*HW];
__device__ __align__(16) float g_xb[4*SZ16];
__device__ float g_bsum[NBLKMAX*64];
__device__ float g_bsq[NBLKMAX*64];
__device__ float g_bmax[NBLKMAX*64];
// stats slots: 0=hf, 1..4=branch outs, 5=pre, 6=y, 7=z, 8=xx, 9=final
__device__ float g_stats[10*128];
__device__ float g_ca[BATCH*64];

// ---------------- f32x2 / cp.async helpers -----------------------------------
__device__ __forceinline__ unsigned long long pack2(float lo, float hi) {
    unsigned long long r;
    asm("mov.b64 %0, {%1, %2};" : "=l"(r) : "f"(lo), "f"(hi));
    return r;
}
__device__ __forceinline__ void fma2(unsigned long long& d,
                                     unsigned long long a, unsigned long long b) {
    asm("fma.rn.f32x2 %0, %1, %2, %0;" : "+l"(d) : "l"(a), "l"(b));
}
__device__ __forceinline__ float lo32(unsigned long long u) {
    return __uint_as_float((unsigned)u);
}
__device__ __forceinline__ float hi32(unsigned long long u) {
    return __uint_as_float((unsigned)(u >> 32));
}
__device__ __forceinline__ unsigned smem_u32(const void* p) {
    unsigned a;
    asm("{ .reg .u64 t; cvta.to.shared.u64 t, %1; cvt.u32.u64 %0, t; }"
        : "=r"(a) : "l"(p));
    return a;
}
#define CP_ASYNC16(sa, gp, ss) \
    asm volatile("cp.async.ca.shared.global [%0], [%1], 16, %2;" \
                 :: "r"(sa), "l"(gp), "r"(ss))
#define CP_COMMIT() asm volatile("cp.async.commit_group;" ::: "memory")
#define CP_WAIT1()  asm volatile("cp.async.wait_group 1;" ::: "memory")
#define CP_WAIT0()  asm volatile("cp.async.wait_group 0;" ::: "memory")

// ---------------- BN finalize ------------------------------------------------
__global__ void bn_final_k(int nblk, int slot)
{
    int c = blockIdx.x, lane = threadIdx.x;
    float s = 0.f, q = 0.f;
    for (int j = lane; j < nblk; j += 32) {
        s += g_bsum[j * 64 + c];
        q += g_bsq[j * 64 + c];
    }
    #pragma unroll
    for (int d = 16; d > 0; d >>= 1) {
        s += __shfl_down_sync(0xffffffffu, s, d);
        q += __shfl_down_sync(0xffffffffu, q, d);
    }
    if (lane == 0) {
        float m = s / (float)NSTAT;
        float v = q / (float)NSTAT - m * m;
        g_stats[slot * 128 + c] = m;
        g_stats[slot * 128 + 64 + c] = rsqrtf(v + 1e-5f);
    }
}

// =============== cp.async-staged 3x3 conv, f32x2, 2 channels/stage ============
// Block: 256 threads -> 4 rows x 256 cols of output. Grid (64, BATCH, zsplit).
template<int CIN, int COUT, int DIL, bool BIAS, bool NORM, bool RELU, bool ADDEND, int STATS>
__global__ void __launch_bounds__(256, 2) conv3x3_s(
    const float* __restrict__ in, int inCt, int inCo,
    const float* __restrict__ stats,
    const float* __restrict__ w, int wCt, int wCo,
    const float* __restrict__ bias,
    const float* __restrict__ addend,
    float* __restrict__ out, int outCt)
{
    constexpr int CCH = (CIN < 16) ? CIN : 16;
    constexpr int COUTP = (COUT + 3) & ~3;
    constexpr int NP = COUTP / 2;
    constexpr int ITR = 4 + 2 * DIL;
    constexpr int TS = 272;
    constexpr int TSZ = ITR * TS;
    constexpr int NCHUNK = ITR * 68;
    constexpr int CPS = (DIL <= 2) ? 2 : 1;          // channels per stage
    constexpr int NSTS = CIN / CPS;
    __shared__ __align__(16) float tile[2][CPS][TSZ];
    __shared__ __align__(16) float ws[CCH * 9 * COUTP];
    __shared__ float sIv[NORM ? CIN : 1], sNm[NORM ? CIN : 1];
    __shared__ float reds[STATS ? COUT * 8 : 1];
    __shared__ float redq[STATS ? COUT * 8 : 1];
    __shared__ float redm[(STATS == 2) ? COUT * 8 : 1];

    const int tid = threadIdx.x;
    const int b = blockIdx.y;
    const int oc0 = blockIdx.z * COUT;
    const int y0 = blockIdx.x * 4;
    const int ry = tid >> 6;
    const int cg = (tid & 63) * 4;

    if (NORM && tid < CIN) {
        float m = stats[tid];
        float iv = stats[64 + tid];
        sIv[tid] = iv; sNm[tid] = -m * iv;
    }

    unsigned long long acc2[4][NP];
    {
        unsigned long long binit[NP];
        #pragma unroll
        for (int j = 0; j < NP; j++) {
            float b0 = (BIAS && 2*j     < COUT) ? __ldg(&bias[oc0 + 2*j])     : 0.f;
            float b1 = (BIAS && 2*j + 1 < COUT) ? __ldg(&bias[oc0 + 2*j + 1]) : 0.f;
            binit[j] = pack2(b0, b1);
        }
        #pragma unroll
        for (int p = 0; p < 4; p++)
            #pragma unroll
            for (int j = 0; j < NP; j++)
                acc2[p][j] = binit[j];
    }

    auto load_ws = [&](int c0) {
        for (int i = tid; i < CCH * 9 * COUTP; i += 256) {
            int o = i % COUTP;
            int rem = i / COUTP;
            int k = rem % 9;
            int cl = rem / 9;
            ws[i] = (o < COUT) ? w[((size_t)(oc0 + o) * wCt + wCo + c0 + cl) * 9 + k] : 0.f;
        }
    };
    auto cp_stage = [&](int s, int buf) {
        #pragma unroll
        for (int cc = 0; cc < CPS; cc++) {
            int c = s * CPS + cc;
            const float* __restrict__ inp = in + (size_t)(b * inCt + inCo + c) * HW;
            unsigned sbase = smem_u32(&tile[buf][cc][0]);
            #pragma unroll
            for (int it = 0; it < (NCHUNK + 255) / 256; it++) {
                int i = it * 256 + tid;
                if (i < NCHUNK) {
                    int r = i / 68;
                    int j = i - r * 68;
                    int gy = y0 - DIL + r;
                    bool ok = (j >= 1) && (j <= 64) && ((unsigned)gy < (unsigned)H);
                    const float* gp = ok ? (inp + gy * W + 4 * (j - 1)) : inp;
                    unsigned sa = sbase + (unsigned)(r * TS + 4 * j) * 4u;
                    CP_ASYNC16(sa, gp, ok ? 16 : 0);
                }
            }
        }
        CP_COMMIT();
    };
    auto compute_stage = [&](int s, int buf) {
        #pragma unroll
        for (int cc = 0; cc < CPS; cc++) {
            int g = s * CPS + cc;
            int cl = g % CCH;
            float iv = NORM ? sIv[g] : 1.f;
            float nm = NORM ? sNm[g] : 0.f;
            #pragma unroll
            for (int ky = 0; ky < 3; ky++) {
                int gy = y0 + ry + (ky - 1) * DIL;
                if ((unsigned)gy >= (unsigned)H) continue;
                const float* trow = &tile[buf][cc][(ry + ky * DIL) * TS + cg];
                float4 ta = *(const float4*)(trow);
                float4 tb4 = *(const float4*)(trow + 4);
                float4 tc4 = *(const float4*)(trow + 8);
                float t[12] = {ta.x, ta.y, ta.z, ta.w,
                               tb4.x, tb4.y, tb4.z, tb4.w,
                               tc4.x, tc4.y, tc4.z, tc4.w};
                unsigned long long vp[12];
                #pragma unroll
                for (int j = 4 - DIL; j <= 7 + DIL; j++) {
                    float v = t[j];
                    if (NORM) v = fmaf(v, iv, nm);
                    if (RELU) v = fmaxf(v, 0.f);
                    if (NORM) {   // normalized padding must be exactly 0 at OOB x
                        if (j < 4 && cg == 0)   v = 0.f;
                        if (j > 7 && cg == 252) v = 0.f;
                    }
                    vp[j] = pack2(v, v);
                }
                #pragma unroll
                for (int kx = 0; kx < 3; kx++) {
                    const ulonglong2* wr =
                        (const ulonglong2*)&ws[(cl * 9 + ky * 3 + kx) * COUTP];
                    #pragma unroll
                    for (int q = 0; q < COUTP / 4; q++) {
                        ulonglong2 wp = wr[q];
                        #pragma unroll
                        for (int p = 0; p < 4; p++) {
                            fma2(acc2[p][2*q],   vp[4 + p + (kx-1)*DIL], wp.x);
                            fma2(acc2[p][2*q+1], vp[4 + p + (kx-1)*DIL], wp.y);
                        }
                    }
                }
            }
        }
    };

    // ---- pipeline: prefetch distance 1 stage (CPS channels), 2 buffers ----
    load_ws(0);
    cp_stage(0, 0);
    #pragma unroll 1
    for (int s = 0; s < NSTS; s++) {
        if (s + 1 < NSTS) { cp_stage(s + 1, (s + 1) & 1); CP_WAIT1(); }
        else              { CP_WAIT0(); }
        __syncthreads();
        if (CIN > CCH && s > 0 && ((s * CPS) % CCH) == 0) {
            load_ws(s * CPS);
            __syncthreads();
        }
        compute_stage(s, s & 1);
        __syncthreads();
    }

    // ---- epilogue: unpack, addend, store, stats ----
    const int pixb = (y0 + ry) * W + cg;
    const int lane = tid & 31, wid = tid >> 5;
    #pragma unroll
    for (int o = 0; o < COUT; o++) {
        float a0 = (o & 1) ? hi32(acc2[0][o >> 1]) : lo32(acc2[0][o >> 1]);
        float a1 = (o & 1) ? hi32(acc2[1][o >> 1]) : lo32(acc2[1][o >> 1]);
        float a2 = (o & 1) ? hi32(acc2[2][o >> 1]) : lo32(acc2[2][o >> 1]);
        float a3 = (o & 1) ? hi32(acc2[3][o >> 1]) : lo32(acc2[3][o >> 1]);
        if (ADDEND) {
            float4 ad = *(const float4*)(addend + (size_t)(b * COUT + o) * HW + pixb);
            a0 += ad.x; a1 += ad.y; a2 += ad.z; a3 += ad.w;
        }
        float4 v = make_float4(a0, a1, a2, a3);
        *(float4*)(out + (size_t)(b * outCt + oc0 + o) * HW + pixb) = v;
        if constexpr (STATS > 0) {
            float s = a0 + a1 + a2 + a3;
            float q = a0*a0 + a1*a1 + a2*a2 + a3*a3;
            float mx = fmaxf(fmaxf(a0, a1), fmaxf(a2, a3));
            #pragma unroll
            for (int d = 16; d > 0; d >>= 1) {
                s += __shfl_down_sync(0xffffffffu, s, d);
                q += __shfl_down_sync(0xffffffffu, q, d);
                if (STATS == 2) mx = fmaxf(mx, __shfl_down_sync(0xffffffffu, mx, d));
            }
            if (lane == 0) {
                reds[o * 8 + wid] = s;
                redq[o * 8 + wid] = q;
                if (STATS == 2) redm[o * 8 + wid] = mx;
            }
        }
    }
    if constexpr (STATS > 0) {
        __syncthreads();
        if (tid < COUT) {
            float s = 0.f, q = 0.f, mx = -INFINITY;
            #pragma unroll
            for (int j = 0; j < 8; j++) {
                s += reds[tid * 8 + j];
                q += redq[tid * 8 + j];
                if (STATS == 2) mx = fmaxf(mx, redm[tid * 8 + j]);
            }
            int rowi = b * gridDim.x + blockIdx.x;
            g_bsum[rowi * 64 + oc0 + tid] = s;
            g_bsq[rowi * 64 + oc0 + tid] = q;
            if (STATS == 2) g_bmax[rowi * 64 + oc0 + tid] = mx;
        }
    }
}

// =============== conv2 (64->16) fused norm*ca*sg, 2 channels/stage ============
__global__ void __launch_bounds__(256, 2) conv2_casg_s(
    const float* __restrict__ w, float* __restrict__ out)
{
    constexpr int TS = 272;
    constexpr int ITR = 6;
    constexpr int TSZ = ITR * TS;
    constexpr int NCHUNK = ITR * 68;
    constexpr int CPS = 2;
    constexpr int NSTS = 64 / CPS;
    __shared__ __align__(16) float tile[2][CPS][TSZ];
    __shared__ __align__(16) float sgt[TSZ];
    __shared__ __align__(16) float ws[16 * 9 * 16];
    __shared__ float reds[16 * 8], redq[16 * 8];
    __shared__ float sc[64], sb[64];

    const int tid = threadIdx.x;
    const int b = blockIdx.y;
    const int y0 = blockIdx.x * 4;
    const int ry = tid >> 6;
    const int cg = (tid & 63) * 4;

    if (tid < 64) {
        float iv = g_stats[7 * 128 + 64 + tid], m = g_stats[7 * 128 + tid];
        float s = iv * g_ca[b * 64 + tid];
        sc[tid] = s; sb[tid] = -m * s;
    }
    {
        const float* sgp = g_sg + (size_t)b * HW;
        for (int i = tid; i < TSZ; i += 256) {
            int r = i / TS;
            int gx = i - r * TS - 4;
            int gy = y0 - 1 + r;
            sgt[i] = ((unsigned)gy < (unsigned)H && (unsigned)gx < (unsigned)W)
                     ? sgp[gy * W + gx] : 0.f;
        }
    }

    unsigned long long acc2[4][8];
    #pragma unroll
    for (int p = 0; p < 4; p++)
        #pragma unroll
        for (int j = 0; j < 8; j++) acc2[p][j] = 0ull;

    auto load_ws = [&](int c0) {
        for (int i = tid; i < 16 * 9 * 16; i += 256) {
            int o = i & 15;
            int rem = i >> 4;
            int k = rem % 9;
            int cl = rem / 9;
            ws[i] = w[((size_t)o * 64 + c0 + cl) * 9 + k];
        }
    };
    auto cp_stage = [&](int s, int buf) {
        #pragma unroll
        for (int cc = 0; cc < CPS; cc++) {
            int c = s * CPS + cc;
            const float* __restrict__ inp = g_z + (size_t)(b * 64 + c) * HW;
            unsigned sbase = smem_u32(&tile[buf][cc][0]);
            #pragma unroll
            for (int it = 0; it < (NCHUNK + 255) / 256; it++) {
                int i = it * 256 + tid;
                if (i < NCHUNK) {
                    int r = i / 68;
                    int j = i - r * 68;
                    int gy = y0 - 1 + r;
                    bool ok = (j >= 1) && (j <= 64) && ((unsigned)gy < (unsigned)H);
                    const float* gp = ok ? (inp + gy * W + 4 * (j - 1)) : inp;
                    unsigned sa = sbase + (unsigned)(r * TS + 4 * j) * 4u;
                    CP_ASYNC16(sa, gp, ok ? 16 : 0);
                }
            }
        }
        CP_COMMIT();
    };
    auto compute_stage = [&](int s, int buf) {
        #pragma unroll
        for (int cc = 0; cc < CPS; cc++) {
            int g = s * CPS + cc;
            int cl = g & 15;
            float scc = sc[g], bcc = sb[g];
            #pragma unroll
            for (int ky = 0; ky < 3; ky++) {
                int gy = y0 + ry + (ky - 1);
                if ((unsigned)gy >= (unsigned)H) continue;
                int roff = (ry + ky) * TS + cg;
                const float* trow = &tile[buf][cc][roff];
                const float* srow = &sgt[roff];
                float4 ta = *(const float4*)(trow);
                float4 tb4 = *(const float4*)(trow + 4);
                float4 tc4 = *(const float4*)(trow + 8);
                float4 sa = *(const float4*)(srow);
                float4 sb4 = *(const float4*)(srow + 4);
                float4 sc4 = *(const float4*)(srow + 8);
                float t[12] = {ta.x, ta.y, ta.z, ta.w,
                               tb4.x, tb4.y, tb4.z, tb4.w,
                               tc4.x, tc4.y, tc4.z, tc4.w};
                float sg[12] = {sa.x, sa.y, sa.z, sa.w,
                                sb4.x, sb4.y, sb4.z, sb4.w,
                                sc4.x, sc4.y, sc4.z, sc4.w};
                unsigned long long vp[12];
                #pragma unroll
                for (int j = 3; j <= 8; j++) {
                    float v = fmaf(t[j], scc, bcc) * sg[j];  // sg==0 at OOB -> 0
                    vp[j] = pack2(v, v);
                }
                #pragma unroll
                for (int kx = 0; kx < 3; kx++) {
                    const ulonglong2* wr = (const ulonglong2*)&ws[(cl*9 + ky*3 + kx) * 16];
                    #pragma unroll
                    for (int q = 0; q < 4; q++) {
                        ulonglong2 wp = wr[q];
                        #pragma unroll
                        for (int p = 0; p < 4; p++) {
                            fma2(acc2[p][2*q],   vp[4 + p + (kx-1)], wp.x);
                            fma2(acc2[p][2*q+1], vp[4 + p + (kx-1)], wp.y);
                        }
                    }
                }
            }
        }
    };

    load_ws(0);
    cp_stage(0, 0);
    #pragma unroll 1
    for (int s = 0; s < NSTS; s++) {
        if (s + 1 < NSTS) { cp_stage(s + 1, (s + 1) & 1); CP_WAIT1(); }
        else              { CP_WAIT0(); }
        __syncthreads();   // also covers sc/sb + sgt on first iteration
        if (s > 0 && ((s * CPS) & 15) == 0) {
            load_ws(s * CPS);
            __syncthreads();
        }
        compute_stage(s, s & 1);
        __syncthreads();
    }

    const int pixb = (y0 + ry) * W + cg;
    const int lane = tid & 31, wid = tid >> 5;
    #pragma unroll
    for (int o = 0; o < 16; o++) {
        float a0 = (o & 1) ? hi32(acc2[0][o >> 1]) : lo32(acc2[0][o >> 1]);
        float a1 = (o & 1) ? hi32(acc2[1][o >> 1]) : lo32(acc2[1][o >> 1]);
        float a2 = (o & 1) ? hi32(acc2[2][o >> 1]) : lo32(acc2[2][o >> 1]);
        float a3 = (o & 1) ? hi32(acc2[3][o >> 1]) : lo32(acc2[3][o >> 1]);
        *(float4*)(out + (size_t)(b * 16 + o) * HW + pixb) = make_float4(a0, a1, a2, a3);
        float s = a0 + a1 + a2 + a3;
        float q = a0*a0 + a1*a1 + a2*a2 + a3*a3;
        #pragma unroll
        for (int d = 16; d > 0; d >>= 1) {
            s += __shfl_down_sync(0xffffffffu, s, d);
            q += __shfl_down_sync(0xffffffffu, q, d);
        }
        if (lane == 0) { reds[o * 8 + wid] = s; redq[o * 8 + wid] = q; }
    }
    __syncthreads();
    if (tid < 16) {
        float s = 0.f, q = 0.f;
        #pragma unroll
        for (int j = 0; j < 8; j++) { s += reds[tid*8+j]; q += redq[tid*8+j]; }
        int rowi = b * gridDim.x + blockIdx.x;
        g_bsum[rowi * 64 + tid] = s;
        g_bsq[rowi * 64 + tid] = q;
    }
}

// ---------------- 1x1 convs, 4 pixels/thread (coalesced float4) --------------
__global__ void __launch_bounds__(128) conv1x1_64_16_p4(
    const float* __restrict__ in, const float* __restrict__ w,
    const float* __restrict__ bias, float* __restrict__ out)
{
    __shared__ __align__(16) float ws[64*16];
    __shared__ float reds[16*4], redq[16*4];
    int tid = threadIdx.x;
    for (int i = tid; i < 64*16; i += 128) {
        int o = i & 15, c = i >> 4;
        ws[i] = w[o * 64 + c];
    }
    __syncthreads();
    int p4 = blockIdx.x * 128 + tid;
    int b = blockIdx.y;
    const float4* inb = (const float4*)(in + (size_t)b * 64 * HW) + p4;
    unsigned long long acc2[4][8];
    #pragma unroll
    for (int j = 0; j < 8; j++) {
        unsigned long long bv = pack2(__ldg(&bias[2*j]), __ldg(&bias[2*j+1]));
        acc2[0][j] = bv; acc2[1][j] = bv; acc2[2][j] = bv; acc2[3][j] = bv;
    }
    #pragma unroll 1
    for (int c = 0; c < 64; c++) {
        float4 v = inb[(size_t)c * (HW / 4)];
        unsigned long long v0 = pack2(v.x, v.x), v1 = pack2(v.y, v.y);
        unsigned long long v2 = pack2(v.z, v.z), v3 = pack2(v.w, v.w);
        const ulonglong2* wr = (const ulonglong2*)&ws[c * 16];
        #pragma unroll
        for (int q = 0; q < 4; q++) {
            ulonglong2 wp = wr[q];
            fma2(acc2[0][2*q], v0, wp.x); fma2(acc2[0][2*q+1], v0, wp.y);
            fma2(acc2[1][2*q], v1, wp.x); fma2(acc2[1][2*q+1], v1, wp.y);
            fma2(acc2[2][2*q], v2, wp.x); fma2(acc2[2][2*q+1], v2, wp.y);
            fma2(acc2[3][2*q], v3, wp.x); fma2(acc2[3][2*q+1], v3, wp.y);
        }
    }
    int lane = tid & 31, wid = tid >> 5;
    #pragma unroll
    for (int o = 0; o < 16; o++) {
        float a0 = (o&1) ? hi32(acc2[0][o>>1]) : lo32(acc2[0][o>>1]);
        float a1 = (o&1) ? hi32(acc2[1][o>>1]) : lo32(acc2[1][o>>1]);
        float a2 = (o&1) ? hi32(acc2[2][o>>1]) : lo32(acc2[2][o>>1]);
        float a3 = (o&1) ? hi32(acc2[3][o>>1]) : lo32(acc2[3][o>>1]);
        ((float4*)out)[(size_t)(b * 16 + o) * (HW / 4) + p4] = make_float4(a0,a1,a2,a3);
        float s = a0+a1+a2+a3;
        float q = a0*a0+a1*a1+a2*a2+a3*a3;
        #pragma unroll
        for (int d = 16; d > 0; d >>= 1) {
            s += __shfl_down_sync(0xffffffffu, s, d);
            q += __shfl_down_sync(0xffffffffu, q, d);
        }
        if (lane == 0) { reds[o*4+wid] = s; redq[o*4+wid] = q; }
    }
    __syncthreads();
    if (tid < 16) {
        float s = 0.f, q = 0.f;
        #pragma unroll
        for (int j = 0; j < 4; j++) { s += reds[tid*4+j]; q += redq[tid*4+j]; }
        int rowi = b * gridDim.x + blockIdx.x;
        g_bsum[rowi * 64 + tid] = s;
        g_bsq[rowi * 64 + tid] = q;
    }
}

// 64->64 1x1 over normalized cat4; split 4 x 16 outputs; 4 px/thread
__global__ void __launch_bounds__(128) conv1x1_cat4_p4(
    const float* __restrict__ xb, const float* __restrict__ w,
    const float* __restrict__ bias, float* __restrict__ out)
{
    __shared__ __align__(16) float ws[64*16];
    __shared__ float siv[64], snm[64];
    __shared__ float reds[16*4], redq[16*4];
    int tid = threadIdx.x;
    int oc0 = blockIdx.z * 16;
    if (tid < 64) {
        int s = tid >> 4, c = tid & 15;
        float m = g_stats[(1 + s) * 128 + c];
        float iv = g_stats[(1 + s) * 128 + 64 + c];
        siv[tid] = iv; snm[tid] = -m * iv;
    }
    for (int i = tid; i < 64*16; i += 128) {
        int o = i & 15, c = i >> 4;
        ws[i] = w[(oc0 + o) * 64 + c];
    }
    __syncthreads();
    int p4 = blockIdx.x * 128 + tid;
    int b = blockIdx.y;
    unsigned long long acc2[4][8];
    #pragma unroll
    for (int j = 0; j < 8; j++) {
        unsigned long long bv = pack2(__ldg(&bias[oc0+2*j]), __ldg(&bias[oc0+2*j+1]));
        acc2[0][j] = bv; acc2[1][j] = bv; acc2[2][j] = bv; acc2[3][j] = bv;
    }
    #pragma unroll 1
    for (int c = 0; c < 64; c++) {
        const float* src = xb + (size_t)(c >> 4) * SZ16 + (size_t)(b * 16 + (c & 15)) * HW;
        float4 v = ((const float4*)src)[p4];
        float ivc = siv[c], nmc = snm[c];
        v.x = fmaf(v.x, ivc, nmc); v.y = fmaf(v.y, ivc, nmc);
        v.z = fmaf(v.z, ivc, nmc); v.w = fmaf(v.w, ivc, nmc);
        unsigned long long v0 = pack2(v.x, v.x), v1 = pack2(v.y, v.y);
        unsigned long long v2 = pack2(v.z, v.z), v3 = pack2(v.w, v.w);
        const ulonglong2* wr = (const ulonglong2*)&ws[c * 16];
        #pragma unroll
        for (int q = 0; q < 4; q++) {
            ulonglong2 wp = wr[q];
            fma2(acc2[0][2*q], v0, wp.x); fma2(acc2[0][2*q+1], v0, wp.y);
            fma2(acc2[1][2*q], v1, wp.x); fma2(acc2[1][2*q+1], v1, wp.y);
            fma2(acc2[2][2*q], v2, wp.x); fma2(acc2[2][2*q+1], v2, wp.y);
            fma2(acc2[3][2*q], v3, wp.x); fma2(acc2[3][2*q+1], v3, wp.y);
        }
    }
    int lane = tid & 31, wid = tid >> 5;
    #pragma unroll
    for (int o = 0; o < 16; o++) {
        float a0 = (o&1) ? hi32(acc2[0][o>>1]) : lo32(acc2[0][o>>1]);
        float a1 = (o&1) ? hi32(acc2[1][o>>1]) : lo32(acc2[1][o>>1]);
        float a2 = (o&1) ? hi32(acc2[2][o>>1]) : lo32(acc2[2][o>>1]);
        float a3 = (o&1) ? hi32(acc2[3][o>>1]) : lo32(acc2[3][o>>1]);
        ((float4*)out)[(size_t)(b * 64 + oc0 + o) * (HW / 4) + p4] = make_float4(a0,a1,a2,a3);
        float s = a0+a1+a2+a3;
        float q = a0*a0+a1*a1+a2*a2+a3*a3;
        #pragma unroll
        for (int d = 16; d > 0; d >>= 1) {
            s += __shfl_down_sync(0xffffffffu, s, d);
            q += __shfl_down_sync(0xffffffffu, q, d);
        }
        if (lane == 0) { reds[o*4+wid] = s; redq[o*4+wid] = q; }
    }
    __syncthreads();
    if (tid < 16) {
        float s = 0.f, q = 0.f;
        #pragma unroll
        for (int j = 0; j < 4; j++) { s += reds[tid*4+j]; q += redq[tid*4+j]; }
        int rowi = b * gridDim.x + blockIdx.x;
        g_bsum[rowi * 64 + oc0 + tid] = s;
        g_bsq[rowi * 64 + oc0 + tid] = q;
    }
}

// ---------------- t materialization (float4) ----------------------------------
__global__ void norm_t_k(const float* __restrict__ pre,
                         const float* __restrict__ add1, const float* __restrict__ st1,
                         const float* __restrict__ lfsrc, int lfco)
{
    int i4 = blockIdx.x * 256 + threadIdx.x;
    int idx = i4 * 4;
    int pix = idx & (HW - 1);
    int rest = idx >> 16;
    int c = rest & 15, b = rest >> 4;
    float m = g_stats[5 * 128 + c], iv = g_stats[5 * 128 + 64 + c];
    float nm = -m * iv;
    float4 v = ((const float4*)pre)[i4];
    v.x = fmaf(v.x, iv, nm); v.y = fmaf(v.y, iv, nm);
    v.z = fmaf(v.z, iv, nm); v.w = fmaf(v.w, iv, nm);
    if (add1) {
        float4 a = ((const float4*)add1)[i4];
        if (st1) {
            float m1 = st1[c], i1 = st1[64 + c], n1 = -m1 * i1;
            a.x = fmaf(a.x, i1, n1); a.y = fmaf(a.y, i1, n1);
            a.z = fmaf(a.z, i1, n1); a.w = fmaf(a.w, i1, n1);
        }
        v.x += a.x; v.y += a.y; v.z += a.z; v.w += a.w;
    }
    if (lfsrc) {
        float4 l = *(const float4*)(lfsrc + (size_t)(b * 64 + lfco + c) * HW + pix);
        v.x += l.x; v.y += l.y; v.z += l.z; v.w += l.w;
    }
    ((float4*)g_t)[i4] = v;
}

// ---------------- deformable conv (exact reference semantics, f32x2) ----------
__global__ void __launch_bounds__(256) deform_k(
    const float* __restrict__ t, const float* __restrict__ off,
    const float* __restrict__ wd, float* __restrict__ out)
{
    __shared__ __align__(16) float ws[16*16*9];
    for (int i = threadIdx.x; i < 2304; i += blockDim.x) {
        int o = i & 15;
        int rem = i >> 4;
        int n = rem % 9;
        int c = rem / 9;
        ws[i] = wd[(o * 16 + c) * 9 + n];
    }
    __syncthreads();
    int pix = blockIdx.x * blockDim.x + threadIdx.x;
    int b = blockIdx.y;
    int yi = pix >> 8, xj = pix & 255;

    unsigned long long acc2[8];
    #pragma unroll
    for (int j = 0; j < 8; j++) acc2[j] = 0ull;

    const float* offb = off + (size_t)b * 18 * HW + pix;
    const float* tb = t + (size_t)b * 16 * HW;

    #pragma unroll 1
    for (int n = 0; n < 9; n++) {
        int dx = n / 3 - 1, dy = n % 3 - 1;
        float ox = offb[(size_t)(2 * n) * HW];
        float oy = offb[(size_t)(2 * n + 1) * HW];
        float plx = (float)(yi + 1 + dx) + ox;
        float ply = (float)(xj + 1 + dy) + oy;
        float flx = floorf(plx), fly = floorf(ply);
        int qltx = min(max((int)flx, 0), 257);
        int qlty = min(max((int)fly, 0), 257);
        int qrbx = min(max((int)flx + 1, 0), 257);
        int qrby = min(max((int)fly + 1, 0), 257);
        bool mx = (plx < 1.0f) || (plx > 256.0f);
        bool my = (ply < 1.0f) || (ply > 256.0f);
        float px = mx ? flx : plx; px = fminf(fmaxf(px, 0.f), 257.f);
        float py = my ? fly : ply; py = fminf(fmaxf(py, 0.f), 257.f);
        float wltx = 1.f + ((float)qltx - px);
        float wrbx = 1.f - ((float)qrbx - px);
        float wlty = 1.f + ((float)qlty - py);
        float wrby = 1.f - ((float)qrby - py);
        float glt = wltx * wlty, grb = wrbx * wrby;
        float glb = wltx * wrby, grt = wrbx * wlty;
        bool vltx = (qltx >= 1 && qltx <= 256);
        bool vlty = (qlty >= 1 && qlty <= 256);
        bool vrbx = (qrbx >= 1 && qrbx <= 256);
        bool vrby = (qrby >= 1 && qrby <= 256);
        int rlt = (qltx - 1) * W + (qlty - 1);
        int rrb = (qrbx - 1) * W + (qrby - 1);
        int rlb = (qltx - 1) * W + (qrby - 1);
        int rrt = (qrbx - 1) * W + (qlty - 1);
        #pragma unroll 4
        for (int c = 0; c < 16; c++) {
            const float* tc = tb + (size_t)c * HW;
            float vlt = (vltx && vlty) ? tc[rlt] : 0.f;
            float vrb = (vrbx && vrby) ? tc[rrb] : 0.f;
            float vlb = (vltx && vrby) ? tc[rlb] : 0.f;
            float vrt = (vrbx && vlty) ? tc[rrt] : 0.f;
            float val = glt * vlt + grb * vrb + glb * vlb + grt * vrt;
            unsigned long long vp = pack2(val, val);
            const ulonglong2* wr = (const ulonglong2*)&ws[(c * 9 + n) * 16];
            #pragma unroll
            for (int q = 0; q < 4; q++) {
                ulonglong2 wp = wr[q];
                fma2(acc2[2*q],   vp, wp.x);
                fma2(acc2[2*q+1], vp, wp.y);
            }
        }
    }
    #pragma unroll
    for (int o = 0; o < 16; o++) {
        float v = (o & 1) ? hi32(acc2[o >> 1]) : lo32(acc2[o >> 1]);
        out[(size_t)(b * 16 + o) * HW + pix] = v;
    }
}

// ---------------- CBAM ----------------------------------------------------------
__global__ void cbam_final_k(int gridX, const float* __restrict__ w1,
                             const float* __restrict__ w2)
{
    int t = threadIdx.x;
    int b = t >> 6, c = t & 63;
    float s = 0.f, q = 0.f, mx = -INFINITY;
    for (int j = 0; j < gridX; j++) {
        int idx = (b * gridX + j) * 64 + c;
        s += g_bsum[idx]; q += g_bsq[idx]; mx = fmaxf(mx, g_bmax[idx]);
    }
    __shared__ float sh_s[4][64], sh_q[4][64], sh_m[4][64];
    sh_s[b][c] = s; sh_q[b][c] = q; sh_m[b][c] = mx;
    __syncthreads();
    __shared__ float sm[64], si[64];
    if (t < 64) {
        float ts = 0.f, tq = 0.f;
        #pragma unroll
        for (int bb = 0; bb < 4; bb++) { ts += sh_s[bb][t]; tq += sh_q[bb][t]; }
        float m = ts / (float)NSTAT;
        float v = tq / (float)NSTAT - m * m;
        float iv = rsqrtf(v + 1e-5f);
        g_stats[7 * 128 + t] = m;
        g_stats[7 * 128 + 64 + t] = iv;
        sm[t] = m; si[t] = iv;
    }
    __syncthreads();
    __shared__ float av[4][64], xmv[4][64];
    av[b][c]  = (sh_s[b][c] / (float)HW - sm[c]) * si[c];
    xmv[b][c] = (sh_m[b][c] - sm[c]) * si[c];
    __syncthreads();
    __shared__ float hid[4][4][2];
    if (t < 32) {
        int bb = t >> 3, h = (t >> 1) & 3, which = t & 1;
        float acc = 0.f;
        for (int cc = 0; cc < 64; cc++)
            acc += w1[h * 64 + cc] * (which ? xmv[bb][cc] : av[bb][cc]);
        hid[bb][h][which] = fmaxf(acc, 0.f);
    }
    __syncthreads();
    {
        float va = 0.f, vm = 0.f;
        #pragma unroll
        for (int h = 0; h < 4; h++) {
            float wv = w2[c * 4 + h];
            va = fmaf(wv, hid[b][h][0], va);
            vm = fmaf(wv, hid[b][h][1], vm);
        }
        g_ca[b * 64 + c] = 1.f / (1.f + expf(-(va + vm)));
    }
}

// sp (mean,max over channels of (z norm * ca)), float4 over pixels
__global__ void apply1_k()
{
    __shared__ float sc[64], sb[64];
    int b = blockIdx.y;
    if (threadIdx.x < 64) {
        int c = threadIdx.x;
        float iv = g_stats[7 * 128 + 64 + c], m = g_stats[7 * 128 + c];
        float s = iv * g_ca[b * 64 + c];
        sc[c] = s; sb[c] = -m * s;
    }
    __syncthreads();
    int p4 = blockIdx.x * 256 + threadIdx.x;
    const float4* zp = (const float4*)(g_z + (size_t)b * 64 * HW) + p4;
    float4 smv = make_float4(0.f, 0.f, 0.f, 0.f);
    float4 mxv = make_float4(-INFINITY, -INFINITY, -INFINITY, -INFINITY);
    #pragma unroll 1
    for (int c = 0; c < 64; c++) {
        float4 v = zp[(size_t)c * (HW / 4)];
        float s = sc[c], bb = sb[c];
        v.x = fmaf(v.x, s, bb); v.y = fmaf(v.y, s, bb);
        v.z = fmaf(v.z, s, bb); v.w = fmaf(v.w, s, bb);
        smv.x += v.x; smv.y += v.y; smv.z += v.z; smv.w += v.w;
        mxv.x = fmaxf(mxv.x, v.x); mxv.y = fmaxf(mxv.y, v.y);
        mxv.z = fmaxf(mxv.z, v.z); mxv.w = fmaxf(mxv.w, v.w);
    }
    const float k = 1.f / 64.f;
    smv.x *= k; smv.y *= k; smv.z *= k; smv.w *= k;
    ((float4*)(g_sp + (size_t)(b * 2) * HW))[p4] = smv;
    ((float4*)(g_sp + (size_t)(b * 2 + 1) * HW))[p4] = mxv;
}

// sg = sigmoid(conv7x7(sp))
__global__ void apply2_k(const float* __restrict__ wsp)
{
    __shared__ float w[98];
    if (threadIdx.x < 98) w[threadIdx.x] = wsp[threadIdx.x];
    __syncthreads();
    int pix = blockIdx.x * 256 + threadIdx.x;
    int b = blockIdx.y;
    int y = pix >> 8, x = pix & 255;
    const float* s0 = g_sp + (size_t)(b * 2) * HW;
    const float* s1 = s0 + HW;
    float acc = 0.f;
    #pragma unroll 1
    for (int ky = 0; ky < 7; ky++) {
        int yy = y + ky - 3;
        if ((unsigned)yy >= (unsigned)H) continue;
        #pragma unroll
        for (int kx = 0; kx < 7; kx++) {
            int xx = x + kx - 3;
            if ((unsigned)xx >= (unsigned)W) continue;
            int ip = yy * W + xx;
            acc += w[ky * 7 + kx] * s0[ip] + w[49 + ky * 7 + kx] * s1[ip];
        }
    }
    g_sg[(size_t)b * HW + pix] = 1.f / (1.f + expf(-acc));
}

// ---------------- final elementwise ----------------------------------------------
__global__ void norm_s_k(const float* __restrict__ xx, const float* __restrict__ lf)
{
    int i4 = blockIdx.x * 256 + threadIdx.x;
    int idx = i4 * 4;
    int c = (idx >> 16) & 63;
    float m = g_stats[8 * 128 + c], iv = g_stats[8 * 128 + 64 + c];
    float nm = -m * iv;
    float4 v = ((const float4*)xx)[i4];
    float4 l = ((const float4*)lf)[i4];
    v.x = fmaxf(fmaf(v.x, iv, nm), 0.f) + l.x;
    v.y = fmaxf(fmaf(v.y, iv, nm), 0.f) + l.y;
    v.z = fmaxf(fmaf(v.z, iv, nm), 0.f) + l.z;
    v.w = fmaxf(fmaf(v.w, iv, nm), 0.f) + l.w;
    ((float4*)g_s)[i4] = v;
}

__global__ void norm_out_k(float* __restrict__ o)
{
    int i4 = blockIdx.x * 256 + threadIdx.x;
    int idx = i4 * 4;
    int c = (idx >> 16) & 63;
    float m = g_stats[9 * 128 + c], iv = g_stats[9 * 128 + 64 + c];
    float nm = -m * iv;
    float4 v = ((float4*)o)[i4];
    v.x = fmaf(v.x, iv, nm); v.y = fmaf(v.y, iv, nm);
    v.z = fmaf(v.z, iv, nm); v.w = fmaf(v.w, iv, nm);
    ((float4*)o)[i4] = v;
}

// ---------------- host orchestration ----------------------------------------------
extern "C" void kernel_launch(void* const* d_in, const int* in_sizes, int n_in,
                              void* d_out, int out_size)
{
    const float* lf   = (const float*)d_in[0];
    const float* hf   = (const float*)d_in[1];
    const float* w11  = (const float*)d_in[2];
    const float* b11  = (const float*)d_in[3];
    const float* wconv= (const float*)d_in[4];
    const float* woff = (const float*)d_in[5];
    const float* boff = (const float*)d_in[6];
    const float* wdef = (const float*)d_in[7];
    const float* wdil[4] = {(const float*)d_in[8], (const float*)d_in[9],
                            (const float*)d_in[10], (const float*)d_in[11]};
    const float* wc1  = (const float*)d_in[12];
    const float* wc2  = (const float*)d_in[13];
    const float* wfc1 = (const float*)d_in[14];
    const float* wfc2 = (const float*)d_in[15];
    const float* wsp  = (const float*)d_in[16];
    const float* wc12 = (const float*)d_in[17];
    const float* bc12 = (const float*)d_in[18];
    const float* wc33 = (const float*)d_in[19];
    float* out = (float*)d_out;

    void* tmp;
#define GETP(name, sym) cudaGetSymbolAddress(&tmp, sym); float* name = (float*)tmp;
    GETP(p_hfpre, g_hfpre) GETP(p_prehf, g_prehf) GETP(p_pre, g_pre)
    GETP(p_t, g_t)         GETP(p_off, g_off)     GETP(p_d16, g_d16)
    GETP(p_y, g_y)         GETP(p_z, g_z)         GETP(p_s, g_s)
    GETP(p_xb, g_xb)       GETP(p_stats, g_stats)
#undef GETP

    const dim3 CS(64, BATCH);            // staged convs: 256 blocks of 256 thr
    const dim3 CSz2(64, BATCH, 2);
    const dim3 CSz4(64, BATCH, 4);
    const dim3 P4(128, BATCH);           // 1x1 p4 kernels
    const dim3 P4z4(128, BATCH, 4);
    const dim3 PGo(256, BATCH);

    // Stage A: hf_pre = conv1x1(hf)+bias; stats slot0
    conv1x1_64_16_p4<<<P4, 128>>>(hf, w11, b11, p_hfpre);
    bn_final_k<<<16, 32>>>(512, 0);

    // Shared hf-part: conv3x3(relu(bn(hf_pre)), wconv[:,16:32])
    conv3x3_s<16,16,1,false,true,true,false,0><<<CS, 256>>>(
        p_hfpre, 16, 0, p_stats + 0*128, wconv, 32, 16, nullptr, nullptr,
        p_prehf, 16);

    for (int k = 0; k < 4; k++) {
        // pre = conv3x3(prev_norm, wconv[:,0:16]) + prehf ; stats slot5
        if (k == 0)
            conv3x3_s<16,16,1,false,false,false,true,1><<<CS, 256>>>(
                lf, 64, 0, nullptr, wconv, 32, 0, nullptr, p_prehf, p_pre, 16);
        else
            conv3x3_s<16,16,1,false,true,false,true,1><<<CS, 256>>>(
                p_xb + (size_t)(k-1) * SZ16, 16, 0, p_stats + k*128,
                wconv, 32, 0, nullptr, p_prehf, p_pre, 16);
        bn_final_k<<<16, 32>>>(256, 5);

        // t = bn(pre) + extras
        const float* add1 = (k >= 1) ? p_xb + (size_t)(k-1) * SZ16 : nullptr;
        const float* st1  = (k >= 1) ? p_stats + k*128 : nullptr;
        const float* lfa  = (k <= 2) ? lf : nullptr;
        int lfco = (k == 0) ? 16 : (k == 1) ? 32 : 48;
        norm_t_k<<<SZ16 / 1024, 256>>>(p_pre, add1, st1, lfa, lfco);

        // offsets (COUT 18 as 2x9) + deformable conv
        conv3x3_s<16,9,1,true,false,false,false,0><<<CSz2, 256>>>(
            p_t, 16, 0, nullptr, woff, 16, 0, boff, nullptr, p_off, 18);
        deform_k<<<PGo, 256>>>(p_t, p_off, wdef, p_d16);

        // dilated conv ; stats slot6
        switch (k) {
        case 0: conv3x3_s<16,16,1,false,false,false,false,1><<<CS, 256>>>(
                    p_d16, 16, 0, nullptr, wdil[0], 16, 0, nullptr, nullptr, p_y, 16); break;
        case 1: conv3x3_s<16,16,2,false,false,false,false,1><<<CS, 256>>>(
                    p_d16, 16, 0, nullptr, wdil[1], 16, 0, nullptr, nullptr, p_y, 16); break;
        case 2: conv3x3_s<16,16,3,false,false,false,false,1><<<CS, 256>>>(
                    p_d16, 16, 0, nullptr, wdil[2], 16, 0, nullptr, nullptr, p_y, 16); break;
        default: conv3x3_s<16,16,4,false,false,false,false,1><<<CS, 256>>>(
                    p_d16, 16, 0, nullptr, wdil[3], 16, 0, nullptr, nullptr, p_y, 16); break;
        }
        bn_final_k<<<16, 32>>>(256, 6);

        // z = conv3x3(bn(y), wc1) 16->64 split 4x16 ; stats+max slot7 partials
        conv3x3_s<16,16,1,false,true,false,false,2><<<CSz4, 256>>>(
            p_y, 16, 0, p_stats + 6*128, wc1, 16, 0, nullptr, nullptr, p_z, 64);
        cbam_final_k<<<1, 256>>>(64, wfc1, wfc2);

        // spatial attention
        apply1_k<<<dim3(64, BATCH), 256>>>();
        apply2_k<<<PGo, 256>>>(wsp);

        // branch output: conv2 with fused norm*ca*sg on load ; stats slot 1+k
        conv2_casg_s<<<CS, 256>>>(wc2, p_xb + (size_t)k * SZ16);
        bn_final_k<<<16, 32>>>(256, 1 + k);
    }

    // xx_pre = conv1x1(cat4_normalized)+bias ; stats slot8
    conv1x1_cat4_p4<<<P4z4, 128>>>(p_xb, wc12, bc12, p_z);
    bn_final_k<<<64, 32>>>(512, 8);
    // s = lf + relu(bn(xx_pre))
    norm_s_k<<<SZ64 / 1024, 256>>>(p_z, lf);

    // out_pre = conv3x3(s, wc33) 64->64 split 4x16 ; stats slot9 ; normalize
    conv3x3_s<64,16,1,false,false,false,false,1><<<CSz4, 256>>>(
        p_s, 64, 0, nullptr, wc33, 64, 0, nullptr, nullptr, out, 64);
    bn_final_k<<<64, 32>>>(256, 9);
    norm_out_k<<<SZ64 / 1024, 256>>>(out);
}